// round 8
// baseline (speedup 1.0000x reference)
#include <cuda_runtime.h>
#include <math.h>

// ---------------------------------------------------------------------------
// Problem constants
// ---------------------------------------------------------------------------
constexpr int BATCH  = 16;
constexpr int NPOS   = 784;          // 28*28
constexpr int CDIM   = 512;
constexpr int NHEADS = 16;
constexpr int DHEAD  = 32;
constexpr int FFD    = 2048;
constexpr int NREL   = 1596;
constexpr int MROWS  = BATCH * NPOS; // 12544

constexpr size_t SZ_NC = (size_t)BATCH * NPOS * CDIM;
constexpr size_t SZ_FF = (size_t)BATCH * NPOS * FFD;

__device__ float g_buf[8 * SZ_NC + SZ_FF];

// ---------------------------------------------------------------------------
// Helpers
// ---------------------------------------------------------------------------
__device__ __forceinline__ void fma_f32x2(unsigned long long& d,
                                          unsigned long long a,
                                          unsigned long long b) {
    asm("fma.rn.f32x2 %0, %1, %2, %0;" : "+l"(d) : "l"(a), "l"(b));
}
__device__ __forceinline__ float2 unpack_f32x2(unsigned long long v) {
    return make_float2(__uint_as_float((unsigned int)(v & 0xffffffffull)),
                       __uint_as_float((unsigned int)(v >> 32)));
}
__device__ __forceinline__ float gelu_exact(float x) {
    return 0.5f * x * (1.0f + erff(x * 0.7071067811865476f));
}

// ---------------------------------------------------------------------------
// Tiled 2D transpose per batch:  src [R][Cc]  ->  dst [Cc][R]
// ---------------------------------------------------------------------------
__global__ void transpose_kernel(const float* __restrict__ in,
                                 float* __restrict__ out, int R, int Cc) {
    __shared__ float tile[32][33];
    const int b = blockIdx.z;
    const float* src = in  + (size_t)b * R * Cc;
    float*       dst = out + (size_t)b * R * Cc;
    const int c0 = blockIdx.x * 32;
    const int r0 = blockIdx.y * 32;
    const int tx = threadIdx.x, ty = threadIdx.y;

    #pragma unroll
    for (int j = 0; j < 32; j += 8) {
        int r = r0 + ty + j, c = c0 + tx;
        if (r < R && c < Cc) tile[ty + j][tx] = src[(size_t)r * Cc + c];
    }
    __syncthreads();
    #pragma unroll
    for (int j = 0; j < 32; j += 8) {
        int oc = c0 + ty + j;
        int orr = r0 + tx;
        if (oc < Cc && orr < R) dst[(size_t)oc * R + orr] = tile[tx][ty + j];
    }
}

// ---------------------------------------------------------------------------
// LayerNorm over C=512, one block (128 threads) per (b,n) row
// ---------------------------------------------------------------------------
__global__ void __launch_bounds__(128) ln_kernel(const float* __restrict__ xc,
                                                 const float* __restrict__ w,
                                                 const float* __restrict__ bsh,
                                                 float* __restrict__ xn) {
    const int row = blockIdx.x;
    const int tid = threadIdx.x;
    const float* xr = xc + (size_t)row * CDIM;
    float4 v = *(const float4*)&xr[tid << 2];
    float s  = v.x + v.y + v.z + v.w;
    float ss = v.x * v.x + v.y * v.y + v.z * v.z + v.w * v.w;
    #pragma unroll
    for (int o = 16; o; o >>= 1) {
        s  += __shfl_xor_sync(0xffffffffu, s, o);
        ss += __shfl_xor_sync(0xffffffffu, ss, o);
    }
    __shared__ float rs[4], rss[4];
    const int warp = tid >> 5, lane = tid & 31;
    if (lane == 0) { rs[warp] = s; rss[warp] = ss; }
    __syncthreads();
    if (tid == 0) {
        float S  = rs[0] + rs[1] + rs[2] + rs[3];
        float SS = rss[0] + rss[1] + rss[2] + rss[3];
        float mu  = S * (1.0f / CDIM);
        float var = SS * (1.0f / CDIM) - mu * mu;
        rs[0]  = mu;
        rss[0] = rsqrtf(var + 1e-5f);
    }
    __syncthreads();
    const float mu = rs[0], rstd = rss[0];
    float4 wv = *(const float4*)&w[tid << 2];
    float4 bv = *(const float4*)&bsh[tid << 2];
    float4 o;
    o.x = (v.x - mu) * rstd * wv.x + bv.x;
    o.y = (v.y - mu) * rstd * wv.y + bv.y;
    o.z = (v.z - mu) * rstd * wv.z + bv.z;
    o.w = (v.w - mu) * rstd * wv.w + bv.w;
    *(float4*)&xn[(size_t)row * CDIM + (tid << 2)] = o;
}

// ---------------------------------------------------------------------------
// fp32 GEMM, 128x128 tile, BK=8, 256 threads, 8x8 microtile, f32x2 FMAs.
// A stored duplicated in smem ({a,a} pairs -> no pack MOVs); B fragment split
// into two 16B chunks 64 cols apart (conflict-free LDS.128); double-buffered
// smem (1 sync per k-step).
// EPI: 0 = bias, 1 = bias+gelu(exact), 2 = bias+residual
// ---------------------------------------------------------------------------
template <int EPI>
__global__ void __launch_bounds__(256, 2) gemm_kernel(
    const float* __restrict__ A, const float* __restrict__ Bm,
    const float* __restrict__ bias, const float* __restrict__ res,
    float* __restrict__ Cout, int M, int K, int Nc) {
    __shared__ float Asd[2][8][256];   // duplicated: col 2m,2m+1 hold A[m]
    __shared__ float Bs[2][8][128];

    const int tid  = threadIdx.x;
    const int row0 = blockIdx.y * 128;
    const int col0 = blockIdx.x * 128;

    const int am  = tid & 127;           // A row within tile
    const int ak  = (tid >> 7) << 2;     // 0 or 4 (k offset)
    const int bkr = tid >> 5;            // 0..7  (B k row)
    const int bc  = (tid & 31) << 2;     // 0..124
    const int wr  = (tid >> 4) << 3;     // 0..120 (8 C rows)
    const int wc  = (tid & 15) << 2;     // chunk0 cols; chunk1 at +64

    const float* Aptr = A  + (size_t)(row0 + am) * K + ak;
    const float* Bptr = Bm + (size_t)bkr * Nc + col0 + bc;

    unsigned long long acc[8][4] = {};

    float4 av = *(const float4*)Aptr;
    float4 bv = *(const float4*)Bptr;

    // stage 0
    *(float2*)&Asd[0][ak + 0][2 * am] = make_float2(av.x, av.x);
    *(float2*)&Asd[0][ak + 1][2 * am] = make_float2(av.y, av.y);
    *(float2*)&Asd[0][ak + 2][2 * am] = make_float2(av.z, av.z);
    *(float2*)&Asd[0][ak + 3][2 * am] = make_float2(av.w, av.w);
    *(float4*)&Bs[0][bkr][bc] = bv;
    __syncthreads();

    int buf = 0;
    for (int k0 = 0; k0 < K; k0 += 8) {
        const bool more = (k0 + 8) < K;
        if (more) {
            av = *(const float4*)(Aptr + (k0 + 8));
            bv = *(const float4*)(Bptr + (size_t)(k0 + 8) * Nc);
        }
        #pragma unroll
        for (int kk = 0; kk < 8; ++kk) {
            ulonglong2 a01 = *(const ulonglong2*)&Asd[buf][kk][2 * wr];
            ulonglong2 a23 = *(const ulonglong2*)&Asd[buf][kk][2 * wr + 4];
            ulonglong2 a45 = *(const ulonglong2*)&Asd[buf][kk][2 * wr + 8];
            ulonglong2 a67 = *(const ulonglong2*)&Asd[buf][kk][2 * wr + 12];
            ulonglong2 bA  = *(const ulonglong2*)&Bs[buf][kk][wc];
            ulonglong2 bB  = *(const ulonglong2*)&Bs[buf][kk][wc + 64];
            unsigned long long a2[8] = {a01.x, a01.y, a23.x, a23.y,
                                        a45.x, a45.y, a67.x, a67.y};
            unsigned long long b2[4] = {bA.x, bA.y, bB.x, bB.y};
            #pragma unroll
            for (int i = 0; i < 8; ++i) {
                #pragma unroll
                for (int j = 0; j < 4; ++j) fma_f32x2(acc[i][j], a2[i], b2[j]);
            }
        }
        if (more) {
            const int nb = buf ^ 1;
            *(float2*)&Asd[nb][ak + 0][2 * am] = make_float2(av.x, av.x);
            *(float2*)&Asd[nb][ak + 1][2 * am] = make_float2(av.y, av.y);
            *(float2*)&Asd[nb][ak + 2][2 * am] = make_float2(av.z, av.z);
            *(float2*)&Asd[nb][ak + 3][2 * am] = make_float2(av.w, av.w);
            *(float4*)&Bs[nb][bkr][bc] = bv;
            __syncthreads();
            buf = nb;
        }
    }

    const int cA = col0 + wc;
    const int cB = cA + 64;
    const float4 biasA = *(const float4*)&bias[cA];
    const float4 biasB = *(const float4*)&bias[cB];
    #pragma unroll
    for (int i = 0; i < 8; ++i) {
        const size_t r = (size_t)(row0 + wr + i);
        float2 p0 = unpack_f32x2(acc[i][0]);
        float2 p1 = unpack_f32x2(acc[i][1]);
        float2 p2 = unpack_f32x2(acc[i][2]);
        float2 p3 = unpack_f32x2(acc[i][3]);
        float4 oA = make_float4(p0.x + biasA.x, p0.y + biasA.y,
                                p1.x + biasA.z, p1.y + biasA.w);
        float4 oB = make_float4(p2.x + biasB.x, p2.y + biasB.y,
                                p3.x + biasB.z, p3.y + biasB.w);
        if (EPI == 1) {
            oA.x = gelu_exact(oA.x); oA.y = gelu_exact(oA.y);
            oA.z = gelu_exact(oA.z); oA.w = gelu_exact(oA.w);
            oB.x = gelu_exact(oB.x); oB.y = gelu_exact(oB.y);
            oB.z = gelu_exact(oB.z); oB.w = gelu_exact(oB.w);
        }
        if (EPI == 2) {
            float4 rA = *(const float4*)&res[r * Nc + cA];
            float4 rB = *(const float4*)&res[r * Nc + cB];
            oA.x += rA.x; oA.y += rA.y; oA.z += rA.z; oA.w += rA.w;
            oB.x += rB.x; oB.y += rB.y; oB.z += rB.z; oB.w += rB.w;
        }
        *(float4*)&Cout[r * Nc + cA] = oA;
        *(float4*)&Cout[r * Nc + cB] = oB;
    }
}

// ---------------------------------------------------------------------------
// Fused attention for one (b, h, 16-query tile). Exact two-pass softmax,
// full 784-wide score rows in smem.
//   pass1: 2q x 4m register tile per thread, float4 smem loads
//   pass3: transposed V tile (pad 116), broadcast float4 weight loads
// smem: sS[16][784] + sQ[16][36] + union(sK[112][36], sV[32][116])
// ---------------------------------------------------------------------------
constexpr int SQ_PAD = 36;
constexpr int SK_PAD = 36;
constexpr int SV_PAD = 116;
constexpr int ATTN_SMEM =
    (16 * 784 + 16 * SQ_PAD + 112 * SK_PAD) * 4;  // 112*36=4032 >= 32*116=3712

__global__ void __launch_bounds__(256) attn_kernel(
    const float* __restrict__ q, const float* __restrict__ k,
    const float* __restrict__ v, const float* __restrict__ rel_bias,
    const int* __restrict__ rel_idx, float* __restrict__ att) {
    const int qt = blockIdx.x;   // 0..48
    const int h  = blockIdx.y;
    const int b  = blockIdx.z;
    const int n0 = qt * 16;
    const int tid = threadIdx.x;

    extern __shared__ float sm[];
    float* sS  = sm;                      // 16 x 784
    float* sQ  = sm + 16 * 784;           // 16 x 36
    float* sKV = sQ + 16 * SQ_PAD;        // union: K tile / V tile (transposed)

    // load Q tile
    #pragma unroll
    for (int e = tid; e < 16 * 32; e += 256) {
        int qi = e >> 5, d = e & 31;
        sQ[qi * SQ_PAD + d] =
            q[((size_t)(b * NPOS + n0 + qi)) * CDIM + h * DHEAD + d];
    }

    const int qg  = tid / 28;          // 0..7 (+ garbage for tid>=224)
    const int mg  = tid % 28;          // 0..27
    const int qi0 = qg * 2;
    const bool active = (tid < 224);

    // ---- pass 1: scores = q.k^T + rel_bias ----
    for (int kt = 0; kt < 7; ++kt) {
        const int m0 = kt * 112;
        __syncthreads();
        #pragma unroll
        for (int e = tid; e < 112 * 32; e += 256) {
            int mi = e >> 5, d = e & 31;
            sKV[mi * SK_PAD + d] =
                k[((size_t)(b * NPOS + m0 + mi)) * CDIM + h * DHEAD + d];
        }
        __syncthreads();
        if (active) {
            float acc[2][4] = {};
            #pragma unroll
            for (int d4 = 0; d4 < 32; d4 += 4) {
                float4 q0v = *(const float4*)&sQ[qi0 * SQ_PAD + d4];
                float4 q1v = *(const float4*)&sQ[(qi0 + 1) * SQ_PAD + d4];
                #pragma unroll
                for (int j = 0; j < 4; ++j) {
                    float4 kv = *(const float4*)&sKV[(mg + 28 * j) * SK_PAD + d4];
                    acc[0][j] = fmaf(q0v.x, kv.x, acc[0][j]);
                    acc[0][j] = fmaf(q0v.y, kv.y, acc[0][j]);
                    acc[0][j] = fmaf(q0v.z, kv.z, acc[0][j]);
                    acc[0][j] = fmaf(q0v.w, kv.w, acc[0][j]);
                    acc[1][j] = fmaf(q1v.x, kv.x, acc[1][j]);
                    acc[1][j] = fmaf(q1v.y, kv.y, acc[1][j]);
                    acc[1][j] = fmaf(q1v.z, kv.z, acc[1][j]);
                    acc[1][j] = fmaf(q1v.w, kv.w, acc[1][j]);
                }
            }
            int   rl[2][4];
            #pragma unroll
            for (int r = 0; r < 2; ++r)
                #pragma unroll
                for (int j = 0; j < 4; ++j)
                    rl[r][j] = rel_idx[(size_t)(n0 + qi0 + r) * NPOS +
                                       (m0 + mg + 28 * j)];
            #pragma unroll
            for (int r = 0; r < 2; ++r)
                #pragma unroll
                for (int j = 0; j < 4; ++j) {
                    const int m = m0 + mg + 28 * j;
                    sS[(qi0 + r) * 784 + m] =
                        acc[r][j] + rel_bias[h * NREL + rl[r][j]];
                }
        }
    }
    __syncthreads();

    // ---- pass 2: softmax per query row (warp w handles rows w, w+8) ----
    {
        const int warp = tid >> 5, lane = tid & 31;
        #pragma unroll
        for (int rr = 0; rr < 2; ++rr) {
            float* row = sS + (warp + rr * 8) * 784;
            float mx = -1e30f;
            for (int m = lane; m < 784; m += 32) mx = fmaxf(mx, row[m]);
            #pragma unroll
            for (int o = 16; o; o >>= 1)
                mx = fmaxf(mx, __shfl_xor_sync(0xffffffffu, mx, o));
            float sum = 0.0f;
            for (int m = lane; m < 784; m += 32) {
                float e = expf(row[m] - mx);
                row[m] = e;
                sum += e;
            }
            #pragma unroll
            for (int o = 16; o; o >>= 1)
                sum += __shfl_xor_sync(0xffffffffu, sum, o);
            const float inv = 1.0f / sum;
            for (int m = lane; m < 784; m += 32) row[m] *= inv;
        }
    }

    // ---- pass 3: out = attn @ v  (V transposed in smem) ----
    const int warp = tid >> 5;   // row pair {warp, warp+8}
    const int d    = tid & 31;
    float acc0 = 0.0f, acc1 = 0.0f;
    for (int kt = 0; kt < 7; ++kt) {
        const int m0 = kt * 112;
        __syncthreads();
        #pragma unroll
        for (int e = tid; e < 112 * 32; e += 256) {
            int mi = e >> 5, dd = e & 31;
            sKV[dd * SV_PAD + mi] =
                v[((size_t)(b * NPOS + m0 + mi)) * CDIM + h * DHEAD + dd];
        }
        __syncthreads();
        const float* w0 = &sS[warp * 784 + m0];
        const float* w1 = &sS[(warp + 8) * 784 + m0];
        const float* vr = &sKV[d * SV_PAD];
        #pragma unroll 7
        for (int mi = 0; mi < 112; mi += 4) {
            float4 a0 = *(const float4*)&w0[mi];   // broadcast
            float4 a1 = *(const float4*)&w1[mi];   // broadcast
            float4 vv = *(const float4*)&vr[mi];
            acc0 = fmaf(a0.x, vv.x, acc0);
            acc0 = fmaf(a0.y, vv.y, acc0);
            acc0 = fmaf(a0.z, vv.z, acc0);
            acc0 = fmaf(a0.w, vv.w, acc0);
            acc1 = fmaf(a1.x, vv.x, acc1);
            acc1 = fmaf(a1.y, vv.y, acc1);
            acc1 = fmaf(a1.z, vv.z, acc1);
            acc1 = fmaf(a1.w, vv.w, acc1);
        }
    }
    att[((size_t)(b * NPOS + n0 + warp)) * CDIM + h * DHEAD + d]     = acc0;
    att[((size_t)(b * NPOS + n0 + warp + 8)) * CDIM + h * DHEAD + d] = acc1;
}

// ---------------------------------------------------------------------------
// Launch
// ---------------------------------------------------------------------------
extern "C" void kernel_launch(void* const* d_in, const int* in_sizes, int n_in,
                              void* d_out, int out_size) {
    (void)in_sizes; (void)n_in; (void)out_size;
    const float* x      = (const float*)d_in[0];
    const float* ln_w   = (const float*)d_in[1];
    const float* ln_b   = (const float*)d_in[2];
    const float* Wq     = (const float*)d_in[3];
    const float* bq     = (const float*)d_in[4];
    const float* Wk     = (const float*)d_in[5];
    const float* bk     = (const float*)d_in[6];
    const float* Wv     = (const float*)d_in[7];
    const float* bv     = (const float*)d_in[8];
    const float* Wo     = (const float*)d_in[9];
    const float* bo     = (const float*)d_in[10];
    const float* relb   = (const float*)d_in[11];
    const float* W1     = (const float*)d_in[12];
    const float* b1     = (const float*)d_in[13];
    const float* W2     = (const float*)d_in[14];
    const float* b2     = (const float*)d_in[15];
    const int*   relidx = (const int*)d_in[16];
    float* out = (float*)d_out;

    float* buf = nullptr;
    cudaGetSymbolAddress((void**)&buf, g_buf);
    float* xc  = buf + 0 * SZ_NC;
    float* xn  = buf + 1 * SZ_NC;
    float* qb  = buf + 2 * SZ_NC;
    float* kb  = buf + 3 * SZ_NC;
    float* vb  = buf + 4 * SZ_NC;
    float* att = buf + 5 * SZ_NC;
    float* x1  = buf + 6 * SZ_NC;
    float* x2  = buf + 7 * SZ_NC;
    float* h1  = buf + 8 * SZ_NC;

    cudaFuncSetAttribute(attn_kernel,
                         cudaFuncAttributeMaxDynamicSharedMemorySize,
                         ATTN_SMEM);

    const dim3 tb(32, 8);
    transpose_kernel<<<dim3(25, 16, BATCH), tb>>>(x, xc, CDIM, NPOS);
    ln_kernel<<<MROWS, 128>>>(xc, ln_w, ln_b, xn);

    const dim3 g512(CDIM / 128, MROWS / 128);   // (4, 98)
    const dim3 g2048(FFD / 128, MROWS / 128);   // (16, 98)
    gemm_kernel<0><<<g512, 256>>>(xn, Wq, bq, nullptr, qb, MROWS, CDIM, CDIM);
    gemm_kernel<0><<<g512, 256>>>(xn, Wk, bk, nullptr, kb, MROWS, CDIM, CDIM);
    gemm_kernel<0><<<g512, 256>>>(xn, Wv, bv, nullptr, vb, MROWS, CDIM, CDIM);

    attn_kernel<<<dim3(49, NHEADS, BATCH), 256, ATTN_SMEM>>>(qb, kb, vb, relb,
                                                             relidx, att);

    gemm_kernel<2><<<g512, 256>>>(att, Wo, bo, xc, x1, MROWS, CDIM, CDIM);
    gemm_kernel<1><<<g2048, 256>>>(x1, W1, b1, nullptr, h1, MROWS, CDIM, FFD);
    gemm_kernel<2><<<g512, 256>>>(h1, W2, b2, x1, x2, MROWS, FFD, CDIM);

    transpose_kernel<<<dim3(16, 25, BATCH), tb>>>(x2, out, NPOS, CDIM);
}

// round 9
// speedup vs baseline: 1.0003x; 1.0003x over previous
#include <cuda_runtime.h>
#include <math.h>

// ---------------------------------------------------------------------------
// Problem constants
// ---------------------------------------------------------------------------
constexpr int BATCH  = 16;
constexpr int NPOS   = 784;          // 28*28
constexpr int CDIM   = 512;
constexpr int NHEADS = 16;
constexpr int DHEAD  = 32;
constexpr int FFD    = 2048;
constexpr int NREL   = 1596;
constexpr int MROWS  = BATCH * NPOS; // 12544

constexpr size_t SZ_NC = (size_t)BATCH * NPOS * CDIM;
constexpr size_t SZ_FF = (size_t)BATCH * NPOS * FFD;

__device__ float g_buf[8 * SZ_NC + SZ_FF];

// ---------------------------------------------------------------------------
// Helpers
// ---------------------------------------------------------------------------
__device__ __forceinline__ void fma_f32x2(unsigned long long& d,
                                          unsigned long long a,
                                          unsigned long long b) {
    asm("fma.rn.f32x2 %0, %1, %2, %0;" : "+l"(d) : "l"(a), "l"(b));
}
__device__ __forceinline__ float2 unpack_f32x2(unsigned long long v) {
    return make_float2(__uint_as_float((unsigned int)(v & 0xffffffffull)),
                       __uint_as_float((unsigned int)(v >> 32)));
}
__device__ __forceinline__ float gelu_exact(float x) {
    return 0.5f * x * (1.0f + erff(x * 0.7071067811865476f));
}

// ---------------------------------------------------------------------------
// Tiled 2D transpose per batch:  src [R][Cc]  ->  dst [Cc][R]
// ---------------------------------------------------------------------------
__global__ void transpose_kernel(const float* __restrict__ in,
                                 float* __restrict__ out, int R, int Cc) {
    __shared__ float tile[32][33];
    const int b = blockIdx.z;
    const float* src = in  + (size_t)b * R * Cc;
    float*       dst = out + (size_t)b * R * Cc;
    const int c0 = blockIdx.x * 32;
    const int r0 = blockIdx.y * 32;
    const int tx = threadIdx.x, ty = threadIdx.y;

    #pragma unroll
    for (int j = 0; j < 32; j += 8) {
        int r = r0 + ty + j, c = c0 + tx;
        if (r < R && c < Cc) tile[ty + j][tx] = src[(size_t)r * Cc + c];
    }
    __syncthreads();
    #pragma unroll
    for (int j = 0; j < 32; j += 8) {
        int oc = c0 + ty + j;
        int orr = r0 + tx;
        if (oc < Cc && orr < R) dst[(size_t)oc * R + orr] = tile[tx][ty + j];
    }
}

// ---------------------------------------------------------------------------
// LayerNorm over C=512, one block (128 threads) per (b,n) row
// ---------------------------------------------------------------------------
__global__ void __launch_bounds__(128) ln_kernel(const float* __restrict__ xc,
                                                 const float* __restrict__ w,
                                                 const float* __restrict__ bsh,
                                                 float* __restrict__ xn) {
    const int row = blockIdx.x;
    const int tid = threadIdx.x;
    const float* xr = xc + (size_t)row * CDIM;
    float4 v = *(const float4*)&xr[tid << 2];
    float s  = v.x + v.y + v.z + v.w;
    float ss = v.x * v.x + v.y * v.y + v.z * v.z + v.w * v.w;
    #pragma unroll
    for (int o = 16; o; o >>= 1) {
        s  += __shfl_xor_sync(0xffffffffu, s, o);
        ss += __shfl_xor_sync(0xffffffffu, ss, o);
    }
    __shared__ float rs[4], rss[4];
    const int warp = tid >> 5, lane = tid & 31;
    if (lane == 0) { rs[warp] = s; rss[warp] = ss; }
    __syncthreads();
    if (tid == 0) {
        float S  = rs[0] + rs[1] + rs[2] + rs[3];
        float SS = rss[0] + rss[1] + rss[2] + rss[3];
        float mu  = S * (1.0f / CDIM);
        float var = SS * (1.0f / CDIM) - mu * mu;
        rs[0]  = mu;
        rss[0] = rsqrtf(var + 1e-5f);
    }
    __syncthreads();
    const float mu = rs[0], rstd = rss[0];
    float4 wv = *(const float4*)&w[tid << 2];
    float4 bv = *(const float4*)&bsh[tid << 2];
    float4 o;
    o.x = (v.x - mu) * rstd * wv.x + bv.x;
    o.y = (v.y - mu) * rstd * wv.y + bv.y;
    o.z = (v.z - mu) * rstd * wv.z + bv.z;
    o.w = (v.w - mu) * rstd * wv.w + bv.w;
    *(float4*)&xn[(size_t)row * CDIM + (tid << 2)] = o;
}

// ---------------------------------------------------------------------------
// fp32 GEMM, 128x128 tile, BK=8, 256 threads, 8x8 microtile, f32x2 FMAs.
// A stored duplicated in smem ({a,a} pairs -> no pack MOVs); B fragment split
// into two 16B chunks 64 cols apart (conflict-free LDS.128); double-buffered
// smem (1 sync per k-step).
// EPI: 0 = bias, 1 = bias+gelu(exact), 2 = bias+residual
// ---------------------------------------------------------------------------
template <int EPI>
__global__ void __launch_bounds__(256, 2) gemm_kernel(
    const float* __restrict__ A, const float* __restrict__ Bm,
    const float* __restrict__ bias, const float* __restrict__ res,
    float* __restrict__ Cout, int M, int K, int Nc) {
    __shared__ float Asd[2][8][256];   // duplicated: col 2m,2m+1 hold A[m]
    __shared__ float Bs[2][8][128];

    const int tid  = threadIdx.x;
    const int row0 = blockIdx.y * 128;
    const int col0 = blockIdx.x * 128;

    const int am  = tid & 127;           // A row within tile
    const int ak  = (tid >> 7) << 2;     // 0 or 4 (k offset)
    const int bkr = tid >> 5;            // 0..7  (B k row)
    const int bc  = (tid & 31) << 2;     // 0..124
    const int wr  = (tid >> 4) << 3;     // 0..120 (8 C rows)
    const int wc  = (tid & 15) << 2;     // chunk0 cols; chunk1 at +64

    const float* Aptr = A  + (size_t)(row0 + am) * K + ak;
    const float* Bptr = Bm + (size_t)bkr * Nc + col0 + bc;

    unsigned long long acc[8][4] = {};

    float4 av = *(const float4*)Aptr;
    float4 bv = *(const float4*)Bptr;

    // stage 0
    *(float2*)&Asd[0][ak + 0][2 * am] = make_float2(av.x, av.x);
    *(float2*)&Asd[0][ak + 1][2 * am] = make_float2(av.y, av.y);
    *(float2*)&Asd[0][ak + 2][2 * am] = make_float2(av.z, av.z);
    *(float2*)&Asd[0][ak + 3][2 * am] = make_float2(av.w, av.w);
    *(float4*)&Bs[0][bkr][bc] = bv;
    __syncthreads();

    int buf = 0;
    for (int k0 = 0; k0 < K; k0 += 8) {
        const bool more = (k0 + 8) < K;
        if (more) {
            av = *(const float4*)(Aptr + (k0 + 8));
            bv = *(const float4*)(Bptr + (size_t)(k0 + 8) * Nc);
        }
        #pragma unroll
        for (int kk = 0; kk < 8; ++kk) {
            ulonglong2 a01 = *(const ulonglong2*)&Asd[buf][kk][2 * wr];
            ulonglong2 a23 = *(const ulonglong2*)&Asd[buf][kk][2 * wr + 4];
            ulonglong2 a45 = *(const ulonglong2*)&Asd[buf][kk][2 * wr + 8];
            ulonglong2 a67 = *(const ulonglong2*)&Asd[buf][kk][2 * wr + 12];
            ulonglong2 bA  = *(const ulonglong2*)&Bs[buf][kk][wc];
            ulonglong2 bB  = *(const ulonglong2*)&Bs[buf][kk][wc + 64];
            unsigned long long a2[8] = {a01.x, a01.y, a23.x, a23.y,
                                        a45.x, a45.y, a67.x, a67.y};
            unsigned long long b2[4] = {bA.x, bA.y, bB.x, bB.y};
            #pragma unroll
            for (int i = 0; i < 8; ++i) {
                #pragma unroll
                for (int j = 0; j < 4; ++j) fma_f32x2(acc[i][j], a2[i], b2[j]);
            }
        }
        if (more) {
            const int nb = buf ^ 1;
            *(float2*)&Asd[nb][ak + 0][2 * am] = make_float2(av.x, av.x);
            *(float2*)&Asd[nb][ak + 1][2 * am] = make_float2(av.y, av.y);
            *(float2*)&Asd[nb][ak + 2][2 * am] = make_float2(av.z, av.z);
            *(float2*)&Asd[nb][ak + 3][2 * am] = make_float2(av.w, av.w);
            *(float4*)&Bs[nb][bkr][bc] = bv;
            __syncthreads();
            buf = nb;
        }
    }

    const int cA = col0 + wc;
    const int cB = cA + 64;
    const float4 biasA = *(const float4*)&bias[cA];
    const float4 biasB = *(const float4*)&bias[cB];
    #pragma unroll
    for (int i = 0; i < 8; ++i) {
        const size_t r = (size_t)(row0 + wr + i);
        float2 p0 = unpack_f32x2(acc[i][0]);
        float2 p1 = unpack_f32x2(acc[i][1]);
        float2 p2 = unpack_f32x2(acc[i][2]);
        float2 p3 = unpack_f32x2(acc[i][3]);
        float4 oA = make_float4(p0.x + biasA.x, p0.y + biasA.y,
                                p1.x + biasA.z, p1.y + biasA.w);
        float4 oB = make_float4(p2.x + biasB.x, p2.y + biasB.y,
                                p3.x + biasB.z, p3.y + biasB.w);
        if (EPI == 1) {
            oA.x = gelu_exact(oA.x); oA.y = gelu_exact(oA.y);
            oA.z = gelu_exact(oA.z); oA.w = gelu_exact(oA.w);
            oB.x = gelu_exact(oB.x); oB.y = gelu_exact(oB.y);
            oB.z = gelu_exact(oB.z); oB.w = gelu_exact(oB.w);
        }
        if (EPI == 2) {
            float4 rA = *(const float4*)&res[r * Nc + cA];
            float4 rB = *(const float4*)&res[r * Nc + cB];
            oA.x += rA.x; oA.y += rA.y; oA.z += rA.z; oA.w += rA.w;
            oB.x += rB.x; oB.y += rB.y; oB.z += rB.z; oB.w += rB.w;
        }
        *(float4*)&Cout[r * Nc + cA] = oA;
        *(float4*)&Cout[r * Nc + cB] = oB;
    }
}

// ---------------------------------------------------------------------------
// Fused attention for one (b, h, 16-query tile). Exact two-pass softmax,
// full 784-wide score rows in smem.
//   pass1: 2q x 4m register tile per thread, float4 smem loads
//   pass3: transposed V tile (pad 116), broadcast float4 weight loads
// smem: sS[16][784] + sQ[16][36] + union(sK[112][36], sV[32][116])
// ---------------------------------------------------------------------------
constexpr int SQ_PAD = 36;
constexpr int SK_PAD = 36;
constexpr int SV_PAD = 116;
constexpr int ATTN_SMEM =
    (16 * 784 + 16 * SQ_PAD + 112 * SK_PAD) * 4;  // 112*36=4032 >= 32*116=3712

__global__ void __launch_bounds__(256) attn_kernel(
    const float* __restrict__ q, const float* __restrict__ k,
    const float* __restrict__ v, const float* __restrict__ rel_bias,
    const int* __restrict__ rel_idx, float* __restrict__ att) {
    const int qt = blockIdx.x;   // 0..48
    const int h  = blockIdx.y;
    const int b  = blockIdx.z;
    const int n0 = qt * 16;
    const int tid = threadIdx.x;

    extern __shared__ float sm[];
    float* sS  = sm;                      // 16 x 784
    float* sQ  = sm + 16 * 784;           // 16 x 36
    float* sKV = sQ + 16 * SQ_PAD;        // union: K tile / V tile (transposed)

    // load Q tile
    #pragma unroll
    for (int e = tid; e < 16 * 32; e += 256) {
        int qi = e >> 5, d = e & 31;
        sQ[qi * SQ_PAD + d] =
            q[((size_t)(b * NPOS + n0 + qi)) * CDIM + h * DHEAD + d];
    }

    const int qg  = tid / 28;          // 0..7 (+ garbage for tid>=224)
    const int mg  = tid % 28;          // 0..27
    const int qi0 = qg * 2;
    const bool active = (tid < 224);

    // ---- pass 1: scores = q.k^T + rel_bias ----
    for (int kt = 0; kt < 7; ++kt) {
        const int m0 = kt * 112;
        __syncthreads();
        #pragma unroll
        for (int e = tid; e < 112 * 32; e += 256) {
            int mi = e >> 5, d = e & 31;
            sKV[mi * SK_PAD + d] =
                k[((size_t)(b * NPOS + m0 + mi)) * CDIM + h * DHEAD + d];
        }
        __syncthreads();
        if (active) {
            float acc[2][4] = {};
            #pragma unroll
            for (int d4 = 0; d4 < 32; d4 += 4) {
                float4 q0v = *(const float4*)&sQ[qi0 * SQ_PAD + d4];
                float4 q1v = *(const float4*)&sQ[(qi0 + 1) * SQ_PAD + d4];
                #pragma unroll
                for (int j = 0; j < 4; ++j) {
                    float4 kv = *(const float4*)&sKV[(mg + 28 * j) * SK_PAD + d4];
                    acc[0][j] = fmaf(q0v.x, kv.x, acc[0][j]);
                    acc[0][j] = fmaf(q0v.y, kv.y, acc[0][j]);
                    acc[0][j] = fmaf(q0v.z, kv.z, acc[0][j]);
                    acc[0][j] = fmaf(q0v.w, kv.w, acc[0][j]);
                    acc[1][j] = fmaf(q1v.x, kv.x, acc[1][j]);
                    acc[1][j] = fmaf(q1v.y, kv.y, acc[1][j]);
                    acc[1][j] = fmaf(q1v.z, kv.z, acc[1][j]);
                    acc[1][j] = fmaf(q1v.w, kv.w, acc[1][j]);
                }
            }
            int   rl[2][4];
            #pragma unroll
            for (int r = 0; r < 2; ++r)
                #pragma unroll
                for (int j = 0; j < 4; ++j)
                    rl[r][j] = rel_idx[(size_t)(n0 + qi0 + r) * NPOS +
                                       (m0 + mg + 28 * j)];
            #pragma unroll
            for (int r = 0; r < 2; ++r)
                #pragma unroll
                for (int j = 0; j < 4; ++j) {
                    const int m = m0 + mg + 28 * j;
                    sS[(qi0 + r) * 784 + m] =
                        acc[r][j] + rel_bias[h * NREL + rl[r][j]];
                }
        }
    }
    __syncthreads();

    // ---- pass 2: softmax per query row (warp w handles rows w, w+8) ----
    {
        const int warp = tid >> 5, lane = tid & 31;
        #pragma unroll
        for (int rr = 0; rr < 2; ++rr) {
            float* row = sS + (warp + rr * 8) * 784;
            float mx = -1e30f;
            for (int m = lane; m < 784; m += 32) mx = fmaxf(mx, row[m]);
            #pragma unroll
            for (int o = 16; o; o >>= 1)
                mx = fmaxf(mx, __shfl_xor_sync(0xffffffffu, mx, o));
            float sum = 0.0f;
            for (int m = lane; m < 784; m += 32) {
                float e = expf(row[m] - mx);
                row[m] = e;
                sum += e;
            }
            #pragma unroll
            for (int o = 16; o; o >>= 1)
                sum += __shfl_xor_sync(0xffffffffu, sum, o);
            const float inv = 1.0f / sum;
            for (int m = lane; m < 784; m += 32) row[m] *= inv;
        }
    }

    // ---- pass 3: out = attn @ v  (V transposed in smem) ----
    const int warp = tid >> 5;   // row pair {warp, warp+8}
    const int d    = tid & 31;
    float acc0 = 0.0f, acc1 = 0.0f;
    for (int kt = 0; kt < 7; ++kt) {
        const int m0 = kt * 112;
        __syncthreads();
        #pragma unroll
        for (int e = tid; e < 112 * 32; e += 256) {
            int mi = e >> 5, dd = e & 31;
            sKV[dd * SV_PAD + mi] =
                v[((size_t)(b * NPOS + m0 + mi)) * CDIM + h * DHEAD + dd];
        }
        __syncthreads();
        const float* w0 = &sS[warp * 784 + m0];
        const float* w1 = &sS[(warp + 8) * 784 + m0];
        const float* vr = &sKV[d * SV_PAD];
        #pragma unroll 7
        for (int mi = 0; mi < 112; mi += 4) {
            float4 a0 = *(const float4*)&w0[mi];   // broadcast
            float4 a1 = *(const float4*)&w1[mi];   // broadcast
            float4 vv = *(const float4*)&vr[mi];
            acc0 = fmaf(a0.x, vv.x, acc0);
            acc0 = fmaf(a0.y, vv.y, acc0);
            acc0 = fmaf(a0.z, vv.z, acc0);
            acc0 = fmaf(a0.w, vv.w, acc0);
            acc1 = fmaf(a1.x, vv.x, acc1);
            acc1 = fmaf(a1.y, vv.y, acc1);
            acc1 = fmaf(a1.z, vv.z, acc1);
            acc1 = fmaf(a1.w, vv.w, acc1);
        }
    }
    att[((size_t)(b * NPOS + n0 + warp)) * CDIM + h * DHEAD + d]     = acc0;
    att[((size_t)(b * NPOS + n0 + warp + 8)) * CDIM + h * DHEAD + d] = acc1;
}

// ---------------------------------------------------------------------------
// Launch
// ---------------------------------------------------------------------------
extern "C" void kernel_launch(void* const* d_in, const int* in_sizes, int n_in,
                              void* d_out, int out_size) {
    (void)in_sizes; (void)n_in; (void)out_size;
    const float* x      = (const float*)d_in[0];
    const float* ln_w   = (const float*)d_in[1];
    const float* ln_b   = (const float*)d_in[2];
    const float* Wq     = (const float*)d_in[3];
    const float* bq     = (const float*)d_in[4];
    const float* Wk     = (const float*)d_in[5];
    const float* bk     = (const float*)d_in[6];
    const float* Wv     = (const float*)d_in[7];
    const float* bv     = (const float*)d_in[8];
    const float* Wo     = (const float*)d_in[9];
    const float* bo     = (const float*)d_in[10];
    const float* relb   = (const float*)d_in[11];
    const float* W1     = (const float*)d_in[12];
    const float* b1     = (const float*)d_in[13];
    const float* W2     = (const float*)d_in[14];
    const float* b2     = (const float*)d_in[15];
    const int*   relidx = (const int*)d_in[16];
    float* out = (float*)d_out;

    float* buf = nullptr;
    cudaGetSymbolAddress((void**)&buf, g_buf);
    float* xc  = buf + 0 * SZ_NC;
    float* xn  = buf + 1 * SZ_NC;
    float* qb  = buf + 2 * SZ_NC;
    float* kb  = buf + 3 * SZ_NC;
    float* vb  = buf + 4 * SZ_NC;
    float* att = buf + 5 * SZ_NC;
    float* x1  = buf + 6 * SZ_NC;
    float* x2  = buf + 7 * SZ_NC;
    float* h1  = buf + 8 * SZ_NC;

    cudaFuncSetAttribute(attn_kernel,
                         cudaFuncAttributeMaxDynamicSharedMemorySize,
                         ATTN_SMEM);

    const dim3 tb(32, 8);
    transpose_kernel<<<dim3(25, 16, BATCH), tb>>>(x, xc, CDIM, NPOS);
    ln_kernel<<<MROWS, 128>>>(xc, ln_w, ln_b, xn);

    const dim3 g512(CDIM / 128, MROWS / 128);   // (4, 98)
    const dim3 g2048(FFD / 128, MROWS / 128);   // (16, 98)
    gemm_kernel<0><<<g512, 256>>>(xn, Wq, bq, nullptr, qb, MROWS, CDIM, CDIM);
    gemm_kernel<0><<<g512, 256>>>(xn, Wk, bk, nullptr, kb, MROWS, CDIM, CDIM);
    gemm_kernel<0><<<g512, 256>>>(xn, Wv, bv, nullptr, vb, MROWS, CDIM, CDIM);

    attn_kernel<<<dim3(49, NHEADS, BATCH), 256, ATTN_SMEM>>>(qb, kb, vb, relb,
                                                             relidx, att);

    gemm_kernel<2><<<g512, 256>>>(att, Wo, bo, xc, x1, MROWS, CDIM, CDIM);
    gemm_kernel<1><<<g2048, 256>>>(x1, W1, b1, nullptr, h1, MROWS, CDIM, FFD);
    gemm_kernel<2><<<g512, 256>>>(h1, W2, b2, x1, x2, MROWS, FFD, CDIM);

    transpose_kernel<<<dim3(16, 25, BATCH), tb>>>(x2, out, NPOS, CDIM);
}

// round 10
// speedup vs baseline: 1.0007x; 1.0004x over previous
#include <cuda_runtime.h>
#include <math.h>

// ---------------------------------------------------------------------------
// Problem constants
// ---------------------------------------------------------------------------
constexpr int BATCH  = 16;
constexpr int NPOS   = 784;          // 28*28
constexpr int CDIM   = 512;
constexpr int NHEADS = 16;
constexpr int DHEAD  = 32;
constexpr int FFD    = 2048;
constexpr int NREL   = 1596;
constexpr int MROWS  = BATCH * NPOS; // 12544

constexpr size_t SZ_NC = (size_t)BATCH * NPOS * CDIM;
constexpr size_t SZ_FF = (size_t)BATCH * NPOS * FFD;

__device__ float g_buf[8 * SZ_NC + SZ_FF];

// ---------------------------------------------------------------------------
// Helpers
// ---------------------------------------------------------------------------
__device__ __forceinline__ void fma_f32x2(unsigned long long& d,
                                          unsigned long long a,
                                          unsigned long long b) {
    asm("fma.rn.f32x2 %0, %1, %2, %0;" : "+l"(d) : "l"(a), "l"(b));
}
__device__ __forceinline__ float2 unpack_f32x2(unsigned long long v) {
    return make_float2(__uint_as_float((unsigned int)(v & 0xffffffffull)),
                       __uint_as_float((unsigned int)(v >> 32)));
}
__device__ __forceinline__ float gelu_exact(float x) {
    return 0.5f * x * (1.0f + erff(x * 0.7071067811865476f));
}

// ---------------------------------------------------------------------------
// Tiled 2D transpose per batch:  src [R][Cc]  ->  dst [Cc][R]
// ---------------------------------------------------------------------------
__global__ void transpose_kernel(const float* __restrict__ in,
                                 float* __restrict__ out, int R, int Cc) {
    __shared__ float tile[32][33];
    const int b = blockIdx.z;
    const float* src = in  + (size_t)b * R * Cc;
    float*       dst = out + (size_t)b * R * Cc;
    const int c0 = blockIdx.x * 32;
    const int r0 = blockIdx.y * 32;
    const int tx = threadIdx.x, ty = threadIdx.y;

    #pragma unroll
    for (int j = 0; j < 32; j += 8) {
        int r = r0 + ty + j, c = c0 + tx;
        if (r < R && c < Cc) tile[ty + j][tx] = src[(size_t)r * Cc + c];
    }
    __syncthreads();
    #pragma unroll
    for (int j = 0; j < 32; j += 8) {
        int oc = c0 + ty + j;
        int orr = r0 + tx;
        if (oc < Cc && orr < R) dst[(size_t)oc * R + orr] = tile[tx][ty + j];
    }
}

// ---------------------------------------------------------------------------
// LayerNorm over C=512, one block (128 threads) per (b,n) row
// ---------------------------------------------------------------------------
__global__ void __launch_bounds__(128) ln_kernel(const float* __restrict__ xc,
                                                 const float* __restrict__ w,
                                                 const float* __restrict__ bsh,
                                                 float* __restrict__ xn) {
    const int row = blockIdx.x;
    const int tid = threadIdx.x;
    const float* xr = xc + (size_t)row * CDIM;
    float4 v = *(const float4*)&xr[tid << 2];
    float s  = v.x + v.y + v.z + v.w;
    float ss = v.x * v.x + v.y * v.y + v.z * v.z + v.w * v.w;
    #pragma unroll
    for (int o = 16; o; o >>= 1) {
        s  += __shfl_xor_sync(0xffffffffu, s, o);
        ss += __shfl_xor_sync(0xffffffffu, ss, o);
    }
    __shared__ float rs[4], rss[4];
    const int warp = tid >> 5, lane = tid & 31;
    if (lane == 0) { rs[warp] = s; rss[warp] = ss; }
    __syncthreads();
    if (tid == 0) {
        float S  = rs[0] + rs[1] + rs[2] + rs[3];
        float SS = rss[0] + rss[1] + rss[2] + rss[3];
        float mu  = S * (1.0f / CDIM);
        float var = SS * (1.0f / CDIM) - mu * mu;
        rs[0]  = mu;
        rss[0] = rsqrtf(var + 1e-5f);
    }
    __syncthreads();
    const float mu = rs[0], rstd = rss[0];
    float4 wv = *(const float4*)&w[tid << 2];
    float4 bv = *(const float4*)&bsh[tid << 2];
    float4 o;
    o.x = (v.x - mu) * rstd * wv.x + bv.x;
    o.y = (v.y - mu) * rstd * wv.y + bv.y;
    o.z = (v.z - mu) * rstd * wv.z + bv.z;
    o.w = (v.w - mu) * rstd * wv.w + bv.w;
    *(float4*)&xn[(size_t)row * CDIM + (tid << 2)] = o;
}

// ---------------------------------------------------------------------------
// fp32 GEMM, 128x128 tile, BK=8, 256 threads, 8x8 microtile, f32x2 FMAs.
// A stored duplicated in smem ({a,a} pairs -> no pack MOVs); B fragment split
// into two 16B chunks 64 cols apart (conflict-free LDS.128); double-buffered
// smem (1 sync per k-step).
// EPI: 0 = bias, 1 = bias+gelu(exact), 2 = bias+residual
// ---------------------------------------------------------------------------
template <int EPI>
__global__ void __launch_bounds__(256, 2) gemm_kernel(
    const float* __restrict__ A, const float* __restrict__ Bm,
    const float* __restrict__ bias, const float* __restrict__ res,
    float* __restrict__ Cout, int M, int K, int Nc) {
    __shared__ float Asd[2][8][256];   // duplicated: col 2m,2m+1 hold A[m]
    __shared__ float Bs[2][8][128];

    const int tid  = threadIdx.x;
    const int row0 = blockIdx.y * 128;
    const int col0 = blockIdx.x * 128;

    const int am  = tid & 127;           // A row within tile
    const int ak  = (tid >> 7) << 2;     // 0 or 4 (k offset)
    const int bkr = tid >> 5;            // 0..7  (B k row)
    const int bc  = (tid & 31) << 2;     // 0..124
    const int wr  = (tid >> 4) << 3;     // 0..120 (8 C rows)
    const int wc  = (tid & 15) << 2;     // chunk0 cols; chunk1 at +64

    const float* Aptr = A  + (size_t)(row0 + am) * K + ak;
    const float* Bptr = Bm + (size_t)bkr * Nc + col0 + bc;

    unsigned long long acc[8][4] = {};

    float4 av = *(const float4*)Aptr;
    float4 bv = *(const float4*)Bptr;

    // stage 0
    *(float2*)&Asd[0][ak + 0][2 * am] = make_float2(av.x, av.x);
    *(float2*)&Asd[0][ak + 1][2 * am] = make_float2(av.y, av.y);
    *(float2*)&Asd[0][ak + 2][2 * am] = make_float2(av.z, av.z);
    *(float2*)&Asd[0][ak + 3][2 * am] = make_float2(av.w, av.w);
    *(float4*)&Bs[0][bkr][bc] = bv;
    __syncthreads();

    int buf = 0;
    for (int k0 = 0; k0 < K; k0 += 8) {
        const bool more = (k0 + 8) < K;
        if (more) {
            av = *(const float4*)(Aptr + (k0 + 8));
            bv = *(const float4*)(Bptr + (size_t)(k0 + 8) * Nc);
        }
        #pragma unroll
        for (int kk = 0; kk < 8; ++kk) {
            ulonglong2 a01 = *(const ulonglong2*)&Asd[buf][kk][2 * wr];
            ulonglong2 a23 = *(const ulonglong2*)&Asd[buf][kk][2 * wr + 4];
            ulonglong2 a45 = *(const ulonglong2*)&Asd[buf][kk][2 * wr + 8];
            ulonglong2 a67 = *(const ulonglong2*)&Asd[buf][kk][2 * wr + 12];
            ulonglong2 bA  = *(const ulonglong2*)&Bs[buf][kk][wc];
            ulonglong2 bB  = *(const ulonglong2*)&Bs[buf][kk][wc + 64];
            unsigned long long a2[8] = {a01.x, a01.y, a23.x, a23.y,
                                        a45.x, a45.y, a67.x, a67.y};
            unsigned long long b2[4] = {bA.x, bA.y, bB.x, bB.y};
            #pragma unroll
            for (int i = 0; i < 8; ++i) {
                #pragma unroll
                for (int j = 0; j < 4; ++j) fma_f32x2(acc[i][j], a2[i], b2[j]);
            }
        }
        if (more) {
            const int nb = buf ^ 1;
            *(float2*)&Asd[nb][ak + 0][2 * am] = make_float2(av.x, av.x);
            *(float2*)&Asd[nb][ak + 1][2 * am] = make_float2(av.y, av.y);
            *(float2*)&Asd[nb][ak + 2][2 * am] = make_float2(av.z, av.z);
            *(float2*)&Asd[nb][ak + 3][2 * am] = make_float2(av.w, av.w);
            *(float4*)&Bs[nb][bkr][bc] = bv;
            __syncthreads();
            buf = nb;
        }
    }

    const int cA = col0 + wc;
    const int cB = cA + 64;
    const float4 biasA = *(const float4*)&bias[cA];
    const float4 biasB = *(const float4*)&bias[cB];
    #pragma unroll
    for (int i = 0; i < 8; ++i) {
        const size_t r = (size_t)(row0 + wr + i);
        float2 p0 = unpack_f32x2(acc[i][0]);
        float2 p1 = unpack_f32x2(acc[i][1]);
        float2 p2 = unpack_f32x2(acc[i][2]);
        float2 p3 = unpack_f32x2(acc[i][3]);
        float4 oA = make_float4(p0.x + biasA.x, p0.y + biasA.y,
                                p1.x + biasA.z, p1.y + biasA.w);
        float4 oB = make_float4(p2.x + biasB.x, p2.y + biasB.y,
                                p3.x + biasB.z, p3.y + biasB.w);
        if (EPI == 1) {
            oA.x = gelu_exact(oA.x); oA.y = gelu_exact(oA.y);
            oA.z = gelu_exact(oA.z); oA.w = gelu_exact(oA.w);
            oB.x = gelu_exact(oB.x); oB.y = gelu_exact(oB.y);
            oB.z = gelu_exact(oB.z); oB.w = gelu_exact(oB.w);
        }
        if (EPI == 2) {
            float4 rA = *(const float4*)&res[r * Nc + cA];
            float4 rB = *(const float4*)&res[r * Nc + cB];
            oA.x += rA.x; oA.y += rA.y; oA.z += rA.z; oA.w += rA.w;
            oB.x += rB.x; oB.y += rB.y; oB.z += rB.z; oB.w += rB.w;
        }
        *(float4*)&Cout[r * Nc + cA] = oA;
        *(float4*)&Cout[r * Nc + cB] = oB;
    }
}

// ---------------------------------------------------------------------------
// Fused attention for one (b, h, 16-query tile). Exact two-pass softmax,
// full 784-wide score rows in smem.
//   pass1: 2q x 4m register tile per thread, float4 smem loads
//   pass3: transposed V tile (pad 116), broadcast float4 weight loads
// smem: sS[16][784] + sQ[16][36] + union(sK[112][36], sV[32][116])
// ---------------------------------------------------------------------------
constexpr int SQ_PAD = 36;
constexpr int SK_PAD = 36;
constexpr int SV_PAD = 116;
constexpr int ATTN_SMEM =
    (16 * 784 + 16 * SQ_PAD + 112 * SK_PAD) * 4;  // 112*36=4032 >= 32*116=3712

__global__ void __launch_bounds__(256) attn_kernel(
    const float* __restrict__ q, const float* __restrict__ k,
    const float* __restrict__ v, const float* __restrict__ rel_bias,
    const int* __restrict__ rel_idx, float* __restrict__ att) {
    const int qt = blockIdx.x;   // 0..48
    const int h  = blockIdx.y;
    const int b  = blockIdx.z;
    const int n0 = qt * 16;
    const int tid = threadIdx.x;

    extern __shared__ float sm[];
    float* sS  = sm;                      // 16 x 784
    float* sQ  = sm + 16 * 784;           // 16 x 36
    float* sKV = sQ + 16 * SQ_PAD;        // union: K tile / V tile (transposed)

    // load Q tile
    #pragma unroll
    for (int e = tid; e < 16 * 32; e += 256) {
        int qi = e >> 5, d = e & 31;
        sQ[qi * SQ_PAD + d] =
            q[((size_t)(b * NPOS + n0 + qi)) * CDIM + h * DHEAD + d];
    }

    const int qg  = tid / 28;          // 0..7 (+ garbage for tid>=224)
    const int mg  = tid % 28;          // 0..27
    const int qi0 = qg * 2;
    const bool active = (tid < 224);

    // ---- pass 1: scores = q.k^T + rel_bias ----
    for (int kt = 0; kt < 7; ++kt) {
        const int m0 = kt * 112;
        __syncthreads();
        #pragma unroll
        for (int e = tid; e < 112 * 32; e += 256) {
            int mi = e >> 5, d = e & 31;
            sKV[mi * SK_PAD + d] =
                k[((size_t)(b * NPOS + m0 + mi)) * CDIM + h * DHEAD + d];
        }
        __syncthreads();
        if (active) {
            float acc[2][4] = {};
            #pragma unroll
            for (int d4 = 0; d4 < 32; d4 += 4) {
                float4 q0v = *(const float4*)&sQ[qi0 * SQ_PAD + d4];
                float4 q1v = *(const float4*)&sQ[(qi0 + 1) * SQ_PAD + d4];
                #pragma unroll
                for (int j = 0; j < 4; ++j) {
                    float4 kv = *(const float4*)&sKV[(mg + 28 * j) * SK_PAD + d4];
                    acc[0][j] = fmaf(q0v.x, kv.x, acc[0][j]);
                    acc[0][j] = fmaf(q0v.y, kv.y, acc[0][j]);
                    acc[0][j] = fmaf(q0v.z, kv.z, acc[0][j]);
                    acc[0][j] = fmaf(q0v.w, kv.w, acc[0][j]);
                    acc[1][j] = fmaf(q1v.x, kv.x, acc[1][j]);
                    acc[1][j] = fmaf(q1v.y, kv.y, acc[1][j]);
                    acc[1][j] = fmaf(q1v.z, kv.z, acc[1][j]);
                    acc[1][j] = fmaf(q1v.w, kv.w, acc[1][j]);
                }
            }
            int   rl[2][4];
            #pragma unroll
            for (int r = 0; r < 2; ++r)
                #pragma unroll
                for (int j = 0; j < 4; ++j)
                    rl[r][j] = rel_idx[(size_t)(n0 + qi0 + r) * NPOS +
                                       (m0 + mg + 28 * j)];
            #pragma unroll
            for (int r = 0; r < 2; ++r)
                #pragma unroll
                for (int j = 0; j < 4; ++j) {
                    const int m = m0 + mg + 28 * j;
                    sS[(qi0 + r) * 784 + m] =
                        acc[r][j] + rel_bias[h * NREL + rl[r][j]];
                }
        }
    }
    __syncthreads();

    // ---- pass 2: softmax per query row (warp w handles rows w, w+8) ----
    {
        const int warp = tid >> 5, lane = tid & 31;
        #pragma unroll
        for (int rr = 0; rr < 2; ++rr) {
            float* row = sS + (warp + rr * 8) * 784;
            float mx = -1e30f;
            for (int m = lane; m < 784; m += 32) mx = fmaxf(mx, row[m]);
            #pragma unroll
            for (int o = 16; o; o >>= 1)
                mx = fmaxf(mx, __shfl_xor_sync(0xffffffffu, mx, o));
            float sum = 0.0f;
            for (int m = lane; m < 784; m += 32) {
                float e = expf(row[m] - mx);
                row[m] = e;
                sum += e;
            }
            #pragma unroll
            for (int o = 16; o; o >>= 1)
                sum += __shfl_xor_sync(0xffffffffu, sum, o);
            const float inv = 1.0f / sum;
            for (int m = lane; m < 784; m += 32) row[m] *= inv;
        }
    }

    // ---- pass 3: out = attn @ v  (V transposed in smem) ----
    const int warp = tid >> 5;   // row pair {warp, warp+8}
    const int d    = tid & 31;
    float acc0 = 0.0f, acc1 = 0.0f;
    for (int kt = 0; kt < 7; ++kt) {
        const int m0 = kt * 112;
        __syncthreads();
        #pragma unroll
        for (int e = tid; e < 112 * 32; e += 256) {
            int mi = e >> 5, dd = e & 31;
            sKV[dd * SV_PAD + mi] =
                v[((size_t)(b * NPOS + m0 + mi)) * CDIM + h * DHEAD + dd];
        }
        __syncthreads();
        const float* w0 = &sS[warp * 784 + m0];
        const float* w1 = &sS[(warp + 8) * 784 + m0];
        const float* vr = &sKV[d * SV_PAD];
        #pragma unroll 7
        for (int mi = 0; mi < 112; mi += 4) {
            float4 a0 = *(const float4*)&w0[mi];   // broadcast
            float4 a1 = *(const float4*)&w1[mi];   // broadcast
            float4 vv = *(const float4*)&vr[mi];
            acc0 = fmaf(a0.x, vv.x, acc0);
            acc0 = fmaf(a0.y, vv.y, acc0);
            acc0 = fmaf(a0.z, vv.z, acc0);
            acc0 = fmaf(a0.w, vv.w, acc0);
            acc1 = fmaf(a1.x, vv.x, acc1);
            acc1 = fmaf(a1.y, vv.y, acc1);
            acc1 = fmaf(a1.z, vv.z, acc1);
            acc1 = fmaf(a1.w, vv.w, acc1);
        }
    }
    att[((size_t)(b * NPOS + n0 + warp)) * CDIM + h * DHEAD + d]     = acc0;
    att[((size_t)(b * NPOS + n0 + warp + 8)) * CDIM + h * DHEAD + d] = acc1;
}

// ---------------------------------------------------------------------------
// Launch
// ---------------------------------------------------------------------------
extern "C" void kernel_launch(void* const* d_in, const int* in_sizes, int n_in,
                              void* d_out, int out_size) {
    (void)in_sizes; (void)n_in; (void)out_size;
    const float* x      = (const float*)d_in[0];
    const float* ln_w   = (const float*)d_in[1];
    const float* ln_b   = (const float*)d_in[2];
    const float* Wq     = (const float*)d_in[3];
    const float* bq     = (const float*)d_in[4];
    const float* Wk     = (const float*)d_in[5];
    const float* bk     = (const float*)d_in[6];
    const float* Wv     = (const float*)d_in[7];
    const float* bv     = (const float*)d_in[8];
    const float* Wo     = (const float*)d_in[9];
    const float* bo     = (const float*)d_in[10];
    const float* relb   = (const float*)d_in[11];
    const float* W1     = (const float*)d_in[12];
    const float* b1     = (const float*)d_in[13];
    const float* W2     = (const float*)d_in[14];
    const float* b2     = (const float*)d_in[15];
    const int*   relidx = (const int*)d_in[16];
    float* out = (float*)d_out;

    float* buf = nullptr;
    cudaGetSymbolAddress((void**)&buf, g_buf);
    float* xc  = buf + 0 * SZ_NC;
    float* xn  = buf + 1 * SZ_NC;
    float* qb  = buf + 2 * SZ_NC;
    float* kb  = buf + 3 * SZ_NC;
    float* vb  = buf + 4 * SZ_NC;
    float* att = buf + 5 * SZ_NC;
    float* x1  = buf + 6 * SZ_NC;
    float* x2  = buf + 7 * SZ_NC;
    float* h1  = buf + 8 * SZ_NC;

    cudaFuncSetAttribute(attn_kernel,
                         cudaFuncAttributeMaxDynamicSharedMemorySize,
                         ATTN_SMEM);

    const dim3 tb(32, 8);
    transpose_kernel<<<dim3(25, 16, BATCH), tb>>>(x, xc, CDIM, NPOS);
    ln_kernel<<<MROWS, 128>>>(xc, ln_w, ln_b, xn);

    const dim3 g512(CDIM / 128, MROWS / 128);   // (4, 98)
    const dim3 g2048(FFD / 128, MROWS / 128);   // (16, 98)
    gemm_kernel<0><<<g512, 256>>>(xn, Wq, bq, nullptr, qb, MROWS, CDIM, CDIM);
    gemm_kernel<0><<<g512, 256>>>(xn, Wk, bk, nullptr, kb, MROWS, CDIM, CDIM);
    gemm_kernel<0><<<g512, 256>>>(xn, Wv, bv, nullptr, vb, MROWS, CDIM, CDIM);

    attn_kernel<<<dim3(49, NHEADS, BATCH), 256, ATTN_SMEM>>>(qb, kb, vb, relb,
                                                             relidx, att);

    gemm_kernel<2><<<g512, 256>>>(att, Wo, bo, xc, x1, MROWS, CDIM, CDIM);
    gemm_kernel<1><<<g2048, 256>>>(x1, W1, b1, nullptr, h1, MROWS, CDIM, FFD);
    gemm_kernel<2><<<g512, 256>>>(h1, W2, b2, x1, x2, MROWS, FFD, CDIM);

    transpose_kernel<<<dim3(16, 25, BATCH), tb>>>(x2, out, NPOS, CDIM);
}

// round 12
// speedup vs baseline: 1.2968x; 1.2959x over previous
#include <cuda_runtime.h>
#include <cuda_bf16.h>
#include <math.h>
#include <stdint.h>

// ---------------------------------------------------------------------------
// Problem constants
// ---------------------------------------------------------------------------
constexpr int BATCH  = 16;
constexpr int NPOS   = 784;          // 28*28
constexpr int CDIM   = 512;
constexpr int NHEADS = 16;
constexpr int DHEAD  = 32;
constexpr int FFD    = 2048;
constexpr int NREL   = 1596;
constexpr int MROWS  = BATCH * NPOS; // 12544

constexpr size_t SZ_NC = (size_t)MROWS * CDIM;
constexpr size_t SZ_FF = (size_t)MROWS * FFD;

// ---------------------------------------------------------------------------
// Global scratch (static __device__ arrays — no allocation)
// ---------------------------------------------------------------------------
__device__ float g_xc[SZ_NC];
__device__ float g_q [SZ_NC];
__device__ float g_k [SZ_NC];
__device__ float g_v [SZ_NC];
__device__ float g_x1[SZ_NC];
__device__ float g_x2[SZ_NC];

__device__ __nv_bfloat16 g_xnh[SZ_NC],  g_xnl[SZ_NC];
__device__ __nv_bfloat16 g_atth[SZ_NC], g_attl[SZ_NC];
__device__ __nv_bfloat16 g_x1h[SZ_NC],  g_x1l[SZ_NC];
__device__ __nv_bfloat16 g_h1h[SZ_FF],  g_h1l[SZ_FF];

__device__ __nv_bfloat16 g_wqh[CDIM*CDIM], g_wql[CDIM*CDIM];
__device__ __nv_bfloat16 g_wkh[CDIM*CDIM], g_wkl[CDIM*CDIM];
__device__ __nv_bfloat16 g_wvh[CDIM*CDIM], g_wvl[CDIM*CDIM];
__device__ __nv_bfloat16 g_woh[CDIM*CDIM], g_wol[CDIM*CDIM];
__device__ __nv_bfloat16 g_w1h[(size_t)CDIM*FFD], g_w1l[(size_t)CDIM*FFD];
__device__ __nv_bfloat16 g_w2h[(size_t)FFD*CDIM], g_w2l[(size_t)FFD*CDIM];

// ---------------------------------------------------------------------------
// Helpers
// ---------------------------------------------------------------------------
__device__ __forceinline__ uint32_t smem_u32(const void* p) {
    uint32_t a;
    asm("{ .reg .u64 t; cvta.to.shared.u64 t, %1; cvt.u32.u64 %0, t; }"
        : "=r"(a) : "l"(p));
    return a;
}
__device__ __forceinline__ float gelu_exact(float x) {
    return 0.5f * x * (1.0f + erff(x * 0.7071067811865476f));
}
__device__ __forceinline__ void split_bf16(float a, __nv_bfloat16& h,
                                           __nv_bfloat16& l) {
    h = __float2bfloat16(a);
    l = __float2bfloat16(a - __bfloat162float(h));
}
__device__ __forceinline__ void ldm4(uint32_t* r, uint32_t addr) {
    asm volatile(
        "ldmatrix.sync.aligned.m8n8.x4.shared.b16 {%0,%1,%2,%3}, [%4];"
        : "=r"(r[0]), "=r"(r[1]), "=r"(r[2]), "=r"(r[3]) : "r"(addr)
        : "memory");
}
__device__ __forceinline__ void mma_bf16(float* c, const uint32_t* a,
                                         const uint32_t* b) {
    asm volatile(
        "mma.sync.aligned.m16n8k16.row.col.f32.bf16.bf16.f32 "
        "{%0,%1,%2,%3},{%4,%5,%6,%7},{%8,%9},{%0,%1,%2,%3};"
        : "+f"(c[0]), "+f"(c[1]), "+f"(c[2]), "+f"(c[3])
        : "r"(a[0]), "r"(a[1]), "r"(a[2]), "r"(a[3]), "r"(b[0]), "r"(b[1]));
}

// ---------------------------------------------------------------------------
// Tiled 2D transpose per batch:  src [R][Cc]  ->  dst [Cc][R]
// ---------------------------------------------------------------------------
__global__ void transpose_kernel(const float* __restrict__ in,
                                 float* __restrict__ out, int R, int Cc) {
    __shared__ float tile[32][33];
    const int b = blockIdx.z;
    const float* src = in  + (size_t)b * R * Cc;
    float*       dst = out + (size_t)b * R * Cc;
    const int c0 = blockIdx.x * 32;
    const int r0 = blockIdx.y * 32;
    const int tx = threadIdx.x, ty = threadIdx.y;
    #pragma unroll
    for (int j = 0; j < 32; j += 8) {
        int r = r0 + ty + j, c = c0 + tx;
        if (r < R && c < Cc) tile[ty + j][tx] = src[(size_t)r * Cc + c];
    }
    __syncthreads();
    #pragma unroll
    for (int j = 0; j < 32; j += 8) {
        int oc = c0 + ty + j, orr = r0 + tx;
        if (oc < Cc && orr < R) dst[(size_t)oc * R + orr] = tile[tx][ty + j];
    }
}

// ---------------------------------------------------------------------------
// Weight prep: W[K][N] fp32  ->  Bh/Bl [N][K] bf16 (hi/lo split)
// ---------------------------------------------------------------------------
__global__ void wprep_kernel(const float* __restrict__ W,
                             __nv_bfloat16* __restrict__ Bh,
                             __nv_bfloat16* __restrict__ Bl, int K, int N) {
    __shared__ float t[32][33];
    const int n0 = blockIdx.x * 32, k0 = blockIdx.y * 32;
    const int tx = threadIdx.x, ty = threadIdx.y;
    #pragma unroll
    for (int j = 0; j < 32; j += 8)
        t[ty + j][tx] = W[(size_t)(k0 + ty + j) * N + n0 + tx];
    __syncthreads();
    #pragma unroll
    for (int j = 0; j < 32; j += 8) {
        float vv = t[tx][ty + j];
        __nv_bfloat16 h, l;
        split_bf16(vv, h, l);
        size_t idx = (size_t)(n0 + ty + j) * K + k0 + tx;
        Bh[idx] = h;
        Bl[idx] = l;
    }
}

// ---------------------------------------------------------------------------
// LayerNorm over C=512, one block (128 threads) per row; emits bf16 hi/lo
// ---------------------------------------------------------------------------
__global__ void __launch_bounds__(128) ln_kernel(const float* __restrict__ xc,
                                                 const float* __restrict__ w,
                                                 const float* __restrict__ bsh,
                                                 __nv_bfloat16* __restrict__ xh,
                                                 __nv_bfloat16* __restrict__ xl) {
    const int row = blockIdx.x;
    const int tid = threadIdx.x;
    const float* xr = xc + (size_t)row * CDIM;
    float4 v = *(const float4*)&xr[tid << 2];
    float s  = v.x + v.y + v.z + v.w;
    float ss = v.x * v.x + v.y * v.y + v.z * v.z + v.w * v.w;
    #pragma unroll
    for (int o = 16; o; o >>= 1) {
        s  += __shfl_xor_sync(0xffffffffu, s, o);
        ss += __shfl_xor_sync(0xffffffffu, ss, o);
    }
    __shared__ float rs[4], rss[4];
    const int warp = tid >> 5, lane = tid & 31;
    if (lane == 0) { rs[warp] = s; rss[warp] = ss; }
    __syncthreads();
    if (tid == 0) {
        float S  = rs[0] + rs[1] + rs[2] + rs[3];
        float SS = rss[0] + rss[1] + rss[2] + rss[3];
        float mu  = S * (1.0f / CDIM);
        float var = SS * (1.0f / CDIM) - mu * mu;
        rs[0]  = mu;
        rss[0] = rsqrtf(var + 1e-5f);
    }
    __syncthreads();
    const float mu = rs[0], rstd = rss[0];
    float4 wv = *(const float4*)&w[tid << 2];
    float4 bv = *(const float4*)&bsh[tid << 2];
    float o[4];
    o[0] = (v.x - mu) * rstd * wv.x + bv.x;
    o[1] = (v.y - mu) * rstd * wv.y + bv.y;
    o[2] = (v.z - mu) * rstd * wv.z + bv.z;
    o[3] = (v.w - mu) * rstd * wv.w + bv.w;
    __nv_bfloat16 h[4], l[4];
    #pragma unroll
    for (int i = 0; i < 4; ++i) split_bf16(o[i], h[i], l[i]);
    uint2 hp, lp;
    __nv_bfloat162 t;
    t = __halves2bfloat162(h[0], h[1]); hp.x = *(uint32_t*)&t;
    t = __halves2bfloat162(h[2], h[3]); hp.y = *(uint32_t*)&t;
    t = __halves2bfloat162(l[0], l[1]); lp.x = *(uint32_t*)&t;
    t = __halves2bfloat162(l[2], l[3]); lp.y = *(uint32_t*)&t;
    *(uint2*)&xh[(size_t)row * CDIM + (tid << 2)] = hp;
    *(uint2*)&xl[(size_t)row * CDIM + (tid << 2)] = lp;
}

// ---------------------------------------------------------------------------
// HMMA bf16x3 GEMM:  C = A @ B^T   (A [M][K], B [N][K], bf16 hi/lo)
// CTA 128x128, BK=32, 256 threads; warp tile 32x64 (4m x 2n warps).
// Double-buffered swizzled smem; ldmatrix fragments; mma.m16n8k16 bf16.
// EPI: 0=bias, 1=bias+gelu, 2=bias+residual.  WF: fp32 out.  WH: hi/lo out.
// ---------------------------------------------------------------------------
constexpr int GT_TILE  = 128 * 32 * 2;          // 8 KB per bf16 tile
constexpr int GT_STAGE = 4 * GT_TILE;           // Ah, Al, Bh, Bl = 32 KB
constexpr int GDSMEM   = 2 * GT_STAGE;          // 64 KB

// swizzled byte offset of (row, 16B-chunk kc) inside a [128][32]bf16 tile
__device__ __forceinline__ uint32_t sw_off(int row, int kc) {
    return (uint32_t)(row * 64 + ((kc ^ ((row >> 1) & 3)) << 4));
}

template <int EPI, int WF, int WH>
__global__ void __launch_bounds__(256, 2) hmma_gemm(
    const __nv_bfloat16* __restrict__ Ah, const __nv_bfloat16* __restrict__ Al,
    const __nv_bfloat16* __restrict__ Bh, const __nv_bfloat16* __restrict__ Bl,
    const float* __restrict__ bias, const float* __restrict__ res,
    float* __restrict__ Cf, __nv_bfloat16* __restrict__ Ch,
    __nv_bfloat16* __restrict__ Cl, int K, int Nc) {
    extern __shared__ char smp[];
    const uint32_t sb = smem_u32(smp);
    const int tid  = threadIdx.x;
    const int wid  = tid >> 5, lane = tid & 31;
    const int row0 = blockIdx.y * 128, col0 = blockIdx.x * 128;
    const int wm   = (wid & 3) * 32;       // warp m offset
    const int wn   = (wid >> 2) * 64;      // warp n offset

    // ---- global load / smem store indexing (2 x 16B chunks per thread/tile)
    const int e0   = tid * 2;              // chunk ids e0, e0+1
    const int grow = e0 >> 2;              // 0..127
    const int gkc  = e0 & 3;               // 0 or 2
    const uint32_t so0 = sw_off(grow, gkc);
    const uint32_t so1 = sw_off(grow, gkc + 1);
    const __nv_bfloat16* gA_h = Ah + (size_t)(row0 + grow) * K + gkc * 8;
    const __nv_bfloat16* gA_l = Al + (size_t)(row0 + grow) * K + gkc * 8;
    const __nv_bfloat16* gB_h = Bh + (size_t)(col0 + grow) * K + gkc * 8;
    const __nv_bfloat16* gB_l = Bl + (size_t)(col0 + grow) * K + gkc * 8;

    // ---- ldmatrix lane-derived constants
    const int a_moff = ((lane >> 3) & 1) * 8 + (lane & 7);
    const int a_k8   = lane >> 4;
    const int b_noff = (lane >> 4) * 8 + (lane & 7);
    const int b_k8   = (lane >> 3) & 1;
    uint32_t aRow64[2], aRsw[2];
    #pragma unroll
    for (int mt = 0; mt < 2; ++mt) {
        int r = wm + mt * 16 + a_moff;
        aRow64[mt] = r * 64;
        aRsw[mt]   = (r >> 1) & 3;
    }
    uint32_t bRow64[4], bRsw[4];
    #pragma unroll
    for (int ntp = 0; ntp < 4; ++ntp) {
        int r = wn + ntp * 16 + b_noff;
        bRow64[ntp] = r * 64;
        bRsw[ntp]   = (r >> 1) & 3;
    }

    float acc[2][8][4];
    #pragma unroll
    for (int i = 0; i < 2; ++i)
        #pragma unroll
        for (int j = 0; j < 8; ++j)
            #pragma unroll
            for (int p = 0; p < 4; ++p) acc[i][j][p] = 0.0f;

    const int NCH = K >> 5;
    uint4 pf[8];
    {   // prefetch chunk 0
        pf[0] = *(const uint4*)(gA_h);      pf[1] = *(const uint4*)(gA_h + 8);
        pf[2] = *(const uint4*)(gA_l);      pf[3] = *(const uint4*)(gA_l + 8);
        pf[4] = *(const uint4*)(gB_h);      pf[5] = *(const uint4*)(gB_h + 8);
        pf[6] = *(const uint4*)(gB_l);      pf[7] = *(const uint4*)(gB_l + 8);
    }

    for (int c = 0; c < NCH; ++c) {
        const uint32_t stg = (c & 1) * GT_STAGE;
        char* s = smp + stg;
        *(uint4*)(s + 0 * GT_TILE + so0) = pf[0];
        *(uint4*)(s + 0 * GT_TILE + so1) = pf[1];
        *(uint4*)(s + 1 * GT_TILE + so0) = pf[2];
        *(uint4*)(s + 1 * GT_TILE + so1) = pf[3];
        *(uint4*)(s + 2 * GT_TILE + so0) = pf[4];
        *(uint4*)(s + 2 * GT_TILE + so1) = pf[5];
        *(uint4*)(s + 3 * GT_TILE + so0) = pf[6];
        *(uint4*)(s + 3 * GT_TILE + so1) = pf[7];
        __syncthreads();
        if (c + 1 < NCH) {
            const int ko = (c + 1) << 5;
            pf[0] = *(const uint4*)(gA_h + ko);
            pf[1] = *(const uint4*)(gA_h + ko + 8);
            pf[2] = *(const uint4*)(gA_l + ko);
            pf[3] = *(const uint4*)(gA_l + ko + 8);
            pf[4] = *(const uint4*)(gB_h + ko);
            pf[5] = *(const uint4*)(gB_h + ko + 8);
            pf[6] = *(const uint4*)(gB_l + ko);
            pf[7] = *(const uint4*)(gB_l + ko + 8);
        }
        const uint32_t sAh = sb + stg;
        const uint32_t sAl = sAh + GT_TILE;
        const uint32_t sBh = sAl + GT_TILE;
        const uint32_t sBl = sBh + GT_TILE;
        #pragma unroll
        for (int kk = 0; kk < 2; ++kk) {
            uint32_t ah[2][4], al[2][4];
            #pragma unroll
            for (int mt = 0; mt < 2; ++mt) {
                const uint32_t ck = ((uint32_t)(kk * 2 + a_k8) ^ aRsw[mt]) << 4;
                ldm4(ah[mt], sAh + aRow64[mt] + ck);
                ldm4(al[mt], sAl + aRow64[mt] + ck);
            }
            #pragma unroll
            for (int ntp = 0; ntp < 4; ++ntp) {
                const uint32_t ck = ((uint32_t)(kk * 2 + b_k8) ^ bRsw[ntp]) << 4;
                uint32_t bh4[4], bl4[4];
                ldm4(bh4, sBh + bRow64[ntp] + ck);
                ldm4(bl4, sBl + bRow64[ntp] + ck);
                #pragma unroll
                for (int mt = 0; mt < 2; ++mt) {
                    mma_bf16(acc[mt][2 * ntp],     ah[mt], bh4);
                    mma_bf16(acc[mt][2 * ntp],     ah[mt], bl4);
                    mma_bf16(acc[mt][2 * ntp],     al[mt], bh4);
                    mma_bf16(acc[mt][2 * ntp + 1], ah[mt], bh4 + 2);
                    mma_bf16(acc[mt][2 * ntp + 1], ah[mt], bl4 + 2);
                    mma_bf16(acc[mt][2 * ntp + 1], al[mt], bh4 + 2);
                }
            }
        }
        __syncthreads();
    }

    // ---- epilogue (fragment layout: d0,d1 -> row q; d2,d3 -> row q+8) ----
    const int q  = lane >> 2;
    const int tc = lane & 3;
    #pragma unroll
    for (int mt = 0; mt < 2; ++mt) {
        #pragma unroll
        for (int nt = 0; nt < 8; ++nt) {
            float* cc = acc[mt][nt];
            const int col = col0 + wn + nt * 8 + tc * 2;
            const float2 bb = *(const float2*)&bias[col];
            #pragma unroll
            for (int hrow = 0; hrow < 2; ++hrow) {
                const size_t r = (size_t)(row0 + wm + mt * 16 + q + hrow * 8);
                float v0 = cc[2 * hrow + 0] + bb.x;
                float v1 = cc[2 * hrow + 1] + bb.y;
                if (EPI == 1) { v0 = gelu_exact(v0); v1 = gelu_exact(v1); }
                if (EPI == 2) {
                    float2 rv = *(const float2*)&res[r * Nc + col];
                    v0 += rv.x; v1 += rv.y;
                }
                if (WF) *(float2*)&Cf[r * Nc + col] = make_float2(v0, v1);
                if (WH) {
                    __nv_bfloat16 h0, l0, h1, l1;
                    split_bf16(v0, h0, l0);
                    split_bf16(v1, h1, l1);
                    __nv_bfloat162 th = __halves2bfloat162(h0, h1);
                    __nv_bfloat162 tl = __halves2bfloat162(l0, l1);
                    *(uint32_t*)&Ch[r * Nc + col] = *(uint32_t*)&th;
                    *(uint32_t*)&Cl[r * Nc + col] = *(uint32_t*)&tl;
                }
            }
        }
    }
}

// ---------------------------------------------------------------------------
// Fused attention (fp32 math; epilogue emits bf16 hi/lo)
// ---------------------------------------------------------------------------
constexpr int SQ_PAD = 36;
constexpr int SK_PAD = 36;
constexpr int SV_PAD = 116;
constexpr int ATTN_SMEM = (16 * 784 + 16 * SQ_PAD + 112 * SK_PAD) * 4;

__global__ void __launch_bounds__(256) attn_kernel(
    const float* __restrict__ q, const float* __restrict__ k,
    const float* __restrict__ v, const float* __restrict__ rel_bias,
    const int* __restrict__ rel_idx, __nv_bfloat16* __restrict__ atth,
    __nv_bfloat16* __restrict__ attl) {
    const int qt = blockIdx.x;
    const int h  = blockIdx.y;
    const int b  = blockIdx.z;
    const int n0 = qt * 16;
    const int tid = threadIdx.x;

    extern __shared__ float sm[];
    float* sS  = sm;
    float* sQ  = sm + 16 * 784;
    float* sKV = sQ + 16 * SQ_PAD;

    #pragma unroll
    for (int e = tid; e < 16 * 32; e += 256) {
        int qi = e >> 5, d = e & 31;
        sQ[qi * SQ_PAD + d] =
            q[((size_t)(b * NPOS + n0 + qi)) * CDIM + h * DHEAD + d];
    }

    const int qg  = tid / 28;
    const int mg  = tid % 28;
    const int qi0 = qg * 2;
    const bool active = (tid < 224);

    for (int kt = 0; kt < 7; ++kt) {
        const int m0 = kt * 112;
        __syncthreads();
        #pragma unroll
        for (int e = tid; e < 112 * 32; e += 256) {
            int mi = e >> 5, d = e & 31;
            sKV[mi * SK_PAD + d] =
                k[((size_t)(b * NPOS + m0 + mi)) * CDIM + h * DHEAD + d];
        }
        __syncthreads();
        if (active) {
            float acc[2][4] = {};
            #pragma unroll
            for (int d4 = 0; d4 < 32; d4 += 4) {
                float4 q0v = *(const float4*)&sQ[qi0 * SQ_PAD + d4];
                float4 q1v = *(const float4*)&sQ[(qi0 + 1) * SQ_PAD + d4];
                #pragma unroll
                for (int j = 0; j < 4; ++j) {
                    float4 kv = *(const float4*)&sKV[(mg + 28 * j) * SK_PAD + d4];
                    acc[0][j] = fmaf(q0v.x, kv.x, acc[0][j]);
                    acc[0][j] = fmaf(q0v.y, kv.y, acc[0][j]);
                    acc[0][j] = fmaf(q0v.z, kv.z, acc[0][j]);
                    acc[0][j] = fmaf(q0v.w, kv.w, acc[0][j]);
                    acc[1][j] = fmaf(q1v.x, kv.x, acc[1][j]);
                    acc[1][j] = fmaf(q1v.y, kv.y, acc[1][j]);
                    acc[1][j] = fmaf(q1v.z, kv.z, acc[1][j]);
                    acc[1][j] = fmaf(q1v.w, kv.w, acc[1][j]);
                }
            }
            int rl[2][4];
            #pragma unroll
            for (int r = 0; r < 2; ++r)
                #pragma unroll
                for (int j = 0; j < 4; ++j)
                    rl[r][j] = rel_idx[(size_t)(n0 + qi0 + r) * NPOS +
                                       (m0 + mg + 28 * j)];
            #pragma unroll
            for (int r = 0; r < 2; ++r)
                #pragma unroll
                for (int j = 0; j < 4; ++j) {
                    const int m = m0 + mg + 28 * j;
                    sS[(qi0 + r) * 784 + m] =
                        acc[r][j] + rel_bias[h * NREL + rl[r][j]];
                }
        }
    }
    __syncthreads();

    {
        const int warp = tid >> 5, lane = tid & 31;
        #pragma unroll
        for (int rr = 0; rr < 2; ++rr) {
            float* row = sS + (warp + rr * 8) * 784;
            float mx = -1e30f;
            for (int m = lane; m < 784; m += 32) mx = fmaxf(mx, row[m]);
            #pragma unroll
            for (int o = 16; o; o >>= 1)
                mx = fmaxf(mx, __shfl_xor_sync(0xffffffffu, mx, o));
            float sum = 0.0f;
            for (int m = lane; m < 784; m += 32) {
                float e = expf(row[m] - mx);
                row[m] = e;
                sum += e;
            }
            #pragma unroll
            for (int o = 16; o; o >>= 1)
                sum += __shfl_xor_sync(0xffffffffu, sum, o);
            const float inv = 1.0f / sum;
            for (int m = lane; m < 784; m += 32) row[m] *= inv;
        }
    }

    const int warp = tid >> 5;
    const int d    = tid & 31;
    float acc0 = 0.0f, acc1 = 0.0f;
    for (int kt = 0; kt < 7; ++kt) {
        const int m0 = kt * 112;
        __syncthreads();
        #pragma unroll
        for (int e = tid; e < 112 * 32; e += 256) {
            int mi = e >> 5, dd = e & 31;
            sKV[dd * SV_PAD + mi] =
                v[((size_t)(b * NPOS + m0 + mi)) * CDIM + h * DHEAD + dd];
        }
        __syncthreads();
        const float* w0 = &sS[warp * 784 + m0];
        const float* w1 = &sS[(warp + 8) * 784 + m0];
        const float* vr = &sKV[d * SV_PAD];
        #pragma unroll 7
        for (int mi = 0; mi < 112; mi += 4) {
            float4 a0 = *(const float4*)&w0[mi];
            float4 a1 = *(const float4*)&w1[mi];
            float4 vv = *(const float4*)&vr[mi];
            acc0 = fmaf(a0.x, vv.x, acc0);
            acc0 = fmaf(a0.y, vv.y, acc0);
            acc0 = fmaf(a0.z, vv.z, acc0);
            acc0 = fmaf(a0.w, vv.w, acc0);
            acc1 = fmaf(a1.x, vv.x, acc1);
            acc1 = fmaf(a1.y, vv.y, acc1);
            acc1 = fmaf(a1.z, vv.z, acc1);
            acc1 = fmaf(a1.w, vv.w, acc1);
        }
    }
    {
        __nv_bfloat16 h0, l0, h1, l1;
        split_bf16(acc0, h0, l0);
        split_bf16(acc1, h1, l1);
        size_t i0 = ((size_t)(b * NPOS + n0 + warp)) * CDIM + h * DHEAD + d;
        size_t i1 = ((size_t)(b * NPOS + n0 + warp + 8)) * CDIM + h * DHEAD + d;
        atth[i0] = h0; attl[i0] = l0;
        atth[i1] = h1; attl[i1] = l1;
    }
}

// ---------------------------------------------------------------------------
// Launch
// ---------------------------------------------------------------------------
extern "C" void kernel_launch(void* const* d_in, const int* in_sizes, int n_in,
                              void* d_out, int out_size) {
    (void)in_sizes; (void)n_in; (void)out_size;
    const float* x      = (const float*)d_in[0];
    const float* ln_w   = (const float*)d_in[1];
    const float* ln_b   = (const float*)d_in[2];
    const float* Wq     = (const float*)d_in[3];
    const float* bq     = (const float*)d_in[4];
    const float* Wk     = (const float*)d_in[5];
    const float* bk     = (const float*)d_in[6];
    const float* Wv     = (const float*)d_in[7];
    const float* bv     = (const float*)d_in[8];
    const float* Wo     = (const float*)d_in[9];
    const float* bo     = (const float*)d_in[10];
    const float* relb   = (const float*)d_in[11];
    const float* W1     = (const float*)d_in[12];
    const float* b1     = (const float*)d_in[13];
    const float* W2     = (const float*)d_in[14];
    const float* b2     = (const float*)d_in[15];
    const int*   relidx = (const int*)d_in[16];
    float* out = (float*)d_out;

    auto sym = [](const void* s) {
        void* p = nullptr;
        cudaGetSymbolAddress(&p, s);
        return p;
    };
    float* xc  = (float*)sym(g_xc);
    float* qb  = (float*)sym(g_q);
    float* kb  = (float*)sym(g_k);
    float* vb  = (float*)sym(g_v);
    float* x1  = (float*)sym(g_x1);
    float* x2  = (float*)sym(g_x2);
    __nv_bfloat16* xnh  = (__nv_bfloat16*)sym(g_xnh);
    __nv_bfloat16* xnl  = (__nv_bfloat16*)sym(g_xnl);
    __nv_bfloat16* atth = (__nv_bfloat16*)sym(g_atth);
    __nv_bfloat16* attl = (__nv_bfloat16*)sym(g_attl);
    __nv_bfloat16* x1h  = (__nv_bfloat16*)sym(g_x1h);
    __nv_bfloat16* x1l  = (__nv_bfloat16*)sym(g_x1l);
    __nv_bfloat16* h1h  = (__nv_bfloat16*)sym(g_h1h);
    __nv_bfloat16* h1l  = (__nv_bfloat16*)sym(g_h1l);
    __nv_bfloat16* wqh = (__nv_bfloat16*)sym(g_wqh), *wql = (__nv_bfloat16*)sym(g_wql);
    __nv_bfloat16* wkh = (__nv_bfloat16*)sym(g_wkh), *wkl = (__nv_bfloat16*)sym(g_wkl);
    __nv_bfloat16* wvh = (__nv_bfloat16*)sym(g_wvh), *wvl = (__nv_bfloat16*)sym(g_wvl);
    __nv_bfloat16* woh = (__nv_bfloat16*)sym(g_woh), *wol = (__nv_bfloat16*)sym(g_wol);
    __nv_bfloat16* w1h = (__nv_bfloat16*)sym(g_w1h), *w1l = (__nv_bfloat16*)sym(g_w1l);
    __nv_bfloat16* w2h = (__nv_bfloat16*)sym(g_w2h), *w2l = (__nv_bfloat16*)sym(g_w2l);

    cudaFuncSetAttribute(attn_kernel,
                         cudaFuncAttributeMaxDynamicSharedMemorySize, ATTN_SMEM);
    cudaFuncSetAttribute(hmma_gemm<0, 1, 0>,
                         cudaFuncAttributeMaxDynamicSharedMemorySize, GDSMEM);
    cudaFuncSetAttribute(hmma_gemm<2, 1, 1>,
                         cudaFuncAttributeMaxDynamicSharedMemorySize, GDSMEM);
    cudaFuncSetAttribute(hmma_gemm<1, 0, 1>,
                         cudaFuncAttributeMaxDynamicSharedMemorySize, GDSMEM);
    cudaFuncSetAttribute(hmma_gemm<2, 1, 0>,
                         cudaFuncAttributeMaxDynamicSharedMemorySize, GDSMEM);

    const dim3 tb(32, 8);
    // weight prep (W[K][N] -> [N][K] bf16 hi/lo)
    wprep_kernel<<<dim3(16, 16), tb>>>(Wq, wqh, wql, CDIM, CDIM);
    wprep_kernel<<<dim3(16, 16), tb>>>(Wk, wkh, wkl, CDIM, CDIM);
    wprep_kernel<<<dim3(16, 16), tb>>>(Wv, wvh, wvl, CDIM, CDIM);
    wprep_kernel<<<dim3(16, 16), tb>>>(Wo, woh, wol, CDIM, CDIM);
    wprep_kernel<<<dim3(64, 16), tb>>>(W1, w1h, w1l, CDIM, FFD);
    wprep_kernel<<<dim3(16, 64), tb>>>(W2, w2h, w2l, FFD, CDIM);

    // NCHW -> (b, n, c)
    transpose_kernel<<<dim3(25, 16, BATCH), tb>>>(x, xc, CDIM, NPOS);
    // LayerNorm -> bf16 hi/lo
    ln_kernel<<<MROWS, 128>>>(xc, ln_w, ln_b, xnh, xnl);

    const dim3 g512(CDIM / 128, MROWS / 128);   // (4, 98)
    const dim3 g2048(FFD / 128, MROWS / 128);   // (16, 98)
    // Q / K / V projections (fp32 out for attention)
    hmma_gemm<0, 1, 0><<<g512, 256, GDSMEM>>>(xnh, xnl, wqh, wql, bq, nullptr,
                                              qb, nullptr, nullptr, CDIM, CDIM);
    hmma_gemm<0, 1, 0><<<g512, 256, GDSMEM>>>(xnh, xnl, wkh, wkl, bk, nullptr,
                                              kb, nullptr, nullptr, CDIM, CDIM);
    hmma_gemm<0, 1, 0><<<g512, 256, GDSMEM>>>(xnh, xnl, wvh, wvl, bv, nullptr,
                                              vb, nullptr, nullptr, CDIM, CDIM);
    // Attention -> bf16 hi/lo
    attn_kernel<<<dim3(49, NHEADS, BATCH), 256, ATTN_SMEM>>>(qb, kb, vb, relb,
                                                             relidx, atth, attl);
    // x1 = xc + att @ Wo + bo   (fp32 + hi/lo)
    hmma_gemm<2, 1, 1><<<g512, 256, GDSMEM>>>(atth, attl, woh, wol, bo, xc,
                                              x1, x1h, x1l, CDIM, CDIM);
    // h1 = gelu(x1 @ W1 + b1)   (hi/lo only)
    hmma_gemm<1, 0, 1><<<g2048, 256, GDSMEM>>>(x1h, x1l, w1h, w1l, b1, nullptr,
                                               nullptr, h1h, h1l, CDIM, FFD);
    // x2 = x1 + h1 @ W2 + b2    (fp32)
    hmma_gemm<2, 1, 0><<<g512, 256, GDSMEM>>>(h1h, h1l, w2h, w2l, b2, x1,
                                              x2, nullptr, nullptr, FFD, CDIM);
    // (b, n, c) -> NCHW
    transpose_kernel<<<dim3(16, 25, BATCH), tb>>>(x2, out, NPOS, CDIM);
}

// round 13
// speedup vs baseline: 2.2366x; 1.7247x over previous
#include <cuda_runtime.h>
#include <cuda_bf16.h>
#include <math.h>
#include <stdint.h>

// ---------------------------------------------------------------------------
// Problem constants
// ---------------------------------------------------------------------------
constexpr int BATCH  = 16;
constexpr int NPOS   = 784;          // 28*28
constexpr int CDIM   = 512;
constexpr int NHEADS = 16;
constexpr int DHEAD  = 32;
constexpr int FFD    = 2048;
constexpr int NREL   = 1596;
constexpr int MROWS  = BATCH * NPOS; // 12544

constexpr size_t SZ_NC = (size_t)MROWS * CDIM;
constexpr size_t SZ_FF = (size_t)MROWS * FFD;
constexpr size_t SZ_BI = (size_t)NHEADS * NPOS * NPOS;

// ---------------------------------------------------------------------------
// Global scratch (static __device__ arrays — no allocation)
// ---------------------------------------------------------------------------
__device__ float g_xc[SZ_NC];
__device__ float g_x1[SZ_NC];
__device__ float g_x2[SZ_NC];

__device__ __nv_bfloat16 g_xnh[SZ_NC],  g_xnl[SZ_NC];
__device__ __nv_bfloat16 g_qh[SZ_NC],   g_ql[SZ_NC];
__device__ __nv_bfloat16 g_kh[SZ_NC],   g_kl[SZ_NC];
__device__ __nv_bfloat16 g_vh[SZ_NC],   g_vl[SZ_NC];
__device__ __nv_bfloat16 g_atth[SZ_NC], g_attl[SZ_NC];
__device__ __nv_bfloat16 g_x1h[SZ_NC],  g_x1l[SZ_NC];
__device__ __nv_bfloat16 g_h1h[SZ_FF],  g_h1l[SZ_FF];
__device__ __nv_bfloat16 g_biasb[SZ_BI];

__device__ __nv_bfloat16 g_wqh[CDIM*CDIM], g_wql[CDIM*CDIM];
__device__ __nv_bfloat16 g_wkh[CDIM*CDIM], g_wkl[CDIM*CDIM];
__device__ __nv_bfloat16 g_wvh[CDIM*CDIM], g_wvl[CDIM*CDIM];
__device__ __nv_bfloat16 g_woh[CDIM*CDIM], g_wol[CDIM*CDIM];
__device__ __nv_bfloat16 g_w1h[(size_t)CDIM*FFD], g_w1l[(size_t)CDIM*FFD];
__device__ __nv_bfloat16 g_w2h[(size_t)FFD*CDIM], g_w2l[(size_t)FFD*CDIM];

// ---------------------------------------------------------------------------
// Helpers
// ---------------------------------------------------------------------------
__device__ __forceinline__ uint32_t smem_u32(const void* p) {
    uint32_t a;
    asm("{ .reg .u64 t; cvta.to.shared.u64 t, %1; cvt.u32.u64 %0, t; }"
        : "=r"(a) : "l"(p));
    return a;
}
__device__ __forceinline__ float gelu_exact(float x) {
    return 0.5f * x * (1.0f + erff(x * 0.7071067811865476f));
}
__device__ __forceinline__ void split_bf16(float a, __nv_bfloat16& h,
                                           __nv_bfloat16& l) {
    h = __float2bfloat16(a);
    l = __float2bfloat16(a - __bfloat162float(h));
}
__device__ __forceinline__ void ldm4(uint32_t* r, uint32_t addr) {
    asm volatile(
        "ldmatrix.sync.aligned.m8n8.x4.shared.b16 {%0,%1,%2,%3}, [%4];"
        : "=r"(r[0]), "=r"(r[1]), "=r"(r[2]), "=r"(r[3]) : "r"(addr)
        : "memory");
}
__device__ __forceinline__ void ldm4t(uint32_t* r, uint32_t addr) {
    asm volatile(
        "ldmatrix.sync.aligned.m8n8.x4.trans.shared.b16 {%0,%1,%2,%3}, [%4];"
        : "=r"(r[0]), "=r"(r[1]), "=r"(r[2]), "=r"(r[3]) : "r"(addr)
        : "memory");
}
__device__ __forceinline__ void mma_bf16(float* c, const uint32_t* a,
                                         const uint32_t* b) {
    asm volatile(
        "mma.sync.aligned.m16n8k16.row.col.f32.bf16.bf16.f32 "
        "{%0,%1,%2,%3},{%4,%5,%6,%7},{%8,%9},{%0,%1,%2,%3};"
        : "+f"(c[0]), "+f"(c[1]), "+f"(c[2]), "+f"(c[3])
        : "r"(a[0]), "r"(a[1]), "r"(a[2]), "r"(a[3]), "r"(b[0]), "r"(b[1]));
}
__device__ __forceinline__ uint32_t pack_bf16x2(float a, float b) {
    __nv_bfloat162 t = __floats2bfloat162_rn(a, b);
    return *(uint32_t*)&t;
}

// ---------------------------------------------------------------------------
// Tiled 2D transpose per batch:  src [R][Cc]  ->  dst [Cc][R]
// ---------------------------------------------------------------------------
__global__ void transpose_kernel(const float* __restrict__ in,
                                 float* __restrict__ out, int R, int Cc) {
    __shared__ float tile[32][33];
    const int b = blockIdx.z;
    const float* src = in  + (size_t)b * R * Cc;
    float*       dst = out + (size_t)b * R * Cc;
    const int c0 = blockIdx.x * 32;
    const int r0 = blockIdx.y * 32;
    const int tx = threadIdx.x, ty = threadIdx.y;
    #pragma unroll
    for (int j = 0; j < 32; j += 8) {
        int r = r0 + ty + j, c = c0 + tx;
        if (r < R && c < Cc) tile[ty + j][tx] = src[(size_t)r * Cc + c];
    }
    __syncthreads();
    #pragma unroll
    for (int j = 0; j < 32; j += 8) {
        int oc = c0 + ty + j, orr = r0 + tx;
        if (oc < Cc && orr < R) dst[(size_t)oc * R + orr] = tile[tx][ty + j];
    }
}

// ---------------------------------------------------------------------------
// Weight prep: W[K][N] fp32  ->  Bh/Bl [N][K] bf16 (hi/lo split)
// ---------------------------------------------------------------------------
__global__ void wprep_kernel(const float* __restrict__ W,
                             __nv_bfloat16* __restrict__ Bh,
                             __nv_bfloat16* __restrict__ Bl, int K, int N) {
    __shared__ float t[32][33];
    const int n0 = blockIdx.x * 32, k0 = blockIdx.y * 32;
    const int tx = threadIdx.x, ty = threadIdx.y;
    #pragma unroll
    for (int j = 0; j < 32; j += 8)
        t[ty + j][tx] = W[(size_t)(k0 + ty + j) * N + n0 + tx];
    __syncthreads();
    #pragma unroll
    for (int j = 0; j < 32; j += 8) {
        float vv = t[tx][ty + j];
        __nv_bfloat16 h, l;
        split_bf16(vv, h, l);
        size_t idx = (size_t)(n0 + ty + j) * K + k0 + tx;
        Bh[idx] = h;
        Bl[idx] = l;
    }
}

// ---------------------------------------------------------------------------
// Bias prep: biasb[h][n][m] = bf16(rel_bias[h][rel_idx[n][m]])
// ---------------------------------------------------------------------------
__global__ void bias_prep_kernel(const float* __restrict__ rel_bias,
                                 const int* __restrict__ rel_idx,
                                 __nv_bfloat16* __restrict__ biasb) {
    const int idx = blockIdx.x * 256 + threadIdx.x;
    if (idx >= NPOS * NPOS) return;
    const int ri = rel_idx[idx];
    #pragma unroll
    for (int h = 0; h < NHEADS; ++h)
        biasb[(size_t)h * NPOS * NPOS + idx] =
            __float2bfloat16(rel_bias[h * NREL + ri]);
}

// ---------------------------------------------------------------------------
// LayerNorm over C=512, one block (128 threads) per row; emits bf16 hi/lo
// ---------------------------------------------------------------------------
__global__ void __launch_bounds__(128) ln_kernel(const float* __restrict__ xc,
                                                 const float* __restrict__ w,
                                                 const float* __restrict__ bsh,
                                                 __nv_bfloat16* __restrict__ xh,
                                                 __nv_bfloat16* __restrict__ xl) {
    const int row = blockIdx.x;
    const int tid = threadIdx.x;
    const float* xr = xc + (size_t)row * CDIM;
    float4 v = *(const float4*)&xr[tid << 2];
    float s  = v.x + v.y + v.z + v.w;
    float ss = v.x * v.x + v.y * v.y + v.z * v.z + v.w * v.w;
    #pragma unroll
    for (int o = 16; o; o >>= 1) {
        s  += __shfl_xor_sync(0xffffffffu, s, o);
        ss += __shfl_xor_sync(0xffffffffu, ss, o);
    }
    __shared__ float rs[4], rss[4];
    const int warp = tid >> 5, lane = tid & 31;
    if (lane == 0) { rs[warp] = s; rss[warp] = ss; }
    __syncthreads();
    if (tid == 0) {
        float S  = rs[0] + rs[1] + rs[2] + rs[3];
        float SS = rss[0] + rss[1] + rss[2] + rss[3];
        float mu  = S * (1.0f / CDIM);
        float var = SS * (1.0f / CDIM) - mu * mu;
        rs[0]  = mu;
        rss[0] = rsqrtf(var + 1e-5f);
    }
    __syncthreads();
    const float mu = rs[0], rstd = rss[0];
    float4 wv = *(const float4*)&w[tid << 2];
    float4 bv = *(const float4*)&bsh[tid << 2];
    float o[4];
    o[0] = (v.x - mu) * rstd * wv.x + bv.x;
    o[1] = (v.y - mu) * rstd * wv.y + bv.y;
    o[2] = (v.z - mu) * rstd * wv.z + bv.z;
    o[3] = (v.w - mu) * rstd * wv.w + bv.w;
    __nv_bfloat16 h[4], l[4];
    #pragma unroll
    for (int i = 0; i < 4; ++i) split_bf16(o[i], h[i], l[i]);
    uint2 hp, lp;
    hp.x = pack_bf16x2(o[0], o[1]) ; // hi parts
    __nv_bfloat162 t;
    t = __halves2bfloat162(h[0], h[1]); hp.x = *(uint32_t*)&t;
    t = __halves2bfloat162(h[2], h[3]); hp.y = *(uint32_t*)&t;
    t = __halves2bfloat162(l[0], l[1]); lp.x = *(uint32_t*)&t;
    t = __halves2bfloat162(l[2], l[3]); lp.y = *(uint32_t*)&t;
    *(uint2*)&xh[(size_t)row * CDIM + (tid << 2)] = hp;
    *(uint2*)&xl[(size_t)row * CDIM + (tid << 2)] = lp;
}

// ---------------------------------------------------------------------------
// HMMA bf16x3 GEMM (unchanged from R12):  C = A @ B^T
// ---------------------------------------------------------------------------
constexpr int GT_TILE  = 128 * 32 * 2;
constexpr int GT_STAGE = 4 * GT_TILE;
constexpr int GDSMEM   = 2 * GT_STAGE;

__device__ __forceinline__ uint32_t sw_off(int row, int kc) {
    return (uint32_t)(row * 64 + ((kc ^ ((row >> 1) & 3)) << 4));
}

template <int EPI, int WF, int WH>
__global__ void __launch_bounds__(256, 2) hmma_gemm(
    const __nv_bfloat16* __restrict__ Ah, const __nv_bfloat16* __restrict__ Al,
    const __nv_bfloat16* __restrict__ Bh, const __nv_bfloat16* __restrict__ Bl,
    const float* __restrict__ bias, const float* __restrict__ res,
    float* __restrict__ Cf, __nv_bfloat16* __restrict__ Ch,
    __nv_bfloat16* __restrict__ Cl, int K, int Nc) {
    extern __shared__ char smp[];
    const uint32_t sb = smem_u32(smp);
    const int tid  = threadIdx.x;
    const int wid  = tid >> 5, lane = tid & 31;
    const int row0 = blockIdx.y * 128, col0 = blockIdx.x * 128;
    const int wm   = (wid & 3) * 32;
    const int wn   = (wid >> 2) * 64;

    const int e0   = tid * 2;
    const int grow = e0 >> 2;
    const int gkc  = e0 & 3;
    const uint32_t so0 = sw_off(grow, gkc);
    const uint32_t so1 = sw_off(grow, gkc + 1);
    const __nv_bfloat16* gA_h = Ah + (size_t)(row0 + grow) * K + gkc * 8;
    const __nv_bfloat16* gA_l = Al + (size_t)(row0 + grow) * K + gkc * 8;
    const __nv_bfloat16* gB_h = Bh + (size_t)(col0 + grow) * K + gkc * 8;
    const __nv_bfloat16* gB_l = Bl + (size_t)(col0 + grow) * K + gkc * 8;

    const int a_moff = ((lane >> 3) & 1) * 8 + (lane & 7);
    const int a_k8   = lane >> 4;
    const int b_noff = (lane >> 4) * 8 + (lane & 7);
    const int b_k8   = (lane >> 3) & 1;
    uint32_t aRow64[2], aRsw[2];
    #pragma unroll
    for (int mt = 0; mt < 2; ++mt) {
        int r = wm + mt * 16 + a_moff;
        aRow64[mt] = r * 64;
        aRsw[mt]   = (r >> 1) & 3;
    }
    uint32_t bRow64[4], bRsw[4];
    #pragma unroll
    for (int ntp = 0; ntp < 4; ++ntp) {
        int r = wn + ntp * 16 + b_noff;
        bRow64[ntp] = r * 64;
        bRsw[ntp]   = (r >> 1) & 3;
    }

    float acc[2][8][4];
    #pragma unroll
    for (int i = 0; i < 2; ++i)
        #pragma unroll
        for (int j = 0; j < 8; ++j)
            #pragma unroll
            for (int p = 0; p < 4; ++p) acc[i][j][p] = 0.0f;

    const int NCH = K >> 5;
    uint4 pf[8];
    {
        pf[0] = *(const uint4*)(gA_h);      pf[1] = *(const uint4*)(gA_h + 8);
        pf[2] = *(const uint4*)(gA_l);      pf[3] = *(const uint4*)(gA_l + 8);
        pf[4] = *(const uint4*)(gB_h);      pf[5] = *(const uint4*)(gB_h + 8);
        pf[6] = *(const uint4*)(gB_l);      pf[7] = *(const uint4*)(gB_l + 8);
    }

    for (int c = 0; c < NCH; ++c) {
        const uint32_t stg = (c & 1) * GT_STAGE;
        char* s = smp + stg;
        *(uint4*)(s + 0 * GT_TILE + so0) = pf[0];
        *(uint4*)(s + 0 * GT_TILE + so1) = pf[1];
        *(uint4*)(s + 1 * GT_TILE + so0) = pf[2];
        *(uint4*)(s + 1 * GT_TILE + so1) = pf[3];
        *(uint4*)(s + 2 * GT_TILE + so0) = pf[4];
        *(uint4*)(s + 2 * GT_TILE + so1) = pf[5];
        *(uint4*)(s + 3 * GT_TILE + so0) = pf[6];
        *(uint4*)(s + 3 * GT_TILE + so1) = pf[7];
        __syncthreads();
        if (c + 1 < NCH) {
            const int ko = (c + 1) << 5;
            pf[0] = *(const uint4*)(gA_h + ko);
            pf[1] = *(const uint4*)(gA_h + ko + 8);
            pf[2] = *(const uint4*)(gA_l + ko);
            pf[3] = *(const uint4*)(gA_l + ko + 8);
            pf[4] = *(const uint4*)(gB_h + ko);
            pf[5] = *(const uint4*)(gB_h + ko + 8);
            pf[6] = *(const uint4*)(gB_l + ko);
            pf[7] = *(const uint4*)(gB_l + ko + 8);
        }
        const uint32_t sAh = sb + stg;
        const uint32_t sAl = sAh + GT_TILE;
        const uint32_t sBh = sAl + GT_TILE;
        const uint32_t sBl = sBh + GT_TILE;
        #pragma unroll
        for (int kk = 0; kk < 2; ++kk) {
            uint32_t ah[2][4], al[2][4];
            #pragma unroll
            for (int mt = 0; mt < 2; ++mt) {
                const uint32_t ck = ((uint32_t)(kk * 2 + a_k8) ^ aRsw[mt]) << 4;
                ldm4(ah[mt], sAh + aRow64[mt] + ck);
                ldm4(al[mt], sAl + aRow64[mt] + ck);
            }
            #pragma unroll
            for (int ntp = 0; ntp < 4; ++ntp) {
                const uint32_t ck = ((uint32_t)(kk * 2 + b_k8) ^ bRsw[ntp]) << 4;
                uint32_t bh4[4], bl4[4];
                ldm4(bh4, sBh + bRow64[ntp] + ck);
                ldm4(bl4, sBl + bRow64[ntp] + ck);
                #pragma unroll
                for (int mt = 0; mt < 2; ++mt) {
                    mma_bf16(acc[mt][2 * ntp],     ah[mt], bh4);
                    mma_bf16(acc[mt][2 * ntp],     ah[mt], bl4);
                    mma_bf16(acc[mt][2 * ntp],     al[mt], bh4);
                    mma_bf16(acc[mt][2 * ntp + 1], ah[mt], bh4 + 2);
                    mma_bf16(acc[mt][2 * ntp + 1], ah[mt], bl4 + 2);
                    mma_bf16(acc[mt][2 * ntp + 1], al[mt], bh4 + 2);
                }
            }
        }
        __syncthreads();
    }

    const int q  = lane >> 2;
    const int tc = lane & 3;
    #pragma unroll
    for (int mt = 0; mt < 2; ++mt) {
        #pragma unroll
        for (int nt = 0; nt < 8; ++nt) {
            float* cc = acc[mt][nt];
            const int col = col0 + wn + nt * 8 + tc * 2;
            const float2 bb = *(const float2*)&bias[col];
            #pragma unroll
            for (int hrow = 0; hrow < 2; ++hrow) {
                const size_t r = (size_t)(row0 + wm + mt * 16 + q + hrow * 8);
                float v0 = cc[2 * hrow + 0] + bb.x;
                float v1 = cc[2 * hrow + 1] + bb.y;
                if (EPI == 1) { v0 = gelu_exact(v0); v1 = gelu_exact(v1); }
                if (EPI == 2) {
                    float2 rv = *(const float2*)&res[r * Nc + col];
                    v0 += rv.x; v1 += rv.y;
                }
                if (WF) *(float2*)&Cf[r * Nc + col] = make_float2(v0, v1);
                if (WH) {
                    __nv_bfloat16 h0, l0, h1, l1;
                    split_bf16(v0, h0, l0);
                    split_bf16(v1, h1, l1);
                    __nv_bfloat162 th = __halves2bfloat162(h0, h1);
                    __nv_bfloat162 tl = __halves2bfloat162(l0, l1);
                    *(uint32_t*)&Ch[r * Nc + col] = *(uint32_t*)&th;
                    *(uint32_t*)&Cl[r * Nc + col] = *(uint32_t*)&tl;
                }
            }
        }
    }
}

// ---------------------------------------------------------------------------
// MMA flash attention. CTA = (b, h, 112-q-tile); 7 warps x 16 rows.
// Online softmax over 7 K-tiles of 112. bf16x3 HMMA for scores and P.V.
// smem rows padded to 80B (20-word stride -> conflict-free ldmatrix).
// ---------------------------------------------------------------------------
constexpr int AQT   = 112;
constexpr int ROWB  = 80;                   // bytes per 32-elem bf16 row
constexpr int A_SQH = 0;
constexpr int A_SQL = A_SQH + AQT * ROWB;   // 8960
constexpr int A_SKH = A_SQL + AQT * ROWB;
constexpr int A_SKL = A_SKH + AQT * ROWB;
constexpr int A_SVH = A_SKL + AQT * ROWB;
constexpr int A_SVL = A_SVH + AQT * ROWB;
constexpr int A_SBI = A_SVL + AQT * ROWB;   // 53760
constexpr int A_BIW = 16 * 240;             // per-warp bias staging (3840 B)
constexpr int ATTN_SMEM = A_SBI + 7 * A_BIW; // 80640

__global__ void __launch_bounds__(224, 2) attn_mma(
    const __nv_bfloat16* __restrict__ qh, const __nv_bfloat16* __restrict__ ql,
    const __nv_bfloat16* __restrict__ kh, const __nv_bfloat16* __restrict__ kl,
    const __nv_bfloat16* __restrict__ vh, const __nv_bfloat16* __restrict__ vl,
    const __nv_bfloat16* __restrict__ biasb,
    __nv_bfloat16* __restrict__ atth, __nv_bfloat16* __restrict__ attl) {
    extern __shared__ char sm[];
    const uint32_t sb = smem_u32(sm);
    const int tid  = threadIdx.x;
    const int wid  = tid >> 5, lane = tid & 31;
    const int qt = blockIdx.x, h = blockIdx.y, b = blockIdx.z;
    const int n0 = qt * AQT;

    // ---- load Q tile (hi/lo), rows n0..n0+111, cols h*32..+32 ----
    #pragma unroll
    for (int e = tid; e < 448; e += 224) {
        const int r = e >> 2, c = e & 3;
        const size_t g = (size_t)(b * NPOS + n0 + r) * CDIM + h * DHEAD + c * 8;
        *(uint4*)(sm + A_SQH + r * ROWB + c * 16) = *(const uint4*)(qh + g);
        *(uint4*)(sm + A_SQL + r * ROWB + c * 16) = *(const uint4*)(ql + g);
    }
    __syncthreads();

    // ---- Q fragments (held in regs for whole kernel) ----
    const int am  = ((lane >> 3) & 1) * 8 + (lane & 7);
    const int ak8 = lane >> 4;
    uint32_t qfh[2][4], qfl[2][4];
    #pragma unroll
    for (int kk = 0; kk < 2; ++kk) {
        const uint32_t off = (wid * 16 + am) * ROWB + (kk * 2 + ak8) * 16;
        ldm4(qfh[kk], sb + A_SQH + off);
        ldm4(qfl[kk], sb + A_SQL + off);
    }

    const int bn  = (lane >> 4) * 8 + (lane & 7);
    const int bk8 = (lane >> 3) & 1;

    float m0 = -1e30f, m1 = -1e30f, l0 = 0.0f, l1 = 0.0f;
    float oa[4][4];
    #pragma unroll
    for (int j = 0; j < 4; ++j)
        #pragma unroll
        for (int p = 0; p < 4; ++p) oa[j][p] = 0.0f;

    const uint32_t sBiasW = sb + A_SBI + wid * A_BIW;

    for (int kt = 0; kt < 7; ++kt) {
        const int mp0 = kt * AQT;
        __syncthreads();
        // ---- load K/V tiles hi/lo ----
        #pragma unroll
        for (int e = tid; e < 448; e += 224) {
            const int r = e >> 2, c = e & 3;
            const size_t g =
                (size_t)(b * NPOS + mp0 + r) * CDIM + h * DHEAD + c * 8;
            const uint32_t so = r * ROWB + c * 16;
            *(uint4*)(sm + A_SKH + so) = *(const uint4*)(kh + g);
            *(uint4*)(sm + A_SKL + so) = *(const uint4*)(kl + g);
            *(uint4*)(sm + A_SVH + so) = *(const uint4*)(vh + g);
            *(uint4*)(sm + A_SVL + so) = *(const uint4*)(vl + g);
        }
        __syncthreads();

        // ---- warp-private bias staging (16 rows x 112 cols bf16) ----
        #pragma unroll
        for (int e = lane; e < 224; e += 32) {
            const int r = e / 14, c = e % 14;
            *(uint4*)(sm + A_SBI + wid * A_BIW + r * 240 + c * 16) =
                *(const uint4*)(biasb + (size_t)h * NPOS * NPOS +
                                (size_t)(n0 + wid * 16 + r) * NPOS + mp0 +
                                c * 8);
        }
        __syncwarp();

        // ---- scores: S = Q.K^T (bf16x3) ----
        float sa[14][4];
        #pragma unroll
        for (int t = 0; t < 14; ++t)
            #pragma unroll
            for (int p = 0; p < 4; ++p) sa[t][p] = 0.0f;
        #pragma unroll
        for (int kk = 0; kk < 2; ++kk) {
            #pragma unroll
            for (int g = 0; g < 7; ++g) {
                const uint32_t off =
                    (g * 16 + bn) * ROWB + (kk * 2 + bk8) * 16;
                uint32_t kh4[4], kl4[4];
                ldm4(kh4, sb + A_SKH + off);
                ldm4(kl4, sb + A_SKL + off);
                mma_bf16(sa[2 * g],     qfh[kk], kh4);
                mma_bf16(sa[2 * g],     qfh[kk], kl4);
                mma_bf16(sa[2 * g],     qfl[kk], kh4);
                mma_bf16(sa[2 * g + 1], qfh[kk], kh4 + 2);
                mma_bf16(sa[2 * g + 1], qfh[kk], kl4 + 2);
                mma_bf16(sa[2 * g + 1], qfl[kk], kh4 + 2);
            }
        }

        // ---- bias add via ldmatrix (frag layout matches C layout) ----
        #pragma unroll
        for (int c7 = 0; c7 < 7; ++c7) {
            uint32_t bb[4];
            ldm4(bb, sBiasW + am * 240 + c7 * 32 + ak8 * 16);
            float2 f0 = __bfloat1622float2(*(__nv_bfloat162*)&bb[0]);
            float2 f1 = __bfloat1622float2(*(__nv_bfloat162*)&bb[1]);
            float2 f2 = __bfloat1622float2(*(__nv_bfloat162*)&bb[2]);
            float2 f3 = __bfloat1622float2(*(__nv_bfloat162*)&bb[3]);
            sa[2 * c7][0] += f0.x;     sa[2 * c7][1] += f0.y;
            sa[2 * c7][2] += f1.x;     sa[2 * c7][3] += f1.y;
            sa[2 * c7 + 1][0] += f2.x; sa[2 * c7 + 1][1] += f2.y;
            sa[2 * c7 + 1][2] += f3.x; sa[2 * c7 + 1][3] += f3.y;
        }

        // ---- online softmax ----
        float mx0 = -1e30f, mx1 = -1e30f;
        #pragma unroll
        for (int t = 0; t < 14; ++t) {
            mx0 = fmaxf(mx0, fmaxf(sa[t][0], sa[t][1]));
            mx1 = fmaxf(mx1, fmaxf(sa[t][2], sa[t][3]));
        }
        mx0 = fmaxf(mx0, __shfl_xor_sync(0xffffffffu, mx0, 1));
        mx0 = fmaxf(mx0, __shfl_xor_sync(0xffffffffu, mx0, 2));
        mx1 = fmaxf(mx1, __shfl_xor_sync(0xffffffffu, mx1, 1));
        mx1 = fmaxf(mx1, __shfl_xor_sync(0xffffffffu, mx1, 2));
        const float nm0 = fmaxf(m0, mx0), nm1 = fmaxf(m1, mx1);
        const float f0 = __expf(m0 - nm0), f1 = __expf(m1 - nm1);
        m0 = nm0; m1 = nm1;
        float s0 = 0.0f, s1 = 0.0f;
        #pragma unroll
        for (int t = 0; t < 14; ++t) {
            sa[t][0] = __expf(sa[t][0] - m0);
            sa[t][1] = __expf(sa[t][1] - m0);
            sa[t][2] = __expf(sa[t][2] - m1);
            sa[t][3] = __expf(sa[t][3] - m1);
            s0 += sa[t][0] + sa[t][1];
            s1 += sa[t][2] + sa[t][3];
        }
        s0 += __shfl_xor_sync(0xffffffffu, s0, 1);
        s0 += __shfl_xor_sync(0xffffffffu, s0, 2);
        s1 += __shfl_xor_sync(0xffffffffu, s1, 1);
        s1 += __shfl_xor_sync(0xffffffffu, s1, 2);
        l0 = l0 * f0 + s0;
        l1 = l1 * f1 + s1;
        #pragma unroll
        for (int j = 0; j < 4; ++j) {
            oa[j][0] *= f0; oa[j][1] *= f0;
            oa[j][2] *= f1; oa[j][3] *= f1;
        }

        // ---- P.V (bf16x3; P frags from score fragments) ----
        #pragma unroll
        for (int t = 0; t < 7; ++t) {
            uint32_t ph[4], pl[4];
            #pragma unroll
            for (int half = 0; half < 2; ++half) {
                const float* src = sa[2 * t + half];
                // rows q (src[0], src[1]) and q+8 (src[2], src[3])
                __nv_bfloat162 h01 = __floats2bfloat162_rn(src[0], src[1]);
                float2 r01 = __bfloat1622float2(h01);
                __nv_bfloat162 l01 =
                    __floats2bfloat162_rn(src[0] - r01.x, src[1] - r01.y);
                __nv_bfloat162 h23 = __floats2bfloat162_rn(src[2], src[3]);
                float2 r23 = __bfloat1622float2(h23);
                __nv_bfloat162 l23 =
                    __floats2bfloat162_rn(src[2] - r23.x, src[3] - r23.y);
                ph[2 * half]     = *(uint32_t*)&h01;
                ph[2 * half + 1] = *(uint32_t*)&h23;
                pl[2 * half]     = *(uint32_t*)&l01;
                pl[2 * half + 1] = *(uint32_t*)&l23;
            }
            // reorder to A-frag: a0=(q,k0),a1=(q+8,k0),a2=(q,k8),a3=(q+8,k8)
            uint32_t pa_h[4] = {ph[0], ph[1], ph[2], ph[3]};
            uint32_t pa_l[4] = {pl[0], pl[1], pl[2], pl[3]};
            #pragma unroll
            for (int v = 0; v < 2; ++v) {
                const uint32_t off =
                    (t * 16 + am) * ROWB + v * 32 + (lane >> 4) * 16;
                uint32_t vh4[4], vl4[4];
                ldm4t(vh4, sb + A_SVH + off);
                ldm4t(vl4, sb + A_SVL + off);
                mma_bf16(oa[2 * v],     pa_h, vh4);
                mma_bf16(oa[2 * v],     pa_h, vl4);
                mma_bf16(oa[2 * v],     pa_l, vh4);
                mma_bf16(oa[2 * v + 1], pa_h, vh4 + 2);
                mma_bf16(oa[2 * v + 1], pa_h, vl4 + 2);
                mma_bf16(oa[2 * v + 1], pa_l, vh4 + 2);
            }
        }
    }

    // ---- epilogue: O/l -> bf16 hi/lo ----
    const float inv0 = 1.0f / l0, inv1 = 1.0f / l1;
    const int q  = lane >> 2, tc = lane & 3;
    const size_t r0 = (size_t)(b * NPOS + n0 + wid * 16 + q);
    const size_t r1 = r0 + 8;
    #pragma unroll
    for (int j = 0; j < 4; ++j) {
        const int col = h * DHEAD + j * 8 + tc * 2;
        float a0 = oa[j][0] * inv0, a1 = oa[j][1] * inv0;
        float b0 = oa[j][2] * inv1, b1 = oa[j][3] * inv1;
        __nv_bfloat16 h0, lo0, h1, lo1;
        split_bf16(a0, h0, lo0); split_bf16(a1, h1, lo1);
        __nv_bfloat162 th = __halves2bfloat162(h0, h1);
        __nv_bfloat162 tl = __halves2bfloat162(lo0, lo1);
        *(uint32_t*)&atth[r0 * CDIM + col] = *(uint32_t*)&th;
        *(uint32_t*)&attl[r0 * CDIM + col] = *(uint32_t*)&tl;
        split_bf16(b0, h0, lo0); split_bf16(b1, h1, lo1);
        th = __halves2bfloat162(h0, h1);
        tl = __halves2bfloat162(lo0, lo1);
        *(uint32_t*)&atth[r1 * CDIM + col] = *(uint32_t*)&th;
        *(uint32_t*)&attl[r1 * CDIM + col] = *(uint32_t*)&tl;
    }
}

// ---------------------------------------------------------------------------
// Launch
// ---------------------------------------------------------------------------
extern "C" void kernel_launch(void* const* d_in, const int* in_sizes, int n_in,
                              void* d_out, int out_size) {
    (void)in_sizes; (void)n_in; (void)out_size;
    const float* x      = (const float*)d_in[0];
    const float* ln_w   = (const float*)d_in[1];
    const float* ln_b   = (const float*)d_in[2];
    const float* Wq     = (const float*)d_in[3];
    const float* bq     = (const float*)d_in[4];
    const float* Wk     = (const float*)d_in[5];
    const float* bk     = (const float*)d_in[6];
    const float* Wv     = (const float*)d_in[7];
    const float* bv     = (const float*)d_in[8];
    const float* Wo     = (const float*)d_in[9];
    const float* bo     = (const float*)d_in[10];
    const float* relb   = (const float*)d_in[11];
    const float* W1     = (const float*)d_in[12];
    const float* b1     = (const float*)d_in[13];
    const float* W2     = (const float*)d_in[14];
    const float* b2     = (const float*)d_in[15];
    const int*   relidx = (const int*)d_in[16];
    float* out = (float*)d_out;

    auto sym = [](const void* s) {
        void* p = nullptr;
        cudaGetSymbolAddress(&p, s);
        return p;
    };
    float* xc  = (float*)sym(g_xc);
    float* x1  = (float*)sym(g_x1);
    float* x2  = (float*)sym(g_x2);
    __nv_bfloat16* xnh  = (__nv_bfloat16*)sym(g_xnh);
    __nv_bfloat16* xnl  = (__nv_bfloat16*)sym(g_xnl);
    __nv_bfloat16* qh   = (__nv_bfloat16*)sym(g_qh);
    __nv_bfloat16* ql   = (__nv_bfloat16*)sym(g_ql);
    __nv_bfloat16* kh   = (__nv_bfloat16*)sym(g_kh);
    __nv_bfloat16* kl   = (__nv_bfloat16*)sym(g_kl);
    __nv_bfloat16* vh   = (__nv_bfloat16*)sym(g_vh);
    __nv_bfloat16* vl   = (__nv_bfloat16*)sym(g_vl);
    __nv_bfloat16* atth = (__nv_bfloat16*)sym(g_atth);
    __nv_bfloat16* attl = (__nv_bfloat16*)sym(g_attl);
    __nv_bfloat16* x1h  = (__nv_bfloat16*)sym(g_x1h);
    __nv_bfloat16* x1l  = (__nv_bfloat16*)sym(g_x1l);
    __nv_bfloat16* h1h  = (__nv_bfloat16*)sym(g_h1h);
    __nv_bfloat16* h1l  = (__nv_bfloat16*)sym(g_h1l);
    __nv_bfloat16* biasb = (__nv_bfloat16*)sym(g_biasb);
    __nv_bfloat16* wqh = (__nv_bfloat16*)sym(g_wqh), *wql = (__nv_bfloat16*)sym(g_wql);
    __nv_bfloat16* wkh = (__nv_bfloat16*)sym(g_wkh), *wkl = (__nv_bfloat16*)sym(g_wkl);
    __nv_bfloat16* wvh = (__nv_bfloat16*)sym(g_wvh), *wvl = (__nv_bfloat16*)sym(g_wvl);
    __nv_bfloat16* woh = (__nv_bfloat16*)sym(g_woh), *wol = (__nv_bfloat16*)sym(g_wol);
    __nv_bfloat16* w1h = (__nv_bfloat16*)sym(g_w1h), *w1l = (__nv_bfloat16*)sym(g_w1l);
    __nv_bfloat16* w2h = (__nv_bfloat16*)sym(g_w2h), *w2l = (__nv_bfloat16*)sym(g_w2l);

    cudaFuncSetAttribute(attn_mma,
                         cudaFuncAttributeMaxDynamicSharedMemorySize, ATTN_SMEM);
    cudaFuncSetAttribute(hmma_gemm<0, 0, 1>,
                         cudaFuncAttributeMaxDynamicSharedMemorySize, GDSMEM);
    cudaFuncSetAttribute(hmma_gemm<2, 1, 1>,
                         cudaFuncAttributeMaxDynamicSharedMemorySize, GDSMEM);
    cudaFuncSetAttribute(hmma_gemm<1, 0, 1>,
                         cudaFuncAttributeMaxDynamicSharedMemorySize, GDSMEM);
    cudaFuncSetAttribute(hmma_gemm<2, 1, 0>,
                         cudaFuncAttributeMaxDynamicSharedMemorySize, GDSMEM);

    const dim3 tb(32, 8);
    // weight + bias prep
    wprep_kernel<<<dim3(16, 16), tb>>>(Wq, wqh, wql, CDIM, CDIM);
    wprep_kernel<<<dim3(16, 16), tb>>>(Wk, wkh, wkl, CDIM, CDIM);
    wprep_kernel<<<dim3(16, 16), tb>>>(Wv, wvh, wvl, CDIM, CDIM);
    wprep_kernel<<<dim3(16, 16), tb>>>(Wo, woh, wol, CDIM, CDIM);
    wprep_kernel<<<dim3(64, 16), tb>>>(W1, w1h, w1l, CDIM, FFD);
    wprep_kernel<<<dim3(16, 64), tb>>>(W2, w2h, w2l, FFD, CDIM);
    bias_prep_kernel<<<(NPOS * NPOS + 255) / 256, 256>>>(relb, relidx, biasb);

    // NCHW -> (b, n, c)
    transpose_kernel<<<dim3(25, 16, BATCH), tb>>>(x, xc, CDIM, NPOS);
    // LayerNorm -> bf16 hi/lo
    ln_kernel<<<MROWS, 128>>>(xc, ln_w, ln_b, xnh, xnl);

    const dim3 g512(CDIM / 128, MROWS / 128);   // (4, 98)
    const dim3 g2048(FFD / 128, MROWS / 128);   // (16, 98)
    // Q / K / V projections -> bf16 hi/lo only
    hmma_gemm<0, 0, 1><<<g512, 256, GDSMEM>>>(xnh, xnl, wqh, wql, bq, nullptr,
                                              nullptr, qh, ql, CDIM, CDIM);
    hmma_gemm<0, 0, 1><<<g512, 256, GDSMEM>>>(xnh, xnl, wkh, wkl, bk, nullptr,
                                              nullptr, kh, kl, CDIM, CDIM);
    hmma_gemm<0, 0, 1><<<g512, 256, GDSMEM>>>(xnh, xnl, wvh, wvl, bv, nullptr,
                                              nullptr, vh, vl, CDIM, CDIM);
    // MMA flash attention -> bf16 hi/lo
    attn_mma<<<dim3(7, NHEADS, BATCH), 224, ATTN_SMEM>>>(qh, ql, kh, kl, vh,
                                                         vl, biasb, atth, attl);
    // x1 = xc + att @ Wo + bo   (fp32 + hi/lo)
    hmma_gemm<2, 1, 1><<<g512, 256, GDSMEM>>>(atth, attl, woh, wol, bo, xc,
                                              x1, x1h, x1l, CDIM, CDIM);
    // h1 = gelu(x1 @ W1 + b1)   (hi/lo only)
    hmma_gemm<1, 0, 1><<<g2048, 256, GDSMEM>>>(x1h, x1l, w1h, w1l, b1, nullptr,
                                               nullptr, h1h, h1l, CDIM, FFD);
    // x2 = x1 + h1 @ W2 + b2    (fp32)
    hmma_gemm<2, 1, 0><<<g512, 256, GDSMEM>>>(h1h, h1l, w2h, w2l, b2, x1,
                                              x2, nullptr, nullptr, FFD, CDIM);
    // (b, n, c) -> NCHW
    transpose_kernel<<<dim3(16, 25, BATCH), tb>>>(x2, out, NPOS, CDIM);
}

// round 14
// speedup vs baseline: 3.0980x; 1.3851x over previous
#include <cuda_runtime.h>
#include <cuda_bf16.h>
#include <math.h>
#include <stdint.h>

// ---------------------------------------------------------------------------
// Problem constants
// ---------------------------------------------------------------------------
constexpr int BATCH  = 16;
constexpr int NPOS   = 784;          // 28*28
constexpr int CDIM   = 512;
constexpr int NHEADS = 16;
constexpr int DHEAD  = 32;
constexpr int FFD    = 2048;
constexpr int NREL   = 1596;
constexpr int MROWS  = BATCH * NPOS; // 12544
constexpr int QKVC   = 3 * CDIM;     // 1536

constexpr size_t SZ_NC = (size_t)MROWS * CDIM;
constexpr size_t SZ_Q3 = (size_t)MROWS * QKVC;
constexpr size_t SZ_FF = (size_t)MROWS * FFD;
constexpr size_t SZ_BI = (size_t)NHEADS * NPOS * NPOS;

// ---------------------------------------------------------------------------
// Global scratch (static __device__ arrays — no allocation)
// ---------------------------------------------------------------------------
__device__ float g_xc[SZ_NC];
__device__ float g_x1[SZ_NC];
__device__ float g_bqkv[QKVC];

__device__ __nv_bfloat16 g_xnh[SZ_NC],   g_xnl[SZ_NC];
__device__ __nv_bfloat16 g_qkvh[SZ_Q3],  g_qkvl[SZ_Q3];
__device__ __nv_bfloat16 g_atth[SZ_NC],  g_attl[SZ_NC];
__device__ __nv_bfloat16 g_x1h[SZ_NC],   g_x1l[SZ_NC];
__device__ __nv_bfloat16 g_h1h[SZ_FF],   g_h1l[SZ_FF];
__device__ __nv_bfloat16 g_biasb[SZ_BI];

__device__ __nv_bfloat16 g_wqkvh[(size_t)QKVC*CDIM], g_wqkvl[(size_t)QKVC*CDIM];
__device__ __nv_bfloat16 g_woh[CDIM*CDIM], g_wol[CDIM*CDIM];
__device__ __nv_bfloat16 g_w1h[(size_t)CDIM*FFD], g_w1l[(size_t)CDIM*FFD];
__device__ __nv_bfloat16 g_w2h[(size_t)FFD*CDIM], g_w2l[(size_t)FFD*CDIM];

// ---------------------------------------------------------------------------
// Helpers
// ---------------------------------------------------------------------------
__device__ __forceinline__ uint32_t smem_u32(const void* p) {
    uint32_t a;
    asm("{ .reg .u64 t; cvta.to.shared.u64 t, %1; cvt.u32.u64 %0, t; }"
        : "=r"(a) : "l"(p));
    return a;
}
__device__ __forceinline__ float gelu_exact(float x) {
    return 0.5f * x * (1.0f + erff(x * 0.7071067811865476f));
}
__device__ __forceinline__ void split_bf16(float a, __nv_bfloat16& h,
                                           __nv_bfloat16& l) {
    h = __float2bfloat16(a);
    l = __float2bfloat16(a - __bfloat162float(h));
}
__device__ __forceinline__ void ldm4(uint32_t* r, uint32_t addr) {
    asm volatile(
        "ldmatrix.sync.aligned.m8n8.x4.shared.b16 {%0,%1,%2,%3}, [%4];"
        : "=r"(r[0]), "=r"(r[1]), "=r"(r[2]), "=r"(r[3]) : "r"(addr)
        : "memory");
}
__device__ __forceinline__ void ldm4t(uint32_t* r, uint32_t addr) {
    asm volatile(
        "ldmatrix.sync.aligned.m8n8.x4.trans.shared.b16 {%0,%1,%2,%3}, [%4];"
        : "=r"(r[0]), "=r"(r[1]), "=r"(r[2]), "=r"(r[3]) : "r"(addr)
        : "memory");
}
__device__ __forceinline__ void mma_bf16(float* c, const uint32_t* a,
                                         const uint32_t* b) {
    asm volatile(
        "mma.sync.aligned.m16n8k16.row.col.f32.bf16.bf16.f32 "
        "{%0,%1,%2,%3},{%4,%5,%6,%7},{%8,%9},{%0,%1,%2,%3};"
        : "+f"(c[0]), "+f"(c[1]), "+f"(c[2]), "+f"(c[3])
        : "r"(a[0]), "r"(a[1]), "r"(a[2]), "r"(a[3]), "r"(b[0]), "r"(b[1]));
}
__device__ __forceinline__ void cp16(uint32_t dst, const void* src) {
    asm volatile("cp.async.cg.shared.global [%0], [%1], 16;"
                 :: "r"(dst), "l"(src));
}

// ---------------------------------------------------------------------------
// Tiled 2D transpose per batch:  src [R][Cc]  ->  dst [Cc][R]
// ---------------------------------------------------------------------------
__global__ void transpose_kernel(const float* __restrict__ in,
                                 float* __restrict__ out, int R, int Cc) {
    __shared__ float tile[32][33];
    const int b = blockIdx.z;
    const float* src = in  + (size_t)b * R * Cc;
    float*       dst = out + (size_t)b * R * Cc;
    const int c0 = blockIdx.x * 32;
    const int r0 = blockIdx.y * 32;
    const int tx = threadIdx.x, ty = threadIdx.y;
    #pragma unroll
    for (int j = 0; j < 32; j += 8) {
        int r = r0 + ty + j, c = c0 + tx;
        if (r < R && c < Cc) tile[ty + j][tx] = src[(size_t)r * Cc + c];
    }
    __syncthreads();
    #pragma unroll
    for (int j = 0; j < 32; j += 8) {
        int oc = c0 + ty + j, orr = r0 + tx;
        if (oc < Cc && orr < R) dst[(size_t)oc * R + orr] = tile[tx][ty + j];
    }
}

// ---------------------------------------------------------------------------
// Weight prep: W[K][N] fp32  ->  Bh/Bl [N][K] bf16 (hi/lo split)
// ---------------------------------------------------------------------------
__global__ void wprep_kernel(const float* __restrict__ W,
                             __nv_bfloat16* __restrict__ Bh,
                             __nv_bfloat16* __restrict__ Bl, int K, int N) {
    __shared__ float t[32][33];
    const int n0 = blockIdx.x * 32, k0 = blockIdx.y * 32;
    const int tx = threadIdx.x, ty = threadIdx.y;
    #pragma unroll
    for (int j = 0; j < 32; j += 8)
        t[ty + j][tx] = W[(size_t)(k0 + ty + j) * N + n0 + tx];
    __syncthreads();
    #pragma unroll
    for (int j = 0; j < 32; j += 8) {
        float vv = t[tx][ty + j];
        __nv_bfloat16 h, l;
        split_bf16(vv, h, l);
        size_t idx = (size_t)(n0 + ty + j) * K + k0 + tx;
        Bh[idx] = h;
        Bl[idx] = l;
    }
}

// ---------------------------------------------------------------------------
// Bias preps
// ---------------------------------------------------------------------------
__global__ void bias_prep_kernel(const float* __restrict__ rel_bias,
                                 const int* __restrict__ rel_idx,
                                 __nv_bfloat16* __restrict__ biasb) {
    const int idx = blockIdx.x * 256 + threadIdx.x;
    if (idx >= NPOS * NPOS) return;
    const int ri = rel_idx[idx];
    #pragma unroll
    for (int h = 0; h < NHEADS; ++h)
        biasb[(size_t)h * NPOS * NPOS + idx] =
            __float2bfloat16(rel_bias[h * NREL + ri]);
}
__global__ void bqkv_prep_kernel(const float* __restrict__ bq,
                                 const float* __restrict__ bk,
                                 const float* __restrict__ bv,
                                 float* __restrict__ dst) {
    const int t = threadIdx.x;
    dst[t] = bq[t];
    dst[CDIM + t] = bk[t];
    dst[2 * CDIM + t] = bv[t];
}

// ---------------------------------------------------------------------------
// LayerNorm over C=512, one block (128 threads) per row; emits bf16 hi/lo
// ---------------------------------------------------------------------------
__global__ void __launch_bounds__(128) ln_kernel(const float* __restrict__ xc,
                                                 const float* __restrict__ w,
                                                 const float* __restrict__ bsh,
                                                 __nv_bfloat16* __restrict__ xh,
                                                 __nv_bfloat16* __restrict__ xl) {
    const int row = blockIdx.x;
    const int tid = threadIdx.x;
    const float* xr = xc + (size_t)row * CDIM;
    float4 v = *(const float4*)&xr[tid << 2];
    float s  = v.x + v.y + v.z + v.w;
    float ss = v.x * v.x + v.y * v.y + v.z * v.z + v.w * v.w;
    #pragma unroll
    for (int o = 16; o; o >>= 1) {
        s  += __shfl_xor_sync(0xffffffffu, s, o);
        ss += __shfl_xor_sync(0xffffffffu, ss, o);
    }
    __shared__ float rs[4], rss[4];
    const int warp = tid >> 5, lane = tid & 31;
    if (lane == 0) { rs[warp] = s; rss[warp] = ss; }
    __syncthreads();
    if (tid == 0) {
        float S  = rs[0] + rs[1] + rs[2] + rs[3];
        float SS = rss[0] + rss[1] + rss[2] + rss[3];
        float mu  = S * (1.0f / CDIM);
        float var = SS * (1.0f / CDIM) - mu * mu;
        rs[0]  = mu;
        rss[0] = rsqrtf(var + 1e-5f);
    }
    __syncthreads();
    const float mu = rs[0], rstd = rss[0];
    float4 wv = *(const float4*)&w[tid << 2];
    float4 bv = *(const float4*)&bsh[tid << 2];
    float o[4];
    o[0] = (v.x - mu) * rstd * wv.x + bv.x;
    o[1] = (v.y - mu) * rstd * wv.y + bv.y;
    o[2] = (v.z - mu) * rstd * wv.z + bv.z;
    o[3] = (v.w - mu) * rstd * wv.w + bv.w;
    __nv_bfloat16 h[4], l[4];
    #pragma unroll
    for (int i = 0; i < 4; ++i) split_bf16(o[i], h[i], l[i]);
    uint2 hp, lp;
    __nv_bfloat162 t;
    t = __halves2bfloat162(h[0], h[1]); hp.x = *(uint32_t*)&t;
    t = __halves2bfloat162(h[2], h[3]); hp.y = *(uint32_t*)&t;
    t = __halves2bfloat162(l[0], l[1]); lp.x = *(uint32_t*)&t;
    t = __halves2bfloat162(l[2], l[3]); lp.y = *(uint32_t*)&t;
    *(uint2*)&xh[(size_t)row * CDIM + (tid << 2)] = hp;
    *(uint2*)&xl[(size_t)row * CDIM + (tid << 2)] = lp;
}

// ---------------------------------------------------------------------------
// HMMA bf16x3 GEMM:  C = A @ B^T   (A [M][K], B [N][K], bf16 hi/lo)
// CTA 128x128, BK=32, 256 threads; warp tile 32x64 (4m x 2n warps).
// cp.async double-buffered smem (no register staging -> no spills).
// EPI: 0=bias, 1=bias+gelu, 2=bias+residual, 3=bias+residual+NCHW fp32 out.
// WF: fp32 [M][Nc] out.  WH: bf16 hi/lo out.
// ---------------------------------------------------------------------------
constexpr int GT_TILE  = 128 * 32 * 2;
constexpr int GT_STAGE = 4 * GT_TILE;
constexpr int GDSMEM   = 2 * GT_STAGE;

__device__ __forceinline__ uint32_t sw_off(int row, int kc) {
    return (uint32_t)(row * 64 + ((kc ^ ((row >> 1) & 3)) << 4));
}

template <int EPI, int WF, int WH>
__global__ void __launch_bounds__(256, 2) hmma_gemm(
    const __nv_bfloat16* __restrict__ Ah, const __nv_bfloat16* __restrict__ Al,
    const __nv_bfloat16* __restrict__ Bh, const __nv_bfloat16* __restrict__ Bl,
    const float* __restrict__ bias, const float* __restrict__ res,
    float* __restrict__ Cf, __nv_bfloat16* __restrict__ Ch,
    __nv_bfloat16* __restrict__ Cl, int K, int Nc) {
    extern __shared__ char smp[];
    const uint32_t sb = smem_u32(smp);
    const int tid  = threadIdx.x;
    const int wid  = tid >> 5, lane = tid & 31;
    const int row0 = blockIdx.y * 128, col0 = blockIdx.x * 128;
    const int wm   = (wid & 3) * 32;
    const int wn   = (wid >> 2) * 64;

    const int e0   = tid * 2;
    const int grow = e0 >> 2;
    const int gkc  = e0 & 3;
    const uint32_t so0 = sw_off(grow, gkc);
    const uint32_t so1 = sw_off(grow, gkc + 1);
    const __nv_bfloat16* gA_h = Ah + (size_t)(row0 + grow) * K + gkc * 8;
    const __nv_bfloat16* gA_l = Al + (size_t)(row0 + grow) * K + gkc * 8;
    const __nv_bfloat16* gB_h = Bh + (size_t)(col0 + grow) * K + gkc * 8;
    const __nv_bfloat16* gB_l = Bl + (size_t)(col0 + grow) * K + gkc * 8;

    const int a_moff = ((lane >> 3) & 1) * 8 + (lane & 7);
    const int a_k8   = lane >> 4;
    const int b_noff = (lane >> 4) * 8 + (lane & 7);
    const int b_k8   = (lane >> 3) & 1;
    uint32_t aRow64[2], aRsw[2];
    #pragma unroll
    for (int mt = 0; mt < 2; ++mt) {
        int r = wm + mt * 16 + a_moff;
        aRow64[mt] = r * 64;
        aRsw[mt]   = (r >> 1) & 3;
    }
    uint32_t bRow64[4], bRsw[4];
    #pragma unroll
    for (int ntp = 0; ntp < 4; ++ntp) {
        int r = wn + ntp * 16 + b_noff;
        bRow64[ntp] = r * 64;
        bRsw[ntp]   = (r >> 1) & 3;
    }

    float acc[2][8][4];
    #pragma unroll
    for (int i = 0; i < 2; ++i)
        #pragma unroll
        for (int j = 0; j < 8; ++j)
            #pragma unroll
            for (int p = 0; p < 4; ++p) acc[i][j][p] = 0.0f;

    const int NCH = K >> 5;

    // async load of chunk c into buffer c&1
    auto issue = [&](int c) {
        const uint32_t stg = sb + (c & 1) * GT_STAGE;
        const int ko = c << 5;
        cp16(stg + 0 * GT_TILE + so0, gA_h + ko);
        cp16(stg + 0 * GT_TILE + so1, gA_h + ko + 8);
        cp16(stg + 1 * GT_TILE + so0, gA_l + ko);
        cp16(stg + 1 * GT_TILE + so1, gA_l + ko + 8);
        cp16(stg + 2 * GT_TILE + so0, gB_h + ko);
        cp16(stg + 2 * GT_TILE + so1, gB_h + ko + 8);
        cp16(stg + 3 * GT_TILE + so0, gB_l + ko);
        cp16(stg + 3 * GT_TILE + so1, gB_l + ko + 8);
        asm volatile("cp.async.commit_group;");
    };
    issue(0);

    for (int c = 0; c < NCH; ++c) {
        if (c + 1 < NCH) {
            issue(c + 1);
            asm volatile("cp.async.wait_group 1;");
        } else {
            asm volatile("cp.async.wait_group 0;");
        }
        __syncthreads();
        const uint32_t stg = (c & 1) * GT_STAGE;
        const uint32_t sAh = sb + stg;
        const uint32_t sAl = sAh + GT_TILE;
        const uint32_t sBh = sAl + GT_TILE;
        const uint32_t sBl = sBh + GT_TILE;
        #pragma unroll
        for (int kk = 0; kk < 2; ++kk) {
            uint32_t ah[2][4], al[2][4];
            #pragma unroll
            for (int mt = 0; mt < 2; ++mt) {
                const uint32_t ck = ((uint32_t)(kk * 2 + a_k8) ^ aRsw[mt]) << 4;
                ldm4(ah[mt], sAh + aRow64[mt] + ck);
                ldm4(al[mt], sAl + aRow64[mt] + ck);
            }
            #pragma unroll
            for (int ntp = 0; ntp < 4; ++ntp) {
                const uint32_t ck = ((uint32_t)(kk * 2 + b_k8) ^ bRsw[ntp]) << 4;
                uint32_t bh4[4], bl4[4];
                ldm4(bh4, sBh + bRow64[ntp] + ck);
                ldm4(bl4, sBl + bRow64[ntp] + ck);
                #pragma unroll
                for (int mt = 0; mt < 2; ++mt) {
                    mma_bf16(acc[mt][2 * ntp],     ah[mt], bh4);
                    mma_bf16(acc[mt][2 * ntp],     ah[mt], bl4);
                    mma_bf16(acc[mt][2 * ntp],     al[mt], bh4);
                    mma_bf16(acc[mt][2 * ntp + 1], ah[mt], bh4 + 2);
                    mma_bf16(acc[mt][2 * ntp + 1], ah[mt], bl4 + 2);
                    mma_bf16(acc[mt][2 * ntp + 1], al[mt], bh4 + 2);
                }
            }
        }
        __syncthreads();
    }

    const int q  = lane >> 2;
    const int tc = lane & 3;
    #pragma unroll
    for (int mt = 0; mt < 2; ++mt) {
        #pragma unroll
        for (int nt = 0; nt < 8; ++nt) {
            float* cc = acc[mt][nt];
            const int col = col0 + wn + nt * 8 + tc * 2;
            const float2 bb = *(const float2*)&bias[col];
            #pragma unroll
            for (int hrow = 0; hrow < 2; ++hrow) {
                const size_t r = (size_t)(row0 + wm + mt * 16 + q + hrow * 8);
                float v0 = cc[2 * hrow + 0] + bb.x;
                float v1 = cc[2 * hrow + 1] + bb.y;
                if (EPI == 1) { v0 = gelu_exact(v0); v1 = gelu_exact(v1); }
                if (EPI == 2 || EPI == 3) {
                    float2 rv = *(const float2*)&res[r * Nc + col];
                    v0 += rv.x; v1 += rv.y;
                }
                if (EPI == 3) {
                    // write fp32 NCHW directly: out[b][col][n]
                    const int bb_ = (int)r / NPOS;
                    const int nn_ = (int)r - bb_ * NPOS;
                    Cf[((size_t)(bb_ * CDIM + col)) * NPOS + nn_]     = v0;
                    Cf[((size_t)(bb_ * CDIM + col + 1)) * NPOS + nn_] = v1;
                } else if (WF) {
                    *(float2*)&Cf[r * Nc + col] = make_float2(v0, v1);
                }
                if (WH) {
                    __nv_bfloat16 h0, l0, h1, l1;
                    split_bf16(v0, h0, l0);
                    split_bf16(v1, h1, l1);
                    __nv_bfloat162 th = __halves2bfloat162(h0, h1);
                    __nv_bfloat162 tl = __halves2bfloat162(l0, l1);
                    *(uint32_t*)&Ch[r * Nc + col] = *(uint32_t*)&th;
                    *(uint32_t*)&Cl[r * Nc + col] = *(uint32_t*)&tl;
                }
            }
        }
    }
}

// ---------------------------------------------------------------------------
// MMA flash attention. CTA = (b, h, 112-q-tile); 7 warps x 16 rows.
// Q/K/V come from the merged QKV buffer (stride 1536; q@0, k@512, v@1024).
// ---------------------------------------------------------------------------
constexpr int AQT   = 112;
constexpr int ROWB  = 80;
constexpr int A_SQH = 0;
constexpr int A_SQL = A_SQH + AQT * ROWB;
constexpr int A_SKH = A_SQL + AQT * ROWB;
constexpr int A_SKL = A_SKH + AQT * ROWB;
constexpr int A_SVH = A_SKL + AQT * ROWB;
constexpr int A_SVL = A_SVH + AQT * ROWB;
constexpr int A_SBI = A_SVL + AQT * ROWB;
constexpr int A_BIW = 16 * 240;
constexpr int ATTN_SMEM = A_SBI + 7 * A_BIW;

__global__ void __launch_bounds__(224, 2) attn_mma(
    const __nv_bfloat16* __restrict__ qkvh,
    const __nv_bfloat16* __restrict__ qkvl,
    const __nv_bfloat16* __restrict__ biasb,
    __nv_bfloat16* __restrict__ atth, __nv_bfloat16* __restrict__ attl) {
    extern __shared__ char sm[];
    const uint32_t sb = smem_u32(sm);
    const int tid  = threadIdx.x;
    const int wid  = tid >> 5, lane = tid & 31;
    const int qt = blockIdx.x, h = blockIdx.y, b = blockIdx.z;
    const int n0 = qt * AQT;

    // ---- load Q tile (hi/lo) ----
    #pragma unroll
    for (int e = tid; e < 448; e += 224) {
        const int r = e >> 2, c = e & 3;
        const size_t g =
            (size_t)(b * NPOS + n0 + r) * QKVC + h * DHEAD + c * 8;
        *(uint4*)(sm + A_SQH + r * ROWB + c * 16) = *(const uint4*)(qkvh + g);
        *(uint4*)(sm + A_SQL + r * ROWB + c * 16) = *(const uint4*)(qkvl + g);
    }
    __syncthreads();

    const int am  = ((lane >> 3) & 1) * 8 + (lane & 7);
    const int ak8 = lane >> 4;
    uint32_t qfh[2][4], qfl[2][4];
    #pragma unroll
    for (int kk = 0; kk < 2; ++kk) {
        const uint32_t off = (wid * 16 + am) * ROWB + (kk * 2 + ak8) * 16;
        ldm4(qfh[kk], sb + A_SQH + off);
        ldm4(qfl[kk], sb + A_SQL + off);
    }

    const int bn  = (lane >> 4) * 8 + (lane & 7);
    const int bk8 = (lane >> 3) & 1;

    float m0 = -1e30f, m1 = -1e30f, l0 = 0.0f, l1 = 0.0f;
    float oa[4][4];
    #pragma unroll
    for (int j = 0; j < 4; ++j)
        #pragma unroll
        for (int p = 0; p < 4; ++p) oa[j][p] = 0.0f;

    const uint32_t sBiasW = sb + A_SBI + wid * A_BIW;

    for (int kt = 0; kt < 7; ++kt) {
        const int mp0 = kt * AQT;
        __syncthreads();
        #pragma unroll
        for (int e = tid; e < 448; e += 224) {
            const int r = e >> 2, c = e & 3;
            const size_t gk = (size_t)(b * NPOS + mp0 + r) * QKVC + CDIM +
                              h * DHEAD + c * 8;
            const size_t gv = gk + CDIM;
            const uint32_t so = r * ROWB + c * 16;
            *(uint4*)(sm + A_SKH + so) = *(const uint4*)(qkvh + gk);
            *(uint4*)(sm + A_SKL + so) = *(const uint4*)(qkvl + gk);
            *(uint4*)(sm + A_SVH + so) = *(const uint4*)(qkvh + gv);
            *(uint4*)(sm + A_SVL + so) = *(const uint4*)(qkvl + gv);
        }
        __syncthreads();

        #pragma unroll
        for (int e = lane; e < 224; e += 32) {
            const int r = e / 14, c = e % 14;
            *(uint4*)(sm + A_SBI + wid * A_BIW + r * 240 + c * 16) =
                *(const uint4*)(biasb + (size_t)h * NPOS * NPOS +
                                (size_t)(n0 + wid * 16 + r) * NPOS + mp0 +
                                c * 8);
        }
        __syncwarp();

        float sa[14][4];
        #pragma unroll
        for (int t = 0; t < 14; ++t)
            #pragma unroll
            for (int p = 0; p < 4; ++p) sa[t][p] = 0.0f;
        #pragma unroll
        for (int kk = 0; kk < 2; ++kk) {
            #pragma unroll
            for (int g = 0; g < 7; ++g) {
                const uint32_t off =
                    (g * 16 + bn) * ROWB + (kk * 2 + bk8) * 16;
                uint32_t kh4[4], kl4[4];
                ldm4(kh4, sb + A_SKH + off);
                ldm4(kl4, sb + A_SKL + off);
                mma_bf16(sa[2 * g],     qfh[kk], kh4);
                mma_bf16(sa[2 * g],     qfh[kk], kl4);
                mma_bf16(sa[2 * g],     qfl[kk], kh4);
                mma_bf16(sa[2 * g + 1], qfh[kk], kh4 + 2);
                mma_bf16(sa[2 * g + 1], qfh[kk], kl4 + 2);
                mma_bf16(sa[2 * g + 1], qfl[kk], kh4 + 2);
            }
        }

        #pragma unroll
        for (int c7 = 0; c7 < 7; ++c7) {
            uint32_t bb[4];
            ldm4(bb, sBiasW + am * 240 + c7 * 32 + ak8 * 16);
            float2 f0 = __bfloat1622float2(*(__nv_bfloat162*)&bb[0]);
            float2 f1 = __bfloat1622float2(*(__nv_bfloat162*)&bb[1]);
            float2 f2 = __bfloat1622float2(*(__nv_bfloat162*)&bb[2]);
            float2 f3 = __bfloat1622float2(*(__nv_bfloat162*)&bb[3]);
            sa[2 * c7][0] += f0.x;     sa[2 * c7][1] += f0.y;
            sa[2 * c7][2] += f1.x;     sa[2 * c7][3] += f1.y;
            sa[2 * c7 + 1][0] += f2.x; sa[2 * c7 + 1][1] += f2.y;
            sa[2 * c7 + 1][2] += f3.x; sa[2 * c7 + 1][3] += f3.y;
        }

        float mx0 = -1e30f, mx1 = -1e30f;
        #pragma unroll
        for (int t = 0; t < 14; ++t) {
            mx0 = fmaxf(mx0, fmaxf(sa[t][0], sa[t][1]));
            mx1 = fmaxf(mx1, fmaxf(sa[t][2], sa[t][3]));
        }
        mx0 = fmaxf(mx0, __shfl_xor_sync(0xffffffffu, mx0, 1));
        mx0 = fmaxf(mx0, __shfl_xor_sync(0xffffffffu, mx0, 2));
        mx1 = fmaxf(mx1, __shfl_xor_sync(0xffffffffu, mx1, 1));
        mx1 = fmaxf(mx1, __shfl_xor_sync(0xffffffffu, mx1, 2));
        const float nm0 = fmaxf(m0, mx0), nm1 = fmaxf(m1, mx1);
        const float f0 = __expf(m0 - nm0), f1 = __expf(m1 - nm1);
        m0 = nm0; m1 = nm1;
        float s0 = 0.0f, s1 = 0.0f;
        #pragma unroll
        for (int t = 0; t < 14; ++t) {
            sa[t][0] = __expf(sa[t][0] - m0);
            sa[t][1] = __expf(sa[t][1] - m0);
            sa[t][2] = __expf(sa[t][2] - m1);
            sa[t][3] = __expf(sa[t][3] - m1);
            s0 += sa[t][0] + sa[t][1];
            s1 += sa[t][2] + sa[t][3];
        }
        s0 += __shfl_xor_sync(0xffffffffu, s0, 1);
        s0 += __shfl_xor_sync(0xffffffffu, s0, 2);
        s1 += __shfl_xor_sync(0xffffffffu, s1, 1);
        s1 += __shfl_xor_sync(0xffffffffu, s1, 2);
        l0 = l0 * f0 + s0;
        l1 = l1 * f1 + s1;
        #pragma unroll
        for (int j = 0; j < 4; ++j) {
            oa[j][0] *= f0; oa[j][1] *= f0;
            oa[j][2] *= f1; oa[j][3] *= f1;
        }

        #pragma unroll
        for (int t = 0; t < 7; ++t) {
            uint32_t pa_h[4], pa_l[4];
            #pragma unroll
            for (int half = 0; half < 2; ++half) {
                const float* src = sa[2 * t + half];
                __nv_bfloat162 h01 = __floats2bfloat162_rn(src[0], src[1]);
                float2 r01 = __bfloat1622float2(h01);
                __nv_bfloat162 l01 =
                    __floats2bfloat162_rn(src[0] - r01.x, src[1] - r01.y);
                __nv_bfloat162 h23 = __floats2bfloat162_rn(src[2], src[3]);
                float2 r23 = __bfloat1622float2(h23);
                __nv_bfloat162 l23 =
                    __floats2bfloat162_rn(src[2] - r23.x, src[3] - r23.y);
                pa_h[2 * half]     = *(uint32_t*)&h01;
                pa_h[2 * half + 1] = *(uint32_t*)&h23;
                pa_l[2 * half]     = *(uint32_t*)&l01;
                pa_l[2 * half + 1] = *(uint32_t*)&l23;
            }
            #pragma unroll
            for (int v = 0; v < 2; ++v) {
                const uint32_t off =
                    (t * 16 + am) * ROWB + v * 32 + (lane >> 4) * 16;
                uint32_t vh4[4], vl4[4];
                ldm4t(vh4, sb + A_SVH + off);
                ldm4t(vl4, sb + A_SVL + off);
                mma_bf16(oa[2 * v],     pa_h, vh4);
                mma_bf16(oa[2 * v],     pa_h, vl4);
                mma_bf16(oa[2 * v],     pa_l, vh4);
                mma_bf16(oa[2 * v + 1], pa_h, vh4 + 2);
                mma_bf16(oa[2 * v + 1], pa_h, vl4 + 2);
                mma_bf16(oa[2 * v + 1], pa_l, vh4 + 2);
            }
        }
    }

    const float inv0 = 1.0f / l0, inv1 = 1.0f / l1;
    const int q  = lane >> 2, tc = lane & 3;
    const size_t r0 = (size_t)(b * NPOS + n0 + wid * 16 + q);
    const size_t r1 = r0 + 8;
    #pragma unroll
    for (int j = 0; j < 4; ++j) {
        const int col = h * DHEAD + j * 8 + tc * 2;
        float a0 = oa[j][0] * inv0, a1 = oa[j][1] * inv0;
        float b0 = oa[j][2] * inv1, b1 = oa[j][3] * inv1;
        __nv_bfloat16 h0, lo0, h1, lo1;
        split_bf16(a0, h0, lo0); split_bf16(a1, h1, lo1);
        __nv_bfloat162 th = __halves2bfloat162(h0, h1);
        __nv_bfloat162 tl = __halves2bfloat162(lo0, lo1);
        *(uint32_t*)&atth[r0 * CDIM + col] = *(uint32_t*)&th;
        *(uint32_t*)&attl[r0 * CDIM + col] = *(uint32_t*)&tl;
        split_bf16(b0, h0, lo0); split_bf16(b1, h1, lo1);
        th = __halves2bfloat162(h0, h1);
        tl = __halves2bfloat162(lo0, lo1);
        *(uint32_t*)&atth[r1 * CDIM + col] = *(uint32_t*)&th;
        *(uint32_t*)&attl[r1 * CDIM + col] = *(uint32_t*)&tl;
    }
}

// ---------------------------------------------------------------------------
// Launch
// ---------------------------------------------------------------------------
extern "C" void kernel_launch(void* const* d_in, const int* in_sizes, int n_in,
                              void* d_out, int out_size) {
    (void)in_sizes; (void)n_in; (void)out_size;
    const float* x      = (const float*)d_in[0];
    const float* ln_w   = (const float*)d_in[1];
    const float* ln_b   = (const float*)d_in[2];
    const float* Wq     = (const float*)d_in[3];
    const float* bq     = (const float*)d_in[4];
    const float* Wk     = (const float*)d_in[5];
    const float* bk     = (const float*)d_in[6];
    const float* Wv     = (const float*)d_in[7];
    const float* bv     = (const float*)d_in[8];
    const float* Wo     = (const float*)d_in[9];
    const float* bo     = (const float*)d_in[10];
    const float* relb   = (const float*)d_in[11];
    const float* W1     = (const float*)d_in[12];
    const float* b1     = (const float*)d_in[13];
    const float* W2     = (const float*)d_in[14];
    const float* b2     = (const float*)d_in[15];
    const int*   relidx = (const int*)d_in[16];
    float* out = (float*)d_out;

    auto sym = [](const void* s) {
        void* p = nullptr;
        cudaGetSymbolAddress(&p, s);
        return p;
    };
    float* xc   = (float*)sym(g_xc);
    float* x1   = (float*)sym(g_x1);
    float* bqkv = (float*)sym(g_bqkv);
    __nv_bfloat16* xnh   = (__nv_bfloat16*)sym(g_xnh);
    __nv_bfloat16* xnl   = (__nv_bfloat16*)sym(g_xnl);
    __nv_bfloat16* qkvh  = (__nv_bfloat16*)sym(g_qkvh);
    __nv_bfloat16* qkvl  = (__nv_bfloat16*)sym(g_qkvl);
    __nv_bfloat16* atth  = (__nv_bfloat16*)sym(g_atth);
    __nv_bfloat16* attl  = (__nv_bfloat16*)sym(g_attl);
    __nv_bfloat16* x1h   = (__nv_bfloat16*)sym(g_x1h);
    __nv_bfloat16* x1l   = (__nv_bfloat16*)sym(g_x1l);
    __nv_bfloat16* h1h   = (__nv_bfloat16*)sym(g_h1h);
    __nv_bfloat16* h1l   = (__nv_bfloat16*)sym(g_h1l);
    __nv_bfloat16* biasb = (__nv_bfloat16*)sym(g_biasb);
    __nv_bfloat16* wqkvh = (__nv_bfloat16*)sym(g_wqkvh);
    __nv_bfloat16* wqkvl = (__nv_bfloat16*)sym(g_wqkvl);
    __nv_bfloat16* woh = (__nv_bfloat16*)sym(g_woh), *wol = (__nv_bfloat16*)sym(g_wol);
    __nv_bfloat16* w1h = (__nv_bfloat16*)sym(g_w1h), *w1l = (__nv_bfloat16*)sym(g_w1l);
    __nv_bfloat16* w2h = (__nv_bfloat16*)sym(g_w2h), *w2l = (__nv_bfloat16*)sym(g_w2l);

    cudaFuncSetAttribute(attn_mma,
                         cudaFuncAttributeMaxDynamicSharedMemorySize, ATTN_SMEM);
    cudaFuncSetAttribute(hmma_gemm<0, 0, 1>,
                         cudaFuncAttributeMaxDynamicSharedMemorySize, GDSMEM);
    cudaFuncSetAttribute(hmma_gemm<2, 1, 1>,
                         cudaFuncAttributeMaxDynamicSharedMemorySize, GDSMEM);
    cudaFuncSetAttribute(hmma_gemm<1, 0, 1>,
                         cudaFuncAttributeMaxDynamicSharedMemorySize, GDSMEM);
    cudaFuncSetAttribute(hmma_gemm<3, 1, 0>,
                         cudaFuncAttributeMaxDynamicSharedMemorySize, GDSMEM);

    const dim3 tb(32, 8);
    // weight + bias prep (QKV weights stacked along N into one [1536][512])
    wprep_kernel<<<dim3(16, 16), tb>>>(Wq, wqkvh, wqkvl, CDIM, CDIM);
    wprep_kernel<<<dim3(16, 16), tb>>>(Wk, wqkvh + (size_t)CDIM * CDIM,
                                       wqkvl + (size_t)CDIM * CDIM, CDIM, CDIM);
    wprep_kernel<<<dim3(16, 16), tb>>>(Wv, wqkvh + (size_t)2 * CDIM * CDIM,
                                       wqkvl + (size_t)2 * CDIM * CDIM, CDIM,
                                       CDIM);
    wprep_kernel<<<dim3(16, 16), tb>>>(Wo, woh, wol, CDIM, CDIM);
    wprep_kernel<<<dim3(64, 16), tb>>>(W1, w1h, w1l, CDIM, FFD);
    wprep_kernel<<<dim3(16, 64), tb>>>(W2, w2h, w2l, FFD, CDIM);
    bias_prep_kernel<<<(NPOS * NPOS + 255) / 256, 256>>>(relb, relidx, biasb);
    bqkv_prep_kernel<<<1, CDIM>>>(bq, bk, bv, bqkv);

    // NCHW -> (b, n, c)
    transpose_kernel<<<dim3(25, 16, BATCH), tb>>>(x, xc, CDIM, NPOS);
    // LayerNorm -> bf16 hi/lo
    ln_kernel<<<MROWS, 128>>>(xc, ln_w, ln_b, xnh, xnl);

    const dim3 gqkv(QKVC / 128, MROWS / 128);   // (12, 98)
    const dim3 g512(CDIM / 128, MROWS / 128);   // (4, 98)
    const dim3 g2048(FFD / 128, MROWS / 128);   // (16, 98)
    // fused QKV projection -> merged bf16 hi/lo [M][1536]
    hmma_gemm<0, 0, 1><<<gqkv, 256, GDSMEM>>>(xnh, xnl, wqkvh, wqkvl, bqkv,
                                              nullptr, nullptr, qkvh, qkvl,
                                              CDIM, QKVC);
    // MMA flash attention -> bf16 hi/lo
    attn_mma<<<dim3(7, NHEADS, BATCH), 224, ATTN_SMEM>>>(qkvh, qkvl, biasb,
                                                         atth, attl);
    // x1 = xc + att @ Wo + bo   (fp32 + hi/lo)
    hmma_gemm<2, 1, 1><<<g512, 256, GDSMEM>>>(atth, attl, woh, wol, bo, xc,
                                              x1, x1h, x1l, CDIM, CDIM);
    // h1 = gelu(x1 @ W1 + b1)   (hi/lo only)
    hmma_gemm<1, 0, 1><<<g2048, 256, GDSMEM>>>(x1h, x1l, w1h, w1l, b1, nullptr,
                                               nullptr, h1h, h1l, CDIM, FFD);
    // out(NCHW) = x1 + h1 @ W2 + b2   (fused final transpose)
    hmma_gemm<3, 1, 0><<<g512, 256, GDSMEM>>>(h1h, h1l, w2h, w2l, b2, x1,
                                              out, nullptr, nullptr, FFD,
                                              CDIM);
}

// round 15
// speedup vs baseline: 3.1032x; 1.0017x over previous
#include <cuda_runtime.h>
#include <cuda_bf16.h>
#include <math.h>
#include <stdint.h>

// ---------------------------------------------------------------------------
// Problem constants
// ---------------------------------------------------------------------------
constexpr int BATCH  = 16;
constexpr int NPOS   = 784;          // 28*28
constexpr int CDIM   = 512;
constexpr int NHEADS = 16;
constexpr int DHEAD  = 32;
constexpr int FFD    = 2048;
constexpr int NREL   = 1596;
constexpr int MROWS  = BATCH * NPOS; // 12544
constexpr int QKVC   = 3 * CDIM;     // 1536

constexpr size_t SZ_NC = (size_t)MROWS * CDIM;
constexpr size_t SZ_Q3 = (size_t)MROWS * QKVC;
constexpr size_t SZ_FF = (size_t)MROWS * FFD;
constexpr size_t SZ_BI = (size_t)NHEADS * NPOS * NPOS;

// ---------------------------------------------------------------------------
// Global scratch (static __device__ arrays — no allocation)
// ---------------------------------------------------------------------------
__device__ float g_xc[SZ_NC];
__device__ float g_bqkv[QKVC];

__device__ __nv_bfloat16 g_xnh[SZ_NC],   g_xnl[SZ_NC];
__device__ __nv_bfloat16 g_qkvh[SZ_Q3],  g_qkvl[SZ_Q3];
__device__ __nv_bfloat16 g_atth[SZ_NC],  g_attl[SZ_NC];
__device__ __nv_bfloat16 g_x1h[SZ_NC],   g_x1l[SZ_NC];
__device__ __nv_bfloat16 g_h1h[SZ_FF],   g_h1l[SZ_FF];
__device__ __nv_bfloat16 g_biasb[SZ_BI];

__device__ __nv_bfloat16 g_wqkvh[(size_t)QKVC*CDIM], g_wqkvl[(size_t)QKVC*CDIM];
__device__ __nv_bfloat16 g_woh[CDIM*CDIM], g_wol[CDIM*CDIM];
__device__ __nv_bfloat16 g_w1h[(size_t)CDIM*FFD], g_w1l[(size_t)CDIM*FFD];
__device__ __nv_bfloat16 g_w2h[(size_t)FFD*CDIM], g_w2l[(size_t)FFD*CDIM];

// ---------------------------------------------------------------------------
// Helpers
// ---------------------------------------------------------------------------
__device__ __forceinline__ uint32_t smem_u32(const void* p) {
    uint32_t a;
    asm("{ .reg .u64 t; cvta.to.shared.u64 t, %1; cvt.u32.u64 %0, t; }"
        : "=r"(a) : "l"(p));
    return a;
}
__device__ __forceinline__ float gelu_exact(float x) {
    return 0.5f * x * (1.0f + erff(x * 0.7071067811865476f));
}
__device__ __forceinline__ void split_bf16(float a, __nv_bfloat16& h,
                                           __nv_bfloat16& l) {
    h = __float2bfloat16(a);
    l = __float2bfloat16(a - __bfloat162float(h));
}
__device__ __forceinline__ void ldm4(uint32_t* r, uint32_t addr) {
    asm volatile(
        "ldmatrix.sync.aligned.m8n8.x4.shared.b16 {%0,%1,%2,%3}, [%4];"
        : "=r"(r[0]), "=r"(r[1]), "=r"(r[2]), "=r"(r[3]) : "r"(addr)
        : "memory");
}
__device__ __forceinline__ void ldm4t(uint32_t* r, uint32_t addr) {
    asm volatile(
        "ldmatrix.sync.aligned.m8n8.x4.trans.shared.b16 {%0,%1,%2,%3}, [%4];"
        : "=r"(r[0]), "=r"(r[1]), "=r"(r[2]), "=r"(r[3]) : "r"(addr)
        : "memory");
}
__device__ __forceinline__ void mma_bf16(float* c, const uint32_t* a,
                                         const uint32_t* b) {
    asm volatile(
        "mma.sync.aligned.m16n8k16.row.col.f32.bf16.bf16.f32 "
        "{%0,%1,%2,%3},{%4,%5,%6,%7},{%8,%9},{%0,%1,%2,%3};"
        : "+f"(c[0]), "+f"(c[1]), "+f"(c[2]), "+f"(c[3])
        : "r"(a[0]), "r"(a[1]), "r"(a[2]), "r"(a[3]), "r"(b[0]), "r"(b[1]));
}
__device__ __forceinline__ void cp16(uint32_t dst, const void* src) {
    asm volatile("cp.async.cg.shared.global [%0], [%1], 16;"
                 :: "r"(dst), "l"(src));
}

// ---------------------------------------------------------------------------
// Tiled 2D transpose per batch:  src [R][Cc]  ->  dst [Cc][R]
// ---------------------------------------------------------------------------
__global__ void transpose_kernel(const float* __restrict__ in,
                                 float* __restrict__ out, int R, int Cc) {
    __shared__ float tile[32][33];
    const int b = blockIdx.z;
    const float* src = in  + (size_t)b * R * Cc;
    float*       dst = out + (size_t)b * R * Cc;
    const int c0 = blockIdx.x * 32;
    const int r0 = blockIdx.y * 32;
    const int tx = threadIdx.x, ty = threadIdx.y;
    #pragma unroll
    for (int j = 0; j < 32; j += 8) {
        int r = r0 + ty + j, c = c0 + tx;
        if (r < R && c < Cc) tile[ty + j][tx] = src[(size_t)r * Cc + c];
    }
    __syncthreads();
    #pragma unroll
    for (int j = 0; j < 32; j += 8) {
        int oc = c0 + ty + j, orr = r0 + tx;
        if (oc < Cc && orr < R) dst[(size_t)oc * R + orr] = tile[tx][ty + j];
    }
}

// ---------------------------------------------------------------------------
// Weight prep: W[K][N] fp32  ->  Bh/Bl [N][K] bf16 (hi/lo split)
// ---------------------------------------------------------------------------
__global__ void wprep_kernel(const float* __restrict__ W,
                             __nv_bfloat16* __restrict__ Bh,
                             __nv_bfloat16* __restrict__ Bl, int K, int N) {
    __shared__ float t[32][33];
    const int n0 = blockIdx.x * 32, k0 = blockIdx.y * 32;
    const int tx = threadIdx.x, ty = threadIdx.y;
    #pragma unroll
    for (int j = 0; j < 32; j += 8)
        t[ty + j][tx] = W[(size_t)(k0 + ty + j) * N + n0 + tx];
    __syncthreads();
    #pragma unroll
    for (int j = 0; j < 32; j += 8) {
        float vv = t[tx][ty + j];
        __nv_bfloat16 h, l;
        split_bf16(vv, h, l);
        size_t idx = (size_t)(n0 + ty + j) * K + k0 + tx;
        Bh[idx] = h;
        Bl[idx] = l;
    }
}

// Fused QKV weight prep: z = 0/1/2 selects Wq/Wk/Wv, stacked along N.
__global__ void wqkv_prep_kernel(const float* __restrict__ Wq,
                                 const float* __restrict__ Wk,
                                 const float* __restrict__ Wv,
                                 __nv_bfloat16* __restrict__ Bh,
                                 __nv_bfloat16* __restrict__ Bl) {
    __shared__ float t[32][33];
    const int z = blockIdx.z;
    const float* W = (z == 0) ? Wq : ((z == 1) ? Wk : Wv);
    const size_t off = (size_t)z * CDIM * CDIM;
    const int n0 = blockIdx.x * 32, k0 = blockIdx.y * 32;
    const int tx = threadIdx.x, ty = threadIdx.y;
    #pragma unroll
    for (int j = 0; j < 32; j += 8)
        t[ty + j][tx] = W[(size_t)(k0 + ty + j) * CDIM + n0 + tx];
    __syncthreads();
    #pragma unroll
    for (int j = 0; j < 32; j += 8) {
        float vv = t[tx][ty + j];
        __nv_bfloat16 h, l;
        split_bf16(vv, h, l);
        size_t idx = off + (size_t)(n0 + ty + j) * CDIM + k0 + tx;
        Bh[idx] = h;
        Bl[idx] = l;
    }
}

// ---------------------------------------------------------------------------
// Bias preps
// ---------------------------------------------------------------------------
__global__ void bias_prep_kernel(const float* __restrict__ rel_bias,
                                 const int* __restrict__ rel_idx,
                                 __nv_bfloat16* __restrict__ biasb) {
    const int idx = blockIdx.x * 256 + threadIdx.x;
    if (idx >= NPOS * NPOS) return;
    const int ri = rel_idx[idx];
    #pragma unroll
    for (int h = 0; h < NHEADS; ++h)
        biasb[(size_t)h * NPOS * NPOS + idx] =
            __float2bfloat16(rel_bias[h * NREL + ri]);
}
__global__ void bqkv_prep_kernel(const float* __restrict__ bq,
                                 const float* __restrict__ bk,
                                 const float* __restrict__ bv,
                                 float* __restrict__ dst) {
    const int t = threadIdx.x;
    dst[t] = bq[t];
    dst[CDIM + t] = bk[t];
    dst[2 * CDIM + t] = bv[t];
}

// ---------------------------------------------------------------------------
// LayerNorm over C=512, one block (128 threads) per row; emits bf16 hi/lo
// ---------------------------------------------------------------------------
__global__ void __launch_bounds__(128) ln_kernel(const float* __restrict__ xc,
                                                 const float* __restrict__ w,
                                                 const float* __restrict__ bsh,
                                                 __nv_bfloat16* __restrict__ xh,
                                                 __nv_bfloat16* __restrict__ xl) {
    const int row = blockIdx.x;
    const int tid = threadIdx.x;
    const float* xr = xc + (size_t)row * CDIM;
    float4 v = *(const float4*)&xr[tid << 2];
    float s  = v.x + v.y + v.z + v.w;
    float ss = v.x * v.x + v.y * v.y + v.z * v.z + v.w * v.w;
    #pragma unroll
    for (int o = 16; o; o >>= 1) {
        s  += __shfl_xor_sync(0xffffffffu, s, o);
        ss += __shfl_xor_sync(0xffffffffu, ss, o);
    }
    __shared__ float rs[4], rss[4];
    const int warp = tid >> 5, lane = tid & 31;
    if (lane == 0) { rs[warp] = s; rss[warp] = ss; }
    __syncthreads();
    if (tid == 0) {
        float S  = rs[0] + rs[1] + rs[2] + rs[3];
        float SS = rss[0] + rss[1] + rss[2] + rss[3];
        float mu  = S * (1.0f / CDIM);
        float var = SS * (1.0f / CDIM) - mu * mu;
        rs[0]  = mu;
        rss[0] = rsqrtf(var + 1e-5f);
    }
    __syncthreads();
    const float mu = rs[0], rstd = rss[0];
    float4 wv = *(const float4*)&w[tid << 2];
    float4 bv = *(const float4*)&bsh[tid << 2];
    float o[4];
    o[0] = (v.x - mu) * rstd * wv.x + bv.x;
    o[1] = (v.y - mu) * rstd * wv.y + bv.y;
    o[2] = (v.z - mu) * rstd * wv.z + bv.z;
    o[3] = (v.w - mu) * rstd * wv.w + bv.w;
    __nv_bfloat16 h[4], l[4];
    #pragma unroll
    for (int i = 0; i < 4; ++i) split_bf16(o[i], h[i], l[i]);
    uint2 hp, lp;
    __nv_bfloat162 t;
    t = __halves2bfloat162(h[0], h[1]); hp.x = *(uint32_t*)&t;
    t = __halves2bfloat162(h[2], h[3]); hp.y = *(uint32_t*)&t;
    t = __halves2bfloat162(l[0], l[1]); lp.x = *(uint32_t*)&t;
    t = __halves2bfloat162(l[2], l[3]); lp.y = *(uint32_t*)&t;
    *(uint2*)&xh[(size_t)row * CDIM + (tid << 2)] = hp;
    *(uint2*)&xl[(size_t)row * CDIM + (tid << 2)] = lp;
}

// ---------------------------------------------------------------------------
// HMMA bf16x3 GEMM:  C = A @ B^T   (A [M][K], B [N][K], bf16 hi/lo)
// CTA 128x128, BK=32, 256 threads; warp tile 32x64 (4m x 2n warps).
// 3-stage cp.async pipeline, ONE __syncthreads per chunk.
// EPI: 0=bias, 1=bias+gelu, 2=bias+fp32 residual, 3=bias+hi/lo residual+NCHW.
// WF: fp32 [M][Nc] out.  WH: bf16 hi/lo out.
// ---------------------------------------------------------------------------
constexpr int GT_TILE  = 128 * 32 * 2;
constexpr int GT_STAGE = 4 * GT_TILE;            // 32 KB
constexpr int GDSMEM   = 3 * GT_STAGE;           // 96 KB (3 stages)

__device__ __forceinline__ uint32_t sw_off(int row, int kc) {
    return (uint32_t)(row * 64 + ((kc ^ ((row >> 1) & 3)) << 4));
}

template <int EPI, int WF, int WH>
__global__ void __launch_bounds__(256, 2) hmma_gemm(
    const __nv_bfloat16* __restrict__ Ah, const __nv_bfloat16* __restrict__ Al,
    const __nv_bfloat16* __restrict__ Bh, const __nv_bfloat16* __restrict__ Bl,
    const float* __restrict__ bias, const float* __restrict__ resf,
    const __nv_bfloat16* __restrict__ resh,
    const __nv_bfloat16* __restrict__ resl,
    float* __restrict__ Cf, __nv_bfloat16* __restrict__ Ch,
    __nv_bfloat16* __restrict__ Cl, int K, int Nc) {
    extern __shared__ char smp[];
    const uint32_t sb = smem_u32(smp);
    const int tid  = threadIdx.x;
    const int wid  = tid >> 5, lane = tid & 31;
    const int row0 = blockIdx.y * 128, col0 = blockIdx.x * 128;
    const int wm   = (wid & 3) * 32;
    const int wn   = (wid >> 2) * 64;

    const int e0   = tid * 2;
    const int grow = e0 >> 2;
    const int gkc  = e0 & 3;
    const uint32_t so0 = sw_off(grow, gkc);
    const uint32_t so1 = sw_off(grow, gkc + 1);
    const __nv_bfloat16* gA_h = Ah + (size_t)(row0 + grow) * K + gkc * 8;
    const __nv_bfloat16* gA_l = Al + (size_t)(row0 + grow) * K + gkc * 8;
    const __nv_bfloat16* gB_h = Bh + (size_t)(col0 + grow) * K + gkc * 8;
    const __nv_bfloat16* gB_l = Bl + (size_t)(col0 + grow) * K + gkc * 8;

    const int a_moff = ((lane >> 3) & 1) * 8 + (lane & 7);
    const int a_k8   = lane >> 4;
    const int b_noff = (lane >> 4) * 8 + (lane & 7);
    const int b_k8   = (lane >> 3) & 1;
    uint32_t aRow64[2], aRsw[2];
    #pragma unroll
    for (int mt = 0; mt < 2; ++mt) {
        int r = wm + mt * 16 + a_moff;
        aRow64[mt] = r * 64;
        aRsw[mt]   = (r >> 1) & 3;
    }
    uint32_t bRow64[4], bRsw[4];
    #pragma unroll
    for (int ntp = 0; ntp < 4; ++ntp) {
        int r = wn + ntp * 16 + b_noff;
        bRow64[ntp] = r * 64;
        bRsw[ntp]   = (r >> 1) & 3;
    }

    float acc[2][8][4];
    #pragma unroll
    for (int i = 0; i < 2; ++i)
        #pragma unroll
        for (int j = 0; j < 8; ++j)
            #pragma unroll
            for (int p = 0; p < 4; ++p) acc[i][j][p] = 0.0f;

    const int NCH = K >> 5;

    auto issue = [&](int c) {
        const uint32_t stg = sb + (c % 3) * GT_STAGE;
        const int ko = c << 5;
        cp16(stg + 0 * GT_TILE + so0, gA_h + ko);
        cp16(stg + 0 * GT_TILE + so1, gA_h + ko + 8);
        cp16(stg + 1 * GT_TILE + so0, gA_l + ko);
        cp16(stg + 1 * GT_TILE + so1, gA_l + ko + 8);
        cp16(stg + 2 * GT_TILE + so0, gB_h + ko);
        cp16(stg + 2 * GT_TILE + so1, gB_h + ko + 8);
        cp16(stg + 3 * GT_TILE + so0, gB_l + ko);
        cp16(stg + 3 * GT_TILE + so1, gB_l + ko + 8);
        asm volatile("cp.async.commit_group;");
    };
    issue(0);
    if (NCH > 1) issue(1);

    for (int c = 0; c < NCH; ++c) {
        if (c + 1 < NCH)
            asm volatile("cp.async.wait_group 1;");
        else
            asm volatile("cp.async.wait_group 0;");
        __syncthreads();
        if (c + 2 < NCH) issue(c + 2);

        const uint32_t stg = (c % 3) * GT_STAGE;
        const uint32_t sAh = sb + stg;
        const uint32_t sAl = sAh + GT_TILE;
        const uint32_t sBh = sAl + GT_TILE;
        const uint32_t sBl = sBh + GT_TILE;
        #pragma unroll
        for (int kk = 0; kk < 2; ++kk) {
            uint32_t ah[2][4], al[2][4];
            #pragma unroll
            for (int mt = 0; mt < 2; ++mt) {
                const uint32_t ck = ((uint32_t)(kk * 2 + a_k8) ^ aRsw[mt]) << 4;
                ldm4(ah[mt], sAh + aRow64[mt] + ck);
                ldm4(al[mt], sAl + aRow64[mt] + ck);
            }
            #pragma unroll
            for (int ntp = 0; ntp < 4; ++ntp) {
                const uint32_t ck = ((uint32_t)(kk * 2 + b_k8) ^ bRsw[ntp]) << 4;
                uint32_t bh4[4], bl4[4];
                ldm4(bh4, sBh + bRow64[ntp] + ck);
                ldm4(bl4, sBl + bRow64[ntp] + ck);
                #pragma unroll
                for (int mt = 0; mt < 2; ++mt) {
                    mma_bf16(acc[mt][2 * ntp],     ah[mt], bh4);
                    mma_bf16(acc[mt][2 * ntp],     ah[mt], bl4);
                    mma_bf16(acc[mt][2 * ntp],     al[mt], bh4);
                    mma_bf16(acc[mt][2 * ntp + 1], ah[mt], bh4 + 2);
                    mma_bf16(acc[mt][2 * ntp + 1], ah[mt], bl4 + 2);
                    mma_bf16(acc[mt][2 * ntp + 1], al[mt], bh4 + 2);
                }
            }
        }
    }

    const int q  = lane >> 2;
    const int tc = lane & 3;
    #pragma unroll
    for (int mt = 0; mt < 2; ++mt) {
        #pragma unroll
        for (int nt = 0; nt < 8; ++nt) {
            float* cc = acc[mt][nt];
            const int col = col0 + wn + nt * 8 + tc * 2;
            const float2 bb = *(const float2*)&bias[col];
            #pragma unroll
            for (int hrow = 0; hrow < 2; ++hrow) {
                const size_t r = (size_t)(row0 + wm + mt * 16 + q + hrow * 8);
                float v0 = cc[2 * hrow + 0] + bb.x;
                float v1 = cc[2 * hrow + 1] + bb.y;
                if (EPI == 1) { v0 = gelu_exact(v0); v1 = gelu_exact(v1); }
                if (EPI == 2) {
                    float2 rv = *(const float2*)&resf[r * Nc + col];
                    v0 += rv.x; v1 += rv.y;
                }
                if (EPI == 3) {
                    uint32_t rh = *(const uint32_t*)&resh[r * Nc + col];
                    uint32_t rl = *(const uint32_t*)&resl[r * Nc + col];
                    float2 fh = __bfloat1622float2(*(__nv_bfloat162*)&rh);
                    float2 fl = __bfloat1622float2(*(__nv_bfloat162*)&rl);
                    v0 += fh.x + fl.x;
                    v1 += fh.y + fl.y;
                    // write fp32 NCHW directly: out[b][col][n]
                    const int bb_ = (int)r / NPOS;
                    const int nn_ = (int)r - bb_ * NPOS;
                    Cf[((size_t)(bb_ * CDIM + col)) * NPOS + nn_]     = v0;
                    Cf[((size_t)(bb_ * CDIM + col + 1)) * NPOS + nn_] = v1;
                } else if (WF) {
                    *(float2*)&Cf[r * Nc + col] = make_float2(v0, v1);
                }
                if (WH) {
                    __nv_bfloat16 h0, l0, h1, l1;
                    split_bf16(v0, h0, l0);
                    split_bf16(v1, h1, l1);
                    __nv_bfloat162 th = __halves2bfloat162(h0, h1);
                    __nv_bfloat162 tl = __halves2bfloat162(l0, l1);
                    *(uint32_t*)&Ch[r * Nc + col] = *(uint32_t*)&th;
                    *(uint32_t*)&Cl[r * Nc + col] = *(uint32_t*)&tl;
                }
            }
        }
    }
}

// ---------------------------------------------------------------------------
// MMA flash attention. CTA = (b, h, 112-q-tile); 7 warps x 16 rows.
// Q/K/V come from the merged QKV buffer (stride 1536; q@0, k@512, v@1024).
// ---------------------------------------------------------------------------
constexpr int AQT   = 112;
constexpr int ROWB  = 80;
constexpr int A_SQH = 0;
constexpr int A_SQL = A_SQH + AQT * ROWB;
constexpr int A_SKH = A_SQL + AQT * ROWB;
constexpr int A_SKL = A_SKH + AQT * ROWB;
constexpr int A_SVH = A_SKL + AQT * ROWB;
constexpr int A_SVL = A_SVH + AQT * ROWB;
constexpr int A_SBI = A_SVL + AQT * ROWB;
constexpr int A_BIW = 16 * 240;
constexpr int ATTN_SMEM = A_SBI + 7 * A_BIW;

__global__ void __launch_bounds__(224, 2) attn_mma(
    const __nv_bfloat16* __restrict__ qkvh,
    const __nv_bfloat16* __restrict__ qkvl,
    const __nv_bfloat16* __restrict__ biasb,
    __nv_bfloat16* __restrict__ atth, __nv_bfloat16* __restrict__ attl) {
    extern __shared__ char sm[];
    const uint32_t sb = smem_u32(sm);
    const int tid  = threadIdx.x;
    const int wid  = tid >> 5, lane = tid & 31;
    const int qt = blockIdx.x, h = blockIdx.y, b = blockIdx.z;
    const int n0 = qt * AQT;

    #pragma unroll
    for (int e = tid; e < 448; e += 224) {
        const int r = e >> 2, c = e & 3;
        const size_t g =
            (size_t)(b * NPOS + n0 + r) * QKVC + h * DHEAD + c * 8;
        *(uint4*)(sm + A_SQH + r * ROWB + c * 16) = *(const uint4*)(qkvh + g);
        *(uint4*)(sm + A_SQL + r * ROWB + c * 16) = *(const uint4*)(qkvl + g);
    }
    __syncthreads();

    const int am  = ((lane >> 3) & 1) * 8 + (lane & 7);
    const int ak8 = lane >> 4;
    uint32_t qfh[2][4], qfl[2][4];
    #pragma unroll
    for (int kk = 0; kk < 2; ++kk) {
        const uint32_t off = (wid * 16 + am) * ROWB + (kk * 2 + ak8) * 16;
        ldm4(qfh[kk], sb + A_SQH + off);
        ldm4(qfl[kk], sb + A_SQL + off);
    }

    const int bn  = (lane >> 4) * 8 + (lane & 7);
    const int bk8 = (lane >> 3) & 1;

    float m0 = -1e30f, m1 = -1e30f, l0 = 0.0f, l1 = 0.0f;
    float oa[4][4];
    #pragma unroll
    for (int j = 0; j < 4; ++j)
        #pragma unroll
        for (int p = 0; p < 4; ++p) oa[j][p] = 0.0f;

    const uint32_t sBiasW = sb + A_SBI + wid * A_BIW;

    for (int kt = 0; kt < 7; ++kt) {
        const int mp0 = kt * AQT;
        __syncthreads();
        #pragma unroll
        for (int e = tid; e < 448; e += 224) {
            const int r = e >> 2, c = e & 3;
            const size_t gk = (size_t)(b * NPOS + mp0 + r) * QKVC + CDIM +
                              h * DHEAD + c * 8;
            const size_t gv = gk + CDIM;
            const uint32_t so = r * ROWB + c * 16;
            *(uint4*)(sm + A_SKH + so) = *(const uint4*)(qkvh + gk);
            *(uint4*)(sm + A_SKL + so) = *(const uint4*)(qkvl + gk);
            *(uint4*)(sm + A_SVH + so) = *(const uint4*)(qkvh + gv);
            *(uint4*)(sm + A_SVL + so) = *(const uint4*)(qkvl + gv);
        }
        __syncthreads();

        #pragma unroll
        for (int e = lane; e < 224; e += 32) {
            const int r = e / 14, c = e % 14;
            *(uint4*)(sm + A_SBI + wid * A_BIW + r * 240 + c * 16) =
                *(const uint4*)(biasb + (size_t)h * NPOS * NPOS +
                                (size_t)(n0 + wid * 16 + r) * NPOS + mp0 +
                                c * 8);
        }
        __syncwarp();

        float sa[14][4];
        #pragma unroll
        for (int t = 0; t < 14; ++t)
            #pragma unroll
            for (int p = 0; p < 4; ++p) sa[t][p] = 0.0f;
        #pragma unroll
        for (int kk = 0; kk < 2; ++kk) {
            #pragma unroll
            for (int g = 0; g < 7; ++g) {
                const uint32_t off =
                    (g * 16 + bn) * ROWB + (kk * 2 + bk8) * 16;
                uint32_t kh4[4], kl4[4];
                ldm4(kh4, sb + A_SKH + off);
                ldm4(kl4, sb + A_SKL + off);
                mma_bf16(sa[2 * g],     qfh[kk], kh4);
                mma_bf16(sa[2 * g],     qfh[kk], kl4);
                mma_bf16(sa[2 * g],     qfl[kk], kh4);
                mma_bf16(sa[2 * g + 1], qfh[kk], kh4 + 2);
                mma_bf16(sa[2 * g + 1], qfh[kk], kl4 + 2);
                mma_bf16(sa[2 * g + 1], qfl[kk], kh4 + 2);
            }
        }

        #pragma unroll
        for (int c7 = 0; c7 < 7; ++c7) {
            uint32_t bb[4];
            ldm4(bb, sBiasW + am * 240 + c7 * 32 + ak8 * 16);
            float2 f0 = __bfloat1622float2(*(__nv_bfloat162*)&bb[0]);
            float2 f1 = __bfloat1622float2(*(__nv_bfloat162*)&bb[1]);
            float2 f2 = __bfloat1622float2(*(__nv_bfloat162*)&bb[2]);
            float2 f3 = __bfloat1622float2(*(__nv_bfloat162*)&bb[3]);
            sa[2 * c7][0] += f0.x;     sa[2 * c7][1] += f0.y;
            sa[2 * c7][2] += f1.x;     sa[2 * c7][3] += f1.y;
            sa[2 * c7 + 1][0] += f2.x; sa[2 * c7 + 1][1] += f2.y;
            sa[2 * c7 + 1][2] += f3.x; sa[2 * c7 + 1][3] += f3.y;
        }

        float mx0 = -1e30f, mx1 = -1e30f;
        #pragma unroll
        for (int t = 0; t < 14; ++t) {
            mx0 = fmaxf(mx0, fmaxf(sa[t][0], sa[t][1]));
            mx1 = fmaxf(mx1, fmaxf(sa[t][2], sa[t][3]));
        }
        mx0 = fmaxf(mx0, __shfl_xor_sync(0xffffffffu, mx0, 1));
        mx0 = fmaxf(mx0, __shfl_xor_sync(0xffffffffu, mx0, 2));
        mx1 = fmaxf(mx1, __shfl_xor_sync(0xffffffffu, mx1, 1));
        mx1 = fmaxf(mx1, __shfl_xor_sync(0xffffffffu, mx1, 2));
        const float nm0 = fmaxf(m0, mx0), nm1 = fmaxf(m1, mx1);
        const float f0 = __expf(m0 - nm0), f1 = __expf(m1 - nm1);
        m0 = nm0; m1 = nm1;
        float s0 = 0.0f, s1 = 0.0f;
        #pragma unroll
        for (int t = 0; t < 14; ++t) {
            sa[t][0] = __expf(sa[t][0] - m0);
            sa[t][1] = __expf(sa[t][1] - m0);
            sa[t][2] = __expf(sa[t][2] - m1);
            sa[t][3] = __expf(sa[t][3] - m1);
            s0 += sa[t][0] + sa[t][1];
            s1 += sa[t][2] + sa[t][3];
        }
        s0 += __shfl_xor_sync(0xffffffffu, s0, 1);
        s0 += __shfl_xor_sync(0xffffffffu, s0, 2);
        s1 += __shfl_xor_sync(0xffffffffu, s1, 1);
        s1 += __shfl_xor_sync(0xffffffffu, s1, 2);
        l0 = l0 * f0 + s0;
        l1 = l1 * f1 + s1;
        #pragma unroll
        for (int j = 0; j < 4; ++j) {
            oa[j][0] *= f0; oa[j][1] *= f0;
            oa[j][2] *= f1; oa[j][3] *= f1;
        }

        #pragma unroll
        for (int t = 0; t < 7; ++t) {
            uint32_t pa_h[4], pa_l[4];
            #pragma unroll
            for (int half = 0; half < 2; ++half) {
                const float* src = sa[2 * t + half];
                __nv_bfloat162 h01 = __floats2bfloat162_rn(src[0], src[1]);
                float2 r01 = __bfloat1622float2(h01);
                __nv_bfloat162 l01 =
                    __floats2bfloat162_rn(src[0] - r01.x, src[1] - r01.y);
                __nv_bfloat162 h23 = __floats2bfloat162_rn(src[2], src[3]);
                float2 r23 = __bfloat1622float2(h23);
                __nv_bfloat162 l23 =
                    __floats2bfloat162_rn(src[2] - r23.x, src[3] - r23.y);
                pa_h[2 * half]     = *(uint32_t*)&h01;
                pa_h[2 * half + 1] = *(uint32_t*)&h23;
                pa_l[2 * half]     = *(uint32_t*)&l01;
                pa_l[2 * half + 1] = *(uint32_t*)&l23;
            }
            #pragma unroll
            for (int v = 0; v < 2; ++v) {
                const uint32_t off =
                    (t * 16 + am) * ROWB + v * 32 + (lane >> 4) * 16;
                uint32_t vh4[4], vl4[4];
                ldm4t(vh4, sb + A_SVH + off);
                ldm4t(vl4, sb + A_SVL + off);
                mma_bf16(oa[2 * v],     pa_h, vh4);
                mma_bf16(oa[2 * v],     pa_h, vl4);
                mma_bf16(oa[2 * v],     pa_l, vh4);
                mma_bf16(oa[2 * v + 1], pa_h, vh4 + 2);
                mma_bf16(oa[2 * v + 1], pa_h, vl4 + 2);
                mma_bf16(oa[2 * v + 1], pa_l, vh4 + 2);
            }
        }
    }

    const float inv0 = 1.0f / l0, inv1 = 1.0f / l1;
    const int q  = lane >> 2, tc = lane & 3;
    const size_t r0 = (size_t)(b * NPOS + n0 + wid * 16 + q);
    const size_t r1 = r0 + 8;
    #pragma unroll
    for (int j = 0; j < 4; ++j) {
        const int col = h * DHEAD + j * 8 + tc * 2;
        float a0 = oa[j][0] * inv0, a1 = oa[j][1] * inv0;
        float b0 = oa[j][2] * inv1, b1 = oa[j][3] * inv1;
        __nv_bfloat16 h0, lo0, h1, lo1;
        split_bf16(a0, h0, lo0); split_bf16(a1, h1, lo1);
        __nv_bfloat162 th = __halves2bfloat162(h0, h1);
        __nv_bfloat162 tl = __halves2bfloat162(lo0, lo1);
        *(uint32_t*)&atth[r0 * CDIM + col] = *(uint32_t*)&th;
        *(uint32_t*)&attl[r0 * CDIM + col] = *(uint32_t*)&tl;
        split_bf16(b0, h0, lo0); split_bf16(b1, h1, lo1);
        th = __halves2bfloat162(h0, h1);
        tl = __halves2bfloat162(lo0, lo1);
        *(uint32_t*)&atth[r1 * CDIM + col] = *(uint32_t*)&th;
        *(uint32_t*)&attl[r1 * CDIM + col] = *(uint32_t*)&tl;
    }
}

// ---------------------------------------------------------------------------
// Launch
// ---------------------------------------------------------------------------
extern "C" void kernel_launch(void* const* d_in, const int* in_sizes, int n_in,
                              void* d_out, int out_size) {
    (void)in_sizes; (void)n_in; (void)out_size;
    const float* x      = (const float*)d_in[0];
    const float* ln_w   = (const float*)d_in[1];
    const float* ln_b   = (const float*)d_in[2];
    const float* Wq     = (const float*)d_in[3];
    const float* bq     = (const float*)d_in[4];
    const float* Wk     = (const float*)d_in[5];
    const float* bk     = (const float*)d_in[6];
    const float* Wv     = (const float*)d_in[7];
    const float* bv     = (const float*)d_in[8];
    const float* Wo     = (const float*)d_in[9];
    const float* bo     = (const float*)d_in[10];
    const float* relb   = (const float*)d_in[11];
    const float* W1     = (const float*)d_in[12];
    const float* b1     = (const float*)d_in[13];
    const float* W2     = (const float*)d_in[14];
    const float* b2     = (const float*)d_in[15];
    const int*   relidx = (const int*)d_in[16];
    float* out = (float*)d_out;

    auto sym = [](const void* s) {
        void* p = nullptr;
        cudaGetSymbolAddress(&p, s);
        return p;
    };
    float* xc   = (float*)sym(g_xc);
    float* bqkv = (float*)sym(g_bqkv);
    __nv_bfloat16* xnh   = (__nv_bfloat16*)sym(g_xnh);
    __nv_bfloat16* xnl   = (__nv_bfloat16*)sym(g_xnl);
    __nv_bfloat16* qkvh  = (__nv_bfloat16*)sym(g_qkvh);
    __nv_bfloat16* qkvl  = (__nv_bfloat16*)sym(g_qkvl);
    __nv_bfloat16* atth  = (__nv_bfloat16*)sym(g_atth);
    __nv_bfloat16* attl  = (__nv_bfloat16*)sym(g_attl);
    __nv_bfloat16* x1h   = (__nv_bfloat16*)sym(g_x1h);
    __nv_bfloat16* x1l   = (__nv_bfloat16*)sym(g_x1l);
    __nv_bfloat16* h1h   = (__nv_bfloat16*)sym(g_h1h);
    __nv_bfloat16* h1l   = (__nv_bfloat16*)sym(g_h1l);
    __nv_bfloat16* biasb = (__nv_bfloat16*)sym(g_biasb);
    __nv_bfloat16* wqkvh = (__nv_bfloat16*)sym(g_wqkvh);
    __nv_bfloat16* wqkvl = (__nv_bfloat16*)sym(g_wqkvl);
    __nv_bfloat16* woh = (__nv_bfloat16*)sym(g_woh), *wol = (__nv_bfloat16*)sym(g_wol);
    __nv_bfloat16* w1h = (__nv_bfloat16*)sym(g_w1h), *w1l = (__nv_bfloat16*)sym(g_w1l);
    __nv_bfloat16* w2h = (__nv_bfloat16*)sym(g_w2h), *w2l = (__nv_bfloat16*)sym(g_w2l);

    cudaFuncSetAttribute(attn_mma,
                         cudaFuncAttributeMaxDynamicSharedMemorySize, ATTN_SMEM);
    cudaFuncSetAttribute(hmma_gemm<0, 0, 1>,
                         cudaFuncAttributeMaxDynamicSharedMemorySize, GDSMEM);
    cudaFuncSetAttribute(hmma_gemm<2, 0, 1>,
                         cudaFuncAttributeMaxDynamicSharedMemorySize, GDSMEM);
    cudaFuncSetAttribute(hmma_gemm<1, 0, 1>,
                         cudaFuncAttributeMaxDynamicSharedMemorySize, GDSMEM);
    cudaFuncSetAttribute(hmma_gemm<3, 1, 0>,
                         cudaFuncAttributeMaxDynamicSharedMemorySize, GDSMEM);

    const dim3 tb(32, 8);
    const dim3 gqkv(QKVC / 128, MROWS / 128);   // (12, 98)
    const dim3 g512(CDIM / 128, MROWS / 128);   // (4, 98)
    const dim3 g2048(FFD / 128, MROWS / 128);   // (16, 98)

    // Launch order chosen so the QKV GEMM is the 6th launch (ncu -s 5 -c 1).
    // 1: fused QKV weight prep
    wqkv_prep_kernel<<<dim3(16, 16, 3), tb>>>(Wq, Wk, Wv, wqkvh, wqkvl);
    // 2: fused QKV bias
    bqkv_prep_kernel<<<1, CDIM>>>(bq, bk, bv, bqkv);
    // 3: NCHW -> (b, n, c)
    transpose_kernel<<<dim3(25, 16, BATCH), tb>>>(x, xc, CDIM, NPOS);
    // 4: LayerNorm -> bf16 hi/lo
    ln_kernel<<<MROWS, 128>>>(xc, ln_w, ln_b, xnh, xnl);
    // 5: attention bias table
    bias_prep_kernel<<<(NPOS * NPOS + 255) / 256, 256>>>(relb, relidx, biasb);
    // 6: fused QKV projection -> merged bf16 hi/lo [M][1536]  (PROFILED)
    hmma_gemm<0, 0, 1><<<gqkv, 256, GDSMEM>>>(xnh, xnl, wqkvh, wqkvl, bqkv,
                                              nullptr, nullptr, nullptr,
                                              nullptr, qkvh, qkvl, CDIM, QKVC);
    // 7: MMA flash attention -> bf16 hi/lo
    attn_mma<<<dim3(7, NHEADS, BATCH), 224, ATTN_SMEM>>>(qkvh, qkvl, biasb,
                                                         atth, attl);
    // 8-9: x1 = xc + att @ Wo + bo   (hi/lo only)
    wprep_kernel<<<dim3(16, 16), tb>>>(Wo, woh, wol, CDIM, CDIM);
    hmma_gemm<2, 0, 1><<<g512, 256, GDSMEM>>>(atth, attl, woh, wol, bo, xc,
                                              nullptr, nullptr, nullptr,
                                              x1h, x1l, CDIM, CDIM);
    // 10-11: h1 = gelu(x1 @ W1 + b1)   (hi/lo only)
    wprep_kernel<<<dim3(64, 16), tb>>>(W1, w1h, w1l, CDIM, FFD);
    hmma_gemm<1, 0, 1><<<g2048, 256, GDSMEM>>>(x1h, x1l, w1h, w1l, b1,
                                               nullptr, nullptr, nullptr,
                                               nullptr, h1h, h1l, CDIM, FFD);
    // 12-13: out(NCHW) = (x1h+x1l) + h1 @ W2 + b2  (fused final transpose)
    wprep_kernel<<<dim3(16, 64), tb>>>(W2, w2h, w2l, FFD, CDIM);
    hmma_gemm<3, 1, 0><<<g512, 256, GDSMEM>>>(h1h, h1l, w2h, w2l, b2,
                                              nullptr, x1h, x1l,
                                              out, nullptr, nullptr, FFD,
                                              CDIM);
}

// round 16
// speedup vs baseline: 3.9911x; 1.2861x over previous
#include <cuda_runtime.h>
#include <cuda_fp16.h>
#include <math.h>
#include <stdint.h>

// ---------------------------------------------------------------------------
// Problem constants
// ---------------------------------------------------------------------------
constexpr int BATCH  = 16;
constexpr int NPOS   = 784;          // 28*28
constexpr int CDIM   = 512;
constexpr int NHEADS = 16;
constexpr int DHEAD  = 32;
constexpr int FFD    = 2048;
constexpr int NREL   = 1596;
constexpr int MROWS  = BATCH * NPOS; // 12544
constexpr int QKVC   = 3 * CDIM;     // 1536

constexpr size_t SZ_NC = (size_t)MROWS * CDIM;
constexpr size_t SZ_Q3 = (size_t)MROWS * QKVC;
constexpr size_t SZ_FF = (size_t)MROWS * FFD;
constexpr size_t SZ_BI = (size_t)NHEADS * NPOS * NPOS;

// ---------------------------------------------------------------------------
// Global scratch (static __device__ arrays — no allocation)
// ---------------------------------------------------------------------------
__device__ float g_xc[SZ_NC];
__device__ float g_bqkv[QKVC];

__device__ __half g_xnh[SZ_NC],   g_xnl[SZ_NC];
__device__ __half g_qkvh[SZ_Q3],  g_qkvl[SZ_Q3];
__device__ __half g_atth[SZ_NC],  g_attl[SZ_NC];
__device__ __half g_x1h[SZ_NC],   g_x1l[SZ_NC];
__device__ __half g_h1h[SZ_FF],   g_h1l[SZ_FF];
__device__ __half g_biasb[SZ_BI];

// weights: single fp16 copy (correction carried on the activation side)
__device__ __half g_wqkvh[(size_t)QKVC*CDIM];
__device__ __half g_woh[CDIM*CDIM];
__device__ __half g_w1h[(size_t)CDIM*FFD];
__device__ __half g_w2h[(size_t)FFD*CDIM];

// ---------------------------------------------------------------------------
// Helpers
// ---------------------------------------------------------------------------
__device__ __forceinline__ uint32_t smem_u32(const void* p) {
    uint32_t a;
    asm("{ .reg .u64 t; cvta.to.shared.u64 t, %1; cvt.u32.u64 %0, t; }"
        : "=r"(a) : "l"(p));
    return a;
}
__device__ __forceinline__ float gelu_exact(float x) {
    return 0.5f * x * (1.0f + erff(x * 0.7071067811865476f));
}
__device__ __forceinline__ void split_f16(float a, __half& h, __half& l) {
    h = __float2half_rn(a);
    l = __float2half_rn(a - __half2float(h));
}
__device__ __forceinline__ void ldm4(uint32_t* r, uint32_t addr) {
    asm volatile(
        "ldmatrix.sync.aligned.m8n8.x4.shared.b16 {%0,%1,%2,%3}, [%4];"
        : "=r"(r[0]), "=r"(r[1]), "=r"(r[2]), "=r"(r[3]) : "r"(addr)
        : "memory");
}
__device__ __forceinline__ void ldm4t(uint32_t* r, uint32_t addr) {
    asm volatile(
        "ldmatrix.sync.aligned.m8n8.x4.trans.shared.b16 {%0,%1,%2,%3}, [%4];"
        : "=r"(r[0]), "=r"(r[1]), "=r"(r[2]), "=r"(r[3]) : "r"(addr)
        : "memory");
}
__device__ __forceinline__ void mma_f16(float* c, const uint32_t* a,
                                        const uint32_t* b) {
    asm volatile(
        "mma.sync.aligned.m16n8k16.row.col.f32.f16.f16.f32 "
        "{%0,%1,%2,%3},{%4,%5,%6,%7},{%8,%9},{%0,%1,%2,%3};"
        : "+f"(c[0]), "+f"(c[1]), "+f"(c[2]), "+f"(c[3])
        : "r"(a[0]), "r"(a[1]), "r"(a[2]), "r"(a[3]), "r"(b[0]), "r"(b[1]));
}
__device__ __forceinline__ void cp16(uint32_t dst, const void* src) {
    asm volatile("cp.async.cg.shared.global [%0], [%1], 16;"
                 :: "r"(dst), "l"(src));
}

// ---------------------------------------------------------------------------
// Tiled 2D transpose per batch:  src [R][Cc]  ->  dst [Cc][R]
// ---------------------------------------------------------------------------
__global__ void transpose_kernel(const float* __restrict__ in,
                                 float* __restrict__ out, int R, int Cc) {
    __shared__ float tile[32][33];
    const int b = blockIdx.z;
    const float* src = in  + (size_t)b * R * Cc;
    float*       dst = out + (size_t)b * R * Cc;
    const int c0 = blockIdx.x * 32;
    const int r0 = blockIdx.y * 32;
    const int tx = threadIdx.x, ty = threadIdx.y;
    #pragma unroll
    for (int j = 0; j < 32; j += 8) {
        int r = r0 + ty + j, c = c0 + tx;
        if (r < R && c < Cc) tile[ty + j][tx] = src[(size_t)r * Cc + c];
    }
    __syncthreads();
    #pragma unroll
    for (int j = 0; j < 32; j += 8) {
        int oc = c0 + ty + j, orr = r0 + tx;
        if (oc < Cc && orr < R) dst[(size_t)oc * R + orr] = tile[tx][ty + j];
    }
}

// ---------------------------------------------------------------------------
// Weight prep: W[K][N] fp32  ->  Bh [N][K] fp16 (single copy)
// ---------------------------------------------------------------------------
__global__ void wprep_kernel(const float* __restrict__ W,
                             __half* __restrict__ Bh, int K, int N) {
    __shared__ float t[32][33];
    const int n0 = blockIdx.x * 32, k0 = blockIdx.y * 32;
    const int tx = threadIdx.x, ty = threadIdx.y;
    #pragma unroll
    for (int j = 0; j < 32; j += 8)
        t[ty + j][tx] = W[(size_t)(k0 + ty + j) * N + n0 + tx];
    __syncthreads();
    #pragma unroll
    for (int j = 0; j < 32; j += 8)
        Bh[(size_t)(n0 + ty + j) * K + k0 + tx] = __float2half_rn(t[tx][ty + j]);
}

// Fused QKV weight prep: z = 0/1/2 selects Wq/Wk/Wv, stacked along N.
__global__ void wqkv_prep_kernel(const float* __restrict__ Wq,
                                 const float* __restrict__ Wk,
                                 const float* __restrict__ Wv,
                                 __half* __restrict__ Bh) {
    __shared__ float t[32][33];
    const int z = blockIdx.z;
    const float* W = (z == 0) ? Wq : ((z == 1) ? Wk : Wv);
    const size_t off = (size_t)z * CDIM * CDIM;
    const int n0 = blockIdx.x * 32, k0 = blockIdx.y * 32;
    const int tx = threadIdx.x, ty = threadIdx.y;
    #pragma unroll
    for (int j = 0; j < 32; j += 8)
        t[ty + j][tx] = W[(size_t)(k0 + ty + j) * CDIM + n0 + tx];
    __syncthreads();
    #pragma unroll
    for (int j = 0; j < 32; j += 8)
        Bh[off + (size_t)(n0 + ty + j) * CDIM + k0 + tx] =
            __float2half_rn(t[tx][ty + j]);
}

// ---------------------------------------------------------------------------
// Bias preps
// ---------------------------------------------------------------------------
__global__ void bias_prep_kernel(const float* __restrict__ rel_bias,
                                 const int* __restrict__ rel_idx,
                                 __half* __restrict__ biasb) {
    const int idx = blockIdx.x * 256 + threadIdx.x;
    if (idx >= NPOS * NPOS) return;
    const int ri = rel_idx[idx];
    #pragma unroll
    for (int h = 0; h < NHEADS; ++h)
        biasb[(size_t)h * NPOS * NPOS + idx] =
            __float2half_rn(rel_bias[h * NREL + ri]);
}
__global__ void bqkv_prep_kernel(const float* __restrict__ bq,
                                 const float* __restrict__ bk,
                                 const float* __restrict__ bv,
                                 float* __restrict__ dst) {
    const int t = threadIdx.x;
    dst[t] = bq[t];
    dst[CDIM + t] = bk[t];
    dst[2 * CDIM + t] = bv[t];
}

// ---------------------------------------------------------------------------
// LayerNorm over C=512, one block (128 threads) per row; emits fp16 hi/lo
// ---------------------------------------------------------------------------
__global__ void __launch_bounds__(128) ln_kernel(const float* __restrict__ xc,
                                                 const float* __restrict__ w,
                                                 const float* __restrict__ bsh,
                                                 __half* __restrict__ xh,
                                                 __half* __restrict__ xl) {
    const int row = blockIdx.x;
    const int tid = threadIdx.x;
    const float* xr = xc + (size_t)row * CDIM;
    float4 v = *(const float4*)&xr[tid << 2];
    float s  = v.x + v.y + v.z + v.w;
    float ss = v.x * v.x + v.y * v.y + v.z * v.z + v.w * v.w;
    #pragma unroll
    for (int o = 16; o; o >>= 1) {
        s  += __shfl_xor_sync(0xffffffffu, s, o);
        ss += __shfl_xor_sync(0xffffffffu, ss, o);
    }
    __shared__ float rs[4], rss[4];
    const int warp = tid >> 5, lane = tid & 31;
    if (lane == 0) { rs[warp] = s; rss[warp] = ss; }
    __syncthreads();
    if (tid == 0) {
        float S  = rs[0] + rs[1] + rs[2] + rs[3];
        float SS = rss[0] + rss[1] + rss[2] + rss[3];
        float mu  = S * (1.0f / CDIM);
        float var = SS * (1.0f / CDIM) - mu * mu;
        rs[0]  = mu;
        rss[0] = rsqrtf(var + 1e-5f);
    }
    __syncthreads();
    const float mu = rs[0], rstd = rss[0];
    float4 wv = *(const float4*)&w[tid << 2];
    float4 bv = *(const float4*)&bsh[tid << 2];
    float o[4];
    o[0] = (v.x - mu) * rstd * wv.x + bv.x;
    o[1] = (v.y - mu) * rstd * wv.y + bv.y;
    o[2] = (v.z - mu) * rstd * wv.z + bv.z;
    o[3] = (v.w - mu) * rstd * wv.w + bv.w;
    __half h[4], l[4];
    #pragma unroll
    for (int i = 0; i < 4; ++i) split_f16(o[i], h[i], l[i]);
    uint2 hp, lp;
    __half2 t;
    t = __halves2half2(h[0], h[1]); hp.x = *(uint32_t*)&t;
    t = __halves2half2(h[2], h[3]); hp.y = *(uint32_t*)&t;
    t = __halves2half2(l[0], l[1]); lp.x = *(uint32_t*)&t;
    t = __halves2half2(l[2], l[3]); lp.y = *(uint32_t*)&t;
    *(uint2*)&xh[(size_t)row * CDIM + (tid << 2)] = hp;
    *(uint2*)&xl[(size_t)row * CDIM + (tid << 2)] = lp;
}

// ---------------------------------------------------------------------------
// HMMA fp16x2 GEMM:  C = A @ B^T   (A [M][K] fp16 hi/lo, B [N][K] fp16)
// C = Ah.B + Al.B  — B rounding error ~2^-12 rms, inside budget.
// CTA 128x128, BK=32, 256 threads; warp tile 32x64 (4m x 2n warps).
// 3-stage cp.async pipeline (3 tiles/stage: Ah, Al, Bh = 24 KB).
// EPI: 0=bias, 1=bias+gelu, 2=bias (res unused), 3=bias+hi/lo residual+NCHW.
// WF: fp32 [M][Nc] out.  WH: fp16 hi/lo out.
// ---------------------------------------------------------------------------
constexpr int GT_TILE  = 128 * 32 * 2;           // 8 KB
constexpr int GT_STAGE = 3 * GT_TILE;            // 24 KB
constexpr int GDSMEM   = 3 * GT_STAGE;           // 72 KB (3 stages)

__device__ __forceinline__ uint32_t sw_off(int row, int kc) {
    return (uint32_t)(row * 64 + ((kc ^ ((row >> 1) & 3)) << 4));
}

template <int EPI, int WF, int WH>
__global__ void __launch_bounds__(256, 2) hmma_gemm(
    const __half* __restrict__ Ah, const __half* __restrict__ Al,
    const __half* __restrict__ Bh,
    const float* __restrict__ bias, const float* __restrict__ resf,
    const __half* __restrict__ resh, const __half* __restrict__ resl,
    float* __restrict__ Cf, __half* __restrict__ Ch,
    __half* __restrict__ Cl, int K, int Nc) {
    extern __shared__ char smp[];
    const uint32_t sb = smem_u32(smp);
    const int tid  = threadIdx.x;
    const int wid  = tid >> 5, lane = tid & 31;
    const int row0 = blockIdx.y * 128, col0 = blockIdx.x * 128;
    const int wm   = (wid & 3) * 32;
    const int wn   = (wid >> 2) * 64;

    const int e0   = tid * 2;
    const int grow = e0 >> 2;
    const int gkc  = e0 & 3;
    const uint32_t so0 = sw_off(grow, gkc);
    const uint32_t so1 = sw_off(grow, gkc + 1);
    const __half* gA_h = Ah + (size_t)(row0 + grow) * K + gkc * 8;
    const __half* gA_l = Al + (size_t)(row0 + grow) * K + gkc * 8;
    const __half* gB_h = Bh + (size_t)(col0 + grow) * K + gkc * 8;

    const int a_moff = ((lane >> 3) & 1) * 8 + (lane & 7);
    const int a_k8   = lane >> 4;
    const int b_noff = (lane >> 4) * 8 + (lane & 7);
    const int b_k8   = (lane >> 3) & 1;
    uint32_t aRow64[2], aRsw[2];
    #pragma unroll
    for (int mt = 0; mt < 2; ++mt) {
        int r = wm + mt * 16 + a_moff;
        aRow64[mt] = r * 64;
        aRsw[mt]   = (r >> 1) & 3;
    }
    uint32_t bRow64[4], bRsw[4];
    #pragma unroll
    for (int ntp = 0; ntp < 4; ++ntp) {
        int r = wn + ntp * 16 + b_noff;
        bRow64[ntp] = r * 64;
        bRsw[ntp]   = (r >> 1) & 3;
    }

    float acc[2][8][4];
    #pragma unroll
    for (int i = 0; i < 2; ++i)
        #pragma unroll
        for (int j = 0; j < 8; ++j)
            #pragma unroll
            for (int p = 0; p < 4; ++p) acc[i][j][p] = 0.0f;

    const int NCH = K >> 5;

    auto issue = [&](int c) {
        const uint32_t stg = sb + (c % 3) * GT_STAGE;
        const int ko = c << 5;
        cp16(stg + 0 * GT_TILE + so0, gA_h + ko);
        cp16(stg + 0 * GT_TILE + so1, gA_h + ko + 8);
        cp16(stg + 1 * GT_TILE + so0, gA_l + ko);
        cp16(stg + 1 * GT_TILE + so1, gA_l + ko + 8);
        cp16(stg + 2 * GT_TILE + so0, gB_h + ko);
        cp16(stg + 2 * GT_TILE + so1, gB_h + ko + 8);
        asm volatile("cp.async.commit_group;");
    };
    issue(0);
    if (NCH > 1) issue(1);

    for (int c = 0; c < NCH; ++c) {
        if (c + 1 < NCH)
            asm volatile("cp.async.wait_group 1;");
        else
            asm volatile("cp.async.wait_group 0;");
        __syncthreads();
        if (c + 2 < NCH) issue(c + 2);

        const uint32_t stg = (c % 3) * GT_STAGE;
        const uint32_t sAh = sb + stg;
        const uint32_t sAl = sAh + GT_TILE;
        const uint32_t sBh = sAl + GT_TILE;
        #pragma unroll
        for (int kk = 0; kk < 2; ++kk) {
            uint32_t ah[2][4], al[2][4];
            #pragma unroll
            for (int mt = 0; mt < 2; ++mt) {
                const uint32_t ck = ((uint32_t)(kk * 2 + a_k8) ^ aRsw[mt]) << 4;
                ldm4(ah[mt], sAh + aRow64[mt] + ck);
                ldm4(al[mt], sAl + aRow64[mt] + ck);
            }
            #pragma unroll
            for (int ntp = 0; ntp < 4; ++ntp) {
                const uint32_t ck = ((uint32_t)(kk * 2 + b_k8) ^ bRsw[ntp]) << 4;
                uint32_t bh4[4];
                ldm4(bh4, sBh + bRow64[ntp] + ck);
                #pragma unroll
                for (int mt = 0; mt < 2; ++mt) {
                    mma_f16(acc[mt][2 * ntp],     ah[mt], bh4);
                    mma_f16(acc[mt][2 * ntp],     al[mt], bh4);
                    mma_f16(acc[mt][2 * ntp + 1], ah[mt], bh4 + 2);
                    mma_f16(acc[mt][2 * ntp + 1], al[mt], bh4 + 2);
                }
            }
        }
    }

    const int q  = lane >> 2;
    const int tc = lane & 3;
    #pragma unroll
    for (int mt = 0; mt < 2; ++mt) {
        #pragma unroll
        for (int nt = 0; nt < 8; ++nt) {
            float* cc = acc[mt][nt];
            const int col = col0 + wn + nt * 8 + tc * 2;
            const float2 bb = *(const float2*)&bias[col];
            #pragma unroll
            for (int hrow = 0; hrow < 2; ++hrow) {
                const size_t r = (size_t)(row0 + wm + mt * 16 + q + hrow * 8);
                float v0 = cc[2 * hrow + 0] + bb.x;
                float v1 = cc[2 * hrow + 1] + bb.y;
                if (EPI == 1) { v0 = gelu_exact(v0); v1 = gelu_exact(v1); }
                if (EPI == 2) {
                    float2 rv = *(const float2*)&resf[r * Nc + col];
                    v0 += rv.x; v1 += rv.y;
                }
                if (EPI == 3) {
                    uint32_t rh = *(const uint32_t*)&resh[r * Nc + col];
                    uint32_t rl = *(const uint32_t*)&resl[r * Nc + col];
                    float2 fh = __half22float2(*(__half2*)&rh);
                    float2 fl = __half22float2(*(__half2*)&rl);
                    v0 += fh.x + fl.x;
                    v1 += fh.y + fl.y;
                    // write fp32 NCHW directly: out[b][col][n]
                    const int bb_ = (int)r / NPOS;
                    const int nn_ = (int)r - bb_ * NPOS;
                    Cf[((size_t)(bb_ * CDIM + col)) * NPOS + nn_]     = v0;
                    Cf[((size_t)(bb_ * CDIM + col + 1)) * NPOS + nn_] = v1;
                } else if (WF) {
                    *(float2*)&Cf[r * Nc + col] = make_float2(v0, v1);
                }
                if (WH) {
                    __half h0, l0, h1, l1;
                    split_f16(v0, h0, l0);
                    split_f16(v1, h1, l1);
                    __half2 th = __halves2half2(h0, h1);
                    __half2 tl = __halves2half2(l0, l1);
                    *(uint32_t*)&Ch[r * Nc + col] = *(uint32_t*)&th;
                    *(uint32_t*)&Cl[r * Nc + col] = *(uint32_t*)&tl;
                }
            }
        }
    }
}

// ---------------------------------------------------------------------------
// MMA flash attention (fp16 3-term: err ~2^-22). CTA = (b, h, 112-q tile).
// Q/K/V from merged QKV buffer (stride 1536; q@0, k@512, v@1024).
// ---------------------------------------------------------------------------
constexpr int AQT   = 112;
constexpr int ROWB  = 80;
constexpr int A_SQH = 0;
constexpr int A_SQL = A_SQH + AQT * ROWB;
constexpr int A_SKH = A_SQL + AQT * ROWB;
constexpr int A_SKL = A_SKH + AQT * ROWB;
constexpr int A_SVH = A_SKL + AQT * ROWB;
constexpr int A_SVL = A_SVH + AQT * ROWB;
constexpr int A_SBI = A_SVL + AQT * ROWB;
constexpr int A_BIW = 16 * 240;
constexpr int ATTN_SMEM = A_SBI + 7 * A_BIW;

__global__ void __launch_bounds__(224, 2) attn_mma(
    const __half* __restrict__ qkvh, const __half* __restrict__ qkvl,
    const __half* __restrict__ biasb,
    __half* __restrict__ atth, __half* __restrict__ attl) {
    extern __shared__ char sm[];
    const uint32_t sb = smem_u32(sm);
    const int tid  = threadIdx.x;
    const int wid  = tid >> 5, lane = tid & 31;
    const int qt = blockIdx.x, h = blockIdx.y, b = blockIdx.z;
    const int n0 = qt * AQT;

    #pragma unroll
    for (int e = tid; e < 448; e += 224) {
        const int r = e >> 2, c = e & 3;
        const size_t g =
            (size_t)(b * NPOS + n0 + r) * QKVC + h * DHEAD + c * 8;
        *(uint4*)(sm + A_SQH + r * ROWB + c * 16) = *(const uint4*)(qkvh + g);
        *(uint4*)(sm + A_SQL + r * ROWB + c * 16) = *(const uint4*)(qkvl + g);
    }
    __syncthreads();

    const int am  = ((lane >> 3) & 1) * 8 + (lane & 7);
    const int ak8 = lane >> 4;
    uint32_t qfh[2][4], qfl[2][4];
    #pragma unroll
    for (int kk = 0; kk < 2; ++kk) {
        const uint32_t off = (wid * 16 + am) * ROWB + (kk * 2 + ak8) * 16;
        ldm4(qfh[kk], sb + A_SQH + off);
        ldm4(qfl[kk], sb + A_SQL + off);
    }

    const int bn  = (lane >> 4) * 8 + (lane & 7);
    const int bk8 = (lane >> 3) & 1;

    float m0 = -1e30f, m1 = -1e30f, l0 = 0.0f, l1 = 0.0f;
    float oa[4][4];
    #pragma unroll
    for (int j = 0; j < 4; ++j)
        #pragma unroll
        for (int p = 0; p < 4; ++p) oa[j][p] = 0.0f;

    const uint32_t sBiasW = sb + A_SBI + wid * A_BIW;

    for (int kt = 0; kt < 7; ++kt) {
        const int mp0 = kt * AQT;
        __syncthreads();
        #pragma unroll
        for (int e = tid; e < 448; e += 224) {
            const int r = e >> 2, c = e & 3;
            const size_t gk = (size_t)(b * NPOS + mp0 + r) * QKVC + CDIM +
                              h * DHEAD + c * 8;
            const size_t gv = gk + CDIM;
            const uint32_t so = r * ROWB + c * 16;
            *(uint4*)(sm + A_SKH + so) = *(const uint4*)(qkvh + gk);
            *(uint4*)(sm + A_SKL + so) = *(const uint4*)(qkvl + gk);
            *(uint4*)(sm + A_SVH + so) = *(const uint4*)(qkvh + gv);
            *(uint4*)(sm + A_SVL + so) = *(const uint4*)(qkvl + gv);
        }
        __syncthreads();

        #pragma unroll
        for (int e = lane; e < 224; e += 32) {
            const int r = e / 14, c = e % 14;
            *(uint4*)(sm + A_SBI + wid * A_BIW + r * 240 + c * 16) =
                *(const uint4*)(biasb + (size_t)h * NPOS * NPOS +
                                (size_t)(n0 + wid * 16 + r) * NPOS + mp0 +
                                c * 8);
        }
        __syncwarp();

        float sa[14][4];
        #pragma unroll
        for (int t = 0; t < 14; ++t)
            #pragma unroll
            for (int p = 0; p < 4; ++p) sa[t][p] = 0.0f;
        #pragma unroll
        for (int kk = 0; kk < 2; ++kk) {
            #pragma unroll
            for (int g = 0; g < 7; ++g) {
                const uint32_t off =
                    (g * 16 + bn) * ROWB + (kk * 2 + bk8) * 16;
                uint32_t kh4[4], kl4[4];
                ldm4(kh4, sb + A_SKH + off);
                ldm4(kl4, sb + A_SKL + off);
                mma_f16(sa[2 * g],     qfh[kk], kh4);
                mma_f16(sa[2 * g],     qfh[kk], kl4);
                mma_f16(sa[2 * g],     qfl[kk], kh4);
                mma_f16(sa[2 * g + 1], qfh[kk], kh4 + 2);
                mma_f16(sa[2 * g + 1], qfh[kk], kl4 + 2);
                mma_f16(sa[2 * g + 1], qfl[kk], kh4 + 2);
            }
        }

        #pragma unroll
        for (int c7 = 0; c7 < 7; ++c7) {
            uint32_t bb[4];
            ldm4(bb, sBiasW + am * 240 + c7 * 32 + ak8 * 16);
            float2 f0 = __half22float2(*(__half2*)&bb[0]);
            float2 f1 = __half22float2(*(__half2*)&bb[1]);
            float2 f2 = __half22float2(*(__half2*)&bb[2]);
            float2 f3 = __half22float2(*(__half2*)&bb[3]);
            sa[2 * c7][0] += f0.x;     sa[2 * c7][1] += f0.y;
            sa[2 * c7][2] += f1.x;     sa[2 * c7][3] += f1.y;
            sa[2 * c7 + 1][0] += f2.x; sa[2 * c7 + 1][1] += f2.y;
            sa[2 * c7 + 1][2] += f3.x; sa[2 * c7 + 1][3] += f3.y;
        }

        float mx0 = -1e30f, mx1 = -1e30f;
        #pragma unroll
        for (int t = 0; t < 14; ++t) {
            mx0 = fmaxf(mx0, fmaxf(sa[t][0], sa[t][1]));
            mx1 = fmaxf(mx1, fmaxf(sa[t][2], sa[t][3]));
        }
        mx0 = fmaxf(mx0, __shfl_xor_sync(0xffffffffu, mx0, 1));
        mx0 = fmaxf(mx0, __shfl_xor_sync(0xffffffffu, mx0, 2));
        mx1 = fmaxf(mx1, __shfl_xor_sync(0xffffffffu, mx1, 1));
        mx1 = fmaxf(mx1, __shfl_xor_sync(0xffffffffu, mx1, 2));
        const float nm0 = fmaxf(m0, mx0), nm1 = fmaxf(m1, mx1);
        const float f0 = __expf(m0 - nm0), f1 = __expf(m1 - nm1);
        m0 = nm0; m1 = nm1;
        float s0 = 0.0f, s1 = 0.0f;
        #pragma unroll
        for (int t = 0; t < 14; ++t) {
            sa[t][0] = __expf(sa[t][0] - m0);
            sa[t][1] = __expf(sa[t][1] - m0);
            sa[t][2] = __expf(sa[t][2] - m1);
            sa[t][3] = __expf(sa[t][3] - m1);
            s0 += sa[t][0] + sa[t][1];
            s1 += sa[t][2] + sa[t][3];
        }
        s0 += __shfl_xor_sync(0xffffffffu, s0, 1);
        s0 += __shfl_xor_sync(0xffffffffu, s0, 2);
        s1 += __shfl_xor_sync(0xffffffffu, s1, 1);
        s1 += __shfl_xor_sync(0xffffffffu, s1, 2);
        l0 = l0 * f0 + s0;
        l1 = l1 * f1 + s1;
        #pragma unroll
        for (int j = 0; j < 4; ++j) {
            oa[j][0] *= f0; oa[j][1] *= f0;
            oa[j][2] *= f1; oa[j][3] *= f1;
        }

        #pragma unroll
        for (int t = 0; t < 7; ++t) {
            uint32_t pa_h[4], pa_l[4];
            #pragma unroll
            for (int half = 0; half < 2; ++half) {
                const float* src = sa[2 * t + half];
                __half2 h01 = __floats2half2_rn(src[0], src[1]);
                float2 r01 = __half22float2(h01);
                __half2 l01 =
                    __floats2half2_rn(src[0] - r01.x, src[1] - r01.y);
                __half2 h23 = __floats2half2_rn(src[2], src[3]);
                float2 r23 = __half22float2(h23);
                __half2 l23 =
                    __floats2half2_rn(src[2] - r23.x, src[3] - r23.y);
                pa_h[2 * half]     = *(uint32_t*)&h01;
                pa_h[2 * half + 1] = *(uint32_t*)&h23;
                pa_l[2 * half]     = *(uint32_t*)&l01;
                pa_l[2 * half + 1] = *(uint32_t*)&l23;
            }
            #pragma unroll
            for (int v = 0; v < 2; ++v) {
                const uint32_t off =
                    (t * 16 + am) * ROWB + v * 32 + (lane >> 4) * 16;
                uint32_t vh4[4], vl4[4];
                ldm4t(vh4, sb + A_SVH + off);
                ldm4t(vl4, sb + A_SVL + off);
                mma_f16(oa[2 * v],     pa_h, vh4);
                mma_f16(oa[2 * v],     pa_h, vl4);
                mma_f16(oa[2 * v],     pa_l, vh4);
                mma_f16(oa[2 * v + 1], pa_h, vh4 + 2);
                mma_f16(oa[2 * v + 1], pa_h, vl4 + 2);
                mma_f16(oa[2 * v + 1], pa_l, vh4 + 2);
            }
        }
    }

    const float inv0 = 1.0f / l0, inv1 = 1.0f / l1;
    const int q  = lane >> 2, tc = lane & 3;
    const size_t r0 = (size_t)(b * NPOS + n0 + wid * 16 + q);
    const size_t r1 = r0 + 8;
    #pragma unroll
    for (int j = 0; j < 4; ++j) {
        const int col = h * DHEAD + j * 8 + tc * 2;
        float a0 = oa[j][0] * inv0, a1 = oa[j][1] * inv0;
        float b0 = oa[j][2] * inv1, b1 = oa[j][3] * inv1;
        __half h0, lo0, h1, lo1;
        split_f16(a0, h0, lo0); split_f16(a1, h1, lo1);
        __half2 th = __halves2half2(h0, h1);
        __half2 tl = __halves2half2(lo0, lo1);
        *(uint32_t*)&atth[r0 * CDIM + col] = *(uint32_t*)&th;
        *(uint32_t*)&attl[r0 * CDIM + col] = *(uint32_t*)&tl;
        split_f16(b0, h0, lo0); split_f16(b1, h1, lo1);
        th = __halves2half2(h0, h1);
        tl = __halves2half2(lo0, lo1);
        *(uint32_t*)&atth[r1 * CDIM + col] = *(uint32_t*)&th;
        *(uint32_t*)&attl[r1 * CDIM + col] = *(uint32_t*)&tl;
    }
}

// ---------------------------------------------------------------------------
// Launch
// ---------------------------------------------------------------------------
extern "C" void kernel_launch(void* const* d_in, const int* in_sizes, int n_in,
                              void* d_out, int out_size) {
    (void)in_sizes; (void)n_in; (void)out_size;
    const float* x      = (const float*)d_in[0];
    const float* ln_w   = (const float*)d_in[1];
    const float* ln_b   = (const float*)d_in[2];
    const float* Wq     = (const float*)d_in[3];
    const float* bq     = (const float*)d_in[4];
    const float* Wk     = (const float*)d_in[5];
    const float* bk     = (const float*)d_in[6];
    const float* Wv     = (const float*)d_in[7];
    const float* bv     = (const float*)d_in[8];
    const float* Wo     = (const float*)d_in[9];
    const float* bo     = (const float*)d_in[10];
    const float* relb   = (const float*)d_in[11];
    const float* W1     = (const float*)d_in[12];
    const float* b1     = (const float*)d_in[13];
    const float* W2     = (const float*)d_in[14];
    const float* b2     = (const float*)d_in[15];
    const int*   relidx = (const int*)d_in[16];
    float* out = (float*)d_out;

    auto sym = [](const void* s) {
        void* p = nullptr;
        cudaGetSymbolAddress(&p, s);
        return p;
    };
    float* xc   = (float*)sym(g_xc);
    float* bqkv = (float*)sym(g_bqkv);
    __half* xnh   = (__half*)sym(g_xnh);
    __half* xnl   = (__half*)sym(g_xnl);
    __half* qkvh  = (__half*)sym(g_qkvh);
    __half* qkvl  = (__half*)sym(g_qkvl);
    __half* atth  = (__half*)sym(g_atth);
    __half* attl  = (__half*)sym(g_attl);
    __half* x1h   = (__half*)sym(g_x1h);
    __half* x1l   = (__half*)sym(g_x1l);
    __half* h1h   = (__half*)sym(g_h1h);
    __half* h1l   = (__half*)sym(g_h1l);
    __half* biasb = (__half*)sym(g_biasb);
    __half* wqkvh = (__half*)sym(g_wqkvh);
    __half* woh   = (__half*)sym(g_woh);
    __half* w1h   = (__half*)sym(g_w1h);
    __half* w2h   = (__half*)sym(g_w2h);

    cudaFuncSetAttribute(attn_mma,
                         cudaFuncAttributeMaxDynamicSharedMemorySize, ATTN_SMEM);
    cudaFuncSetAttribute(hmma_gemm<0, 0, 1>,
                         cudaFuncAttributeMaxDynamicSharedMemorySize, GDSMEM);
    cudaFuncSetAttribute(hmma_gemm<2, 0, 1>,
                         cudaFuncAttributeMaxDynamicSharedMemorySize, GDSMEM);
    cudaFuncSetAttribute(hmma_gemm<1, 0, 1>,
                         cudaFuncAttributeMaxDynamicSharedMemorySize, GDSMEM);
    cudaFuncSetAttribute(hmma_gemm<3, 1, 0>,
                         cudaFuncAttributeMaxDynamicSharedMemorySize, GDSMEM);

    const dim3 tb(32, 8);
    const dim3 gqkv(QKVC / 128, MROWS / 128);   // (12, 98)
    const dim3 g512(CDIM / 128, MROWS / 128);   // (4, 98)
    const dim3 g2048(FFD / 128, MROWS / 128);   // (16, 98)

    // Launch order keeps the QKV GEMM as the 6th launch (ncu -s 5 -c 1).
    // 1: fused QKV weight prep (single fp16)
    wqkv_prep_kernel<<<dim3(16, 16, 3), tb>>>(Wq, Wk, Wv, wqkvh);
    // 2: fused QKV bias
    bqkv_prep_kernel<<<1, CDIM>>>(bq, bk, bv, bqkv);
    // 3: NCHW -> (b, n, c)
    transpose_kernel<<<dim3(25, 16, BATCH), tb>>>(x, xc, CDIM, NPOS);
    // 4: LayerNorm -> fp16 hi/lo
    ln_kernel<<<MROWS, 128>>>(xc, ln_w, ln_b, xnh, xnl);
    // 5: attention bias table
    bias_prep_kernel<<<(NPOS * NPOS + 255) / 256, 256>>>(relb, relidx, biasb);
    // 6: fused QKV projection -> merged fp16 hi/lo [M][1536]  (PROFILED)
    hmma_gemm<0, 0, 1><<<gqkv, 256, GDSMEM>>>(xnh, xnl, wqkvh, bqkv,
                                              nullptr, nullptr, nullptr,
                                              nullptr, qkvh, qkvl, CDIM, QKVC);
    // 7: MMA flash attention -> fp16 hi/lo
    attn_mma<<<dim3(7, NHEADS, BATCH), 224, ATTN_SMEM>>>(qkvh, qkvl, biasb,
                                                         atth, attl);
    // 8-9: x1 = xc + att @ Wo + bo   (hi/lo only)
    wprep_kernel<<<dim3(16, 16), tb>>>(Wo, woh, CDIM, CDIM);
    hmma_gemm<2, 0, 1><<<g512, 256, GDSMEM>>>(atth, attl, woh, bo, xc,
                                              nullptr, nullptr, nullptr,
                                              x1h, x1l, CDIM, CDIM);
    // 10-11: h1 = gelu(x1 @ W1 + b1)   (hi/lo only)
    wprep_kernel<<<dim3(64, 16), tb>>>(W1, w1h, CDIM, FFD);
    hmma_gemm<1, 0, 1><<<g2048, 256, GDSMEM>>>(x1h, x1l, w1h, b1,
                                               nullptr, nullptr, nullptr,
                                               nullptr, h1h, h1l, CDIM, FFD);
    // 12-13: out(NCHW) = (x1h+x1l) + h1 @ W2 + b2  (fused final transpose)
    wprep_kernel<<<dim3(16, 64), tb>>>(W2, w2h, FFD, CDIM);
    hmma_gemm<3, 1, 0><<<g512, 256, GDSMEM>>>(h1h, h1l, w2h, b2,
                                              nullptr, x1h, x1l,
                                              out, nullptr, nullptr, FFD,
                                              CDIM);
}

// round 17
// speedup vs baseline: 4.3841x; 1.0985x over previous
#include <cuda_runtime.h>
#include <cuda_fp16.h>
#include <math.h>
#include <stdint.h>

// ---------------------------------------------------------------------------
// Problem constants
// ---------------------------------------------------------------------------
constexpr int BATCH  = 16;
constexpr int NPOS   = 784;          // 28*28
constexpr int CDIM   = 512;
constexpr int NHEADS = 16;
constexpr int DHEAD  = 32;
constexpr int FFD    = 2048;
constexpr int NREL   = 1596;
constexpr int MROWS  = BATCH * NPOS; // 12544
constexpr int QKVC   = 3 * CDIM;     // 1536

constexpr size_t SZ_NC = (size_t)MROWS * CDIM;
constexpr size_t SZ_Q3 = (size_t)MROWS * QKVC;
constexpr size_t SZ_FF = (size_t)MROWS * FFD;
constexpr size_t SZ_BI = (size_t)NHEADS * NPOS * NPOS;

// ---------------------------------------------------------------------------
// Global scratch (static __device__ arrays — no allocation)
// ---------------------------------------------------------------------------
__device__ float g_xc[SZ_NC];
__device__ float g_bqkv[QKVC];

__device__ __half g_xnh[SZ_NC],   g_xnl[SZ_NC];
__device__ __half g_qkvh[SZ_Q3],  g_qkvl[SZ_Q3];
__device__ __half g_atth[SZ_NC],  g_attl[SZ_NC];
__device__ __half g_x1h[SZ_NC],   g_x1l[SZ_NC];
__device__ __half g_h1h[SZ_FF],   g_h1l[SZ_FF];
__device__ __half g_biasb[SZ_BI];

__device__ __half g_wqkvh[(size_t)QKVC*CDIM];
__device__ __half g_woh[CDIM*CDIM];
__device__ __half g_w1h[(size_t)CDIM*FFD];
__device__ __half g_w2h[(size_t)FFD*CDIM];

// ---------------------------------------------------------------------------
// Helpers
// ---------------------------------------------------------------------------
__device__ __forceinline__ uint32_t smem_u32(const void* p) {
    uint32_t a;
    asm("{ .reg .u64 t; cvta.to.shared.u64 t, %1; cvt.u32.u64 %0, t; }"
        : "=r"(a) : "l"(p));
    return a;
}
__device__ __forceinline__ float gelu_exact(float x) {
    return 0.5f * x * (1.0f + erff(x * 0.7071067811865476f));
}
__device__ __forceinline__ void split_f16(float a, __half& h, __half& l) {
    h = __float2half_rn(a);
    l = __float2half_rn(a - __half2float(h));
}
__device__ __forceinline__ void ldm4(uint32_t* r, uint32_t addr) {
    asm volatile(
        "ldmatrix.sync.aligned.m8n8.x4.shared.b16 {%0,%1,%2,%3}, [%4];"
        : "=r"(r[0]), "=r"(r[1]), "=r"(r[2]), "=r"(r[3]) : "r"(addr)
        : "memory");
}
__device__ __forceinline__ void ldm4t(uint32_t* r, uint32_t addr) {
    asm volatile(
        "ldmatrix.sync.aligned.m8n8.x4.trans.shared.b16 {%0,%1,%2,%3}, [%4];"
        : "=r"(r[0]), "=r"(r[1]), "=r"(r[2]), "=r"(r[3]) : "r"(addr)
        : "memory");
}
__device__ __forceinline__ void mma_f16(float* c, const uint32_t* a,
                                        const uint32_t* b) {
    asm volatile(
        "mma.sync.aligned.m16n8k16.row.col.f32.f16.f16.f32 "
        "{%0,%1,%2,%3},{%4,%5,%6,%7},{%8,%9},{%0,%1,%2,%3};"
        : "+f"(c[0]), "+f"(c[1]), "+f"(c[2]), "+f"(c[3])
        : "r"(a[0]), "r"(a[1]), "r"(a[2]), "r"(a[3]), "r"(b[0]), "r"(b[1]));
}
__device__ __forceinline__ void cp16(uint32_t dst, const void* src) {
    asm volatile("cp.async.cg.shared.global [%0], [%1], 16;"
                 :: "r"(dst), "l"(src));
}
__device__ __forceinline__ uint32_t ex2_f16x2(uint32_t x) {
    uint32_t r;
    asm("ex2.approx.f16x2 %0, %1;" : "=r"(r) : "r"(x));
    return r;
}
constexpr float LOG2E = 1.4426950408889634f;

// ---------------------------------------------------------------------------
// Tiled 2D transpose per batch:  src [R][Cc]  ->  dst [Cc][R]
// ---------------------------------------------------------------------------
__global__ void transpose_kernel(const float* __restrict__ in,
                                 float* __restrict__ out, int R, int Cc) {
    __shared__ float tile[32][33];
    const int b = blockIdx.z;
    const float* src = in  + (size_t)b * R * Cc;
    float*       dst = out + (size_t)b * R * Cc;
    const int c0 = blockIdx.x * 32;
    const int r0 = blockIdx.y * 32;
    const int tx = threadIdx.x, ty = threadIdx.y;
    #pragma unroll
    for (int j = 0; j < 32; j += 8) {
        int r = r0 + ty + j, c = c0 + tx;
        if (r < R && c < Cc) tile[ty + j][tx] = src[(size_t)r * Cc + c];
    }
    __syncthreads();
    #pragma unroll
    for (int j = 0; j < 32; j += 8) {
        int oc = c0 + ty + j, orr = r0 + tx;
        if (oc < Cc && orr < R) dst[(size_t)oc * R + orr] = tile[tx][ty + j];
    }
}

// ---------------------------------------------------------------------------
// Weight prep: W[K][N] fp32  ->  Bh [N][K] fp16
// ---------------------------------------------------------------------------
__global__ void wprep_kernel(const float* __restrict__ W,
                             __half* __restrict__ Bh, int K, int N) {
    __shared__ float t[32][33];
    const int n0 = blockIdx.x * 32, k0 = blockIdx.y * 32;
    const int tx = threadIdx.x, ty = threadIdx.y;
    #pragma unroll
    for (int j = 0; j < 32; j += 8)
        t[ty + j][tx] = W[(size_t)(k0 + ty + j) * N + n0 + tx];
    __syncthreads();
    #pragma unroll
    for (int j = 0; j < 32; j += 8)
        Bh[(size_t)(n0 + ty + j) * K + k0 + tx] = __float2half_rn(t[tx][ty + j]);
}

__global__ void wqkv_prep_kernel(const float* __restrict__ Wq,
                                 const float* __restrict__ Wk,
                                 const float* __restrict__ Wv,
                                 __half* __restrict__ Bh) {
    __shared__ float t[32][33];
    const int z = blockIdx.z;
    const float* W = (z == 0) ? Wq : ((z == 1) ? Wk : Wv);
    const size_t off = (size_t)z * CDIM * CDIM;
    const int n0 = blockIdx.x * 32, k0 = blockIdx.y * 32;
    const int tx = threadIdx.x, ty = threadIdx.y;
    #pragma unroll
    for (int j = 0; j < 32; j += 8)
        t[ty + j][tx] = W[(size_t)(k0 + ty + j) * CDIM + n0 + tx];
    __syncthreads();
    #pragma unroll
    for (int j = 0; j < 32; j += 8)
        Bh[off + (size_t)(n0 + ty + j) * CDIM + k0 + tx] =
            __float2half_rn(t[tx][ty + j]);
}

// ---------------------------------------------------------------------------
// Bias preps
// ---------------------------------------------------------------------------
__global__ void bias_prep_kernel(const float* __restrict__ rel_bias,
                                 const int* __restrict__ rel_idx,
                                 __half* __restrict__ biasb) {
    const int idx = blockIdx.x * 256 + threadIdx.x;
    if (idx >= NPOS * NPOS) return;
    const int ri = rel_idx[idx];
    #pragma unroll
    for (int h = 0; h < NHEADS; ++h)
        biasb[(size_t)h * NPOS * NPOS + idx] =
            __float2half_rn(rel_bias[h * NREL + ri]);
}
__global__ void bqkv_prep_kernel(const float* __restrict__ bq,
                                 const float* __restrict__ bk,
                                 const float* __restrict__ bv,
                                 float* __restrict__ dst) {
    const int t = threadIdx.x;
    dst[t] = bq[t];
    dst[CDIM + t] = bk[t];
    dst[2 * CDIM + t] = bv[t];
}

// ---------------------------------------------------------------------------
// LayerNorm over C=512, one block (128 threads) per row; emits fp16 hi/lo
// ---------------------------------------------------------------------------
__global__ void __launch_bounds__(128) ln_kernel(const float* __restrict__ xc,
                                                 const float* __restrict__ w,
                                                 const float* __restrict__ bsh,
                                                 __half* __restrict__ xh,
                                                 __half* __restrict__ xl) {
    const int row = blockIdx.x;
    const int tid = threadIdx.x;
    const float* xr = xc + (size_t)row * CDIM;
    float4 v = *(const float4*)&xr[tid << 2];
    float s  = v.x + v.y + v.z + v.w;
    float ss = v.x * v.x + v.y * v.y + v.z * v.z + v.w * v.w;
    #pragma unroll
    for (int o = 16; o; o >>= 1) {
        s  += __shfl_xor_sync(0xffffffffu, s, o);
        ss += __shfl_xor_sync(0xffffffffu, ss, o);
    }
    __shared__ float rs[4], rss[4];
    const int warp = tid >> 5, lane = tid & 31;
    if (lane == 0) { rs[warp] = s; rss[warp] = ss; }
    __syncthreads();
    if (tid == 0) {
        float S  = rs[0] + rs[1] + rs[2] + rs[3];
        float SS = rss[0] + rss[1] + rss[2] + rss[3];
        float mu  = S * (1.0f / CDIM);
        float var = SS * (1.0f / CDIM) - mu * mu;
        rs[0]  = mu;
        rss[0] = rsqrtf(var + 1e-5f);
    }
    __syncthreads();
    const float mu = rs[0], rstd = rss[0];
    float4 wv = *(const float4*)&w[tid << 2];
    float4 bv = *(const float4*)&bsh[tid << 2];
    float o[4];
    o[0] = (v.x - mu) * rstd * wv.x + bv.x;
    o[1] = (v.y - mu) * rstd * wv.y + bv.y;
    o[2] = (v.z - mu) * rstd * wv.z + bv.z;
    o[3] = (v.w - mu) * rstd * wv.w + bv.w;
    __half h[4], l[4];
    #pragma unroll
    for (int i = 0; i < 4; ++i) split_f16(o[i], h[i], l[i]);
    uint2 hp, lp;
    __half2 t;
    t = __halves2half2(h[0], h[1]); hp.x = *(uint32_t*)&t;
    t = __halves2half2(h[2], h[3]); hp.y = *(uint32_t*)&t;
    t = __halves2half2(l[0], l[1]); lp.x = *(uint32_t*)&t;
    t = __halves2half2(l[2], l[3]); lp.y = *(uint32_t*)&t;
    *(uint2*)&xh[(size_t)row * CDIM + (tid << 2)] = hp;
    *(uint2*)&xl[(size_t)row * CDIM + (tid << 2)] = lp;
}

// ---------------------------------------------------------------------------
// HMMA fp16x2 GEMM (unchanged from R16):  C = A @ B^T
// ---------------------------------------------------------------------------
constexpr int GT_TILE  = 128 * 32 * 2;
constexpr int GT_STAGE = 3 * GT_TILE;
constexpr int GDSMEM   = 3 * GT_STAGE;

__device__ __forceinline__ uint32_t sw_off(int row, int kc) {
    return (uint32_t)(row * 64 + ((kc ^ ((row >> 1) & 3)) << 4));
}

template <int EPI, int WF, int WH>
__global__ void __launch_bounds__(256, 2) hmma_gemm(
    const __half* __restrict__ Ah, const __half* __restrict__ Al,
    const __half* __restrict__ Bh,
    const float* __restrict__ bias, const float* __restrict__ resf,
    const __half* __restrict__ resh, const __half* __restrict__ resl,
    float* __restrict__ Cf, __half* __restrict__ Ch,
    __half* __restrict__ Cl, int K, int Nc) {
    extern __shared__ char smp[];
    const uint32_t sb = smem_u32(smp);
    const int tid  = threadIdx.x;
    const int wid  = tid >> 5, lane = tid & 31;
    const int row0 = blockIdx.y * 128, col0 = blockIdx.x * 128;
    const int wm   = (wid & 3) * 32;
    const int wn   = (wid >> 2) * 64;

    const int e0   = tid * 2;
    const int grow = e0 >> 2;
    const int gkc  = e0 & 3;
    const uint32_t so0 = sw_off(grow, gkc);
    const uint32_t so1 = sw_off(grow, gkc + 1);
    const __half* gA_h = Ah + (size_t)(row0 + grow) * K + gkc * 8;
    const __half* gA_l = Al + (size_t)(row0 + grow) * K + gkc * 8;
    const __half* gB_h = Bh + (size_t)(col0 + grow) * K + gkc * 8;

    const int a_moff = ((lane >> 3) & 1) * 8 + (lane & 7);
    const int a_k8   = lane >> 4;
    const int b_noff = (lane >> 4) * 8 + (lane & 7);
    const int b_k8   = (lane >> 3) & 1;
    uint32_t aRow64[2], aRsw[2];
    #pragma unroll
    for (int mt = 0; mt < 2; ++mt) {
        int r = wm + mt * 16 + a_moff;
        aRow64[mt] = r * 64;
        aRsw[mt]   = (r >> 1) & 3;
    }
    uint32_t bRow64[4], bRsw[4];
    #pragma unroll
    for (int ntp = 0; ntp < 4; ++ntp) {
        int r = wn + ntp * 16 + b_noff;
        bRow64[ntp] = r * 64;
        bRsw[ntp]   = (r >> 1) & 3;
    }

    float acc[2][8][4];
    #pragma unroll
    for (int i = 0; i < 2; ++i)
        #pragma unroll
        for (int j = 0; j < 8; ++j)
            #pragma unroll
            for (int p = 0; p < 4; ++p) acc[i][j][p] = 0.0f;

    const int NCH = K >> 5;

    auto issue = [&](int c) {
        const uint32_t stg = sb + (c % 3) * GT_STAGE;
        const int ko = c << 5;
        cp16(stg + 0 * GT_TILE + so0, gA_h + ko);
        cp16(stg + 0 * GT_TILE + so1, gA_h + ko + 8);
        cp16(stg + 1 * GT_TILE + so0, gA_l + ko);
        cp16(stg + 1 * GT_TILE + so1, gA_l + ko + 8);
        cp16(stg + 2 * GT_TILE + so0, gB_h + ko);
        cp16(stg + 2 * GT_TILE + so1, gB_h + ko + 8);
        asm volatile("cp.async.commit_group;");
    };
    issue(0);
    if (NCH > 1) issue(1);

    for (int c = 0; c < NCH; ++c) {
        if (c + 1 < NCH)
            asm volatile("cp.async.wait_group 1;");
        else
            asm volatile("cp.async.wait_group 0;");
        __syncthreads();
        if (c + 2 < NCH) issue(c + 2);

        const uint32_t stg = (c % 3) * GT_STAGE;
        const uint32_t sAh = sb + stg;
        const uint32_t sAl = sAh + GT_TILE;
        const uint32_t sBh = sAl + GT_TILE;
        #pragma unroll
        for (int kk = 0; kk < 2; ++kk) {
            uint32_t ah[2][4], al[2][4];
            #pragma unroll
            for (int mt = 0; mt < 2; ++mt) {
                const uint32_t ck = ((uint32_t)(kk * 2 + a_k8) ^ aRsw[mt]) << 4;
                ldm4(ah[mt], sAh + aRow64[mt] + ck);
                ldm4(al[mt], sAl + aRow64[mt] + ck);
            }
            #pragma unroll
            for (int ntp = 0; ntp < 4; ++ntp) {
                const uint32_t ck = ((uint32_t)(kk * 2 + b_k8) ^ bRsw[ntp]) << 4;
                uint32_t bh4[4];
                ldm4(bh4, sBh + bRow64[ntp] + ck);
                #pragma unroll
                for (int mt = 0; mt < 2; ++mt) {
                    mma_f16(acc[mt][2 * ntp],     ah[mt], bh4);
                    mma_f16(acc[mt][2 * ntp],     al[mt], bh4);
                    mma_f16(acc[mt][2 * ntp + 1], ah[mt], bh4 + 2);
                    mma_f16(acc[mt][2 * ntp + 1], al[mt], bh4 + 2);
                }
            }
        }
    }

    const int q  = lane >> 2;
    const int tc = lane & 3;
    #pragma unroll
    for (int mt = 0; mt < 2; ++mt) {
        #pragma unroll
        for (int nt = 0; nt < 8; ++nt) {
            float* cc = acc[mt][nt];
            const int col = col0 + wn + nt * 8 + tc * 2;
            const float2 bb = *(const float2*)&bias[col];
            #pragma unroll
            for (int hrow = 0; hrow < 2; ++hrow) {
                const size_t r = (size_t)(row0 + wm + mt * 16 + q + hrow * 8);
                float v0 = cc[2 * hrow + 0] + bb.x;
                float v1 = cc[2 * hrow + 1] + bb.y;
                if (EPI == 1) { v0 = gelu_exact(v0); v1 = gelu_exact(v1); }
                if (EPI == 2) {
                    float2 rv = *(const float2*)&resf[r * Nc + col];
                    v0 += rv.x; v1 += rv.y;
                }
                if (EPI == 3) {
                    uint32_t rh = *(const uint32_t*)&resh[r * Nc + col];
                    uint32_t rl = *(const uint32_t*)&resl[r * Nc + col];
                    float2 fh = __half22float2(*(__half2*)&rh);
                    float2 fl = __half22float2(*(__half2*)&rl);
                    v0 += fh.x + fl.x;
                    v1 += fh.y + fl.y;
                    const int bb_ = (int)r / NPOS;
                    const int nn_ = (int)r - bb_ * NPOS;
                    Cf[((size_t)(bb_ * CDIM + col)) * NPOS + nn_]     = v0;
                    Cf[((size_t)(bb_ * CDIM + col + 1)) * NPOS + nn_] = v1;
                } else if (WF) {
                    *(float2*)&Cf[r * Nc + col] = make_float2(v0, v1);
                }
                if (WH) {
                    __half h0, l0, h1, l1;
                    split_f16(v0, h0, l0);
                    split_f16(v1, h1, l1);
                    __half2 th = __halves2half2(h0, h1);
                    __half2 tl = __halves2half2(l0, l1);
                    *(uint32_t*)&Ch[r * Nc + col] = *(uint32_t*)&th;
                    *(uint32_t*)&Cl[r * Nc + col] = *(uint32_t*)&tl;
                }
            }
        }
    }
}

// ---------------------------------------------------------------------------
// MMA flash attention v3.  CTA = (b, h, 112-q tile); 7 warps x 16 rows.
// Scores 2-term (qh.kh + ql.kh); exp via ex2.approx.f16x2 producing P frags
// directly; row sums via ones-column MMA; PV 2-term (p.vh + p.vl).
// cp.async double-buffered K/V + async per-warp bias staging.
// ---------------------------------------------------------------------------
constexpr int AQT     = 112;
constexpr int ROWB    = 80;
constexpr int A_SQH   = 0;
constexpr int A_SQL   = A_SQH + AQT * ROWB;     // 8960
constexpr int KV_TILE = AQT * ROWB;             // 8960
constexpr int KV_BUF  = 3 * KV_TILE;            // Kh, Vh, Vl = 26880
constexpr int A_KV0   = A_SQL + AQT * ROWB;     // 17920
constexpr int A_SBI   = A_KV0 + 2 * KV_BUF;     // 71680
constexpr int A_BIW   = 16 * 240;               // 3840
constexpr int ATTN_SMEM = A_SBI + 7 * A_BIW;    // 98560

__global__ void __launch_bounds__(224, 2) attn_mma(
    const __half* __restrict__ qkvh, const __half* __restrict__ qkvl,
    const __half* __restrict__ biasb,
    __half* __restrict__ atth, __half* __restrict__ attl) {
    extern __shared__ char sm[];
    const uint32_t sb = smem_u32(sm);
    const int tid  = threadIdx.x;
    const int wid  = tid >> 5, lane = tid & 31;
    const int qt = blockIdx.x, h = blockIdx.y, b = blockIdx.z;
    const int n0 = qt * AQT;

    // ---- prologue: async Q (hi/lo) + KV(0) ----
    #pragma unroll
    for (int e = tid; e < 448; e += 224) {
        const int r = e >> 2, c = e & 3;
        const size_t g =
            (size_t)(b * NPOS + n0 + r) * QKVC + h * DHEAD + c * 8;
        cp16(sb + A_SQH + r * ROWB + c * 16, qkvh + g);
        cp16(sb + A_SQL + r * ROWB + c * 16, qkvl + g);
    }
    #pragma unroll
    for (int e = tid; e < 448; e += 224) {
        const int r = e >> 2, c = e & 3;
        const size_t gk =
            (size_t)(b * NPOS + r) * QKVC + CDIM + h * DHEAD + c * 8;
        const uint32_t so = r * ROWB + c * 16;
        cp16(sb + A_KV0 + 0 * KV_TILE + so, qkvh + gk);         // Kh
        cp16(sb + A_KV0 + 1 * KV_TILE + so, qkvh + gk + CDIM);  // Vh
        cp16(sb + A_KV0 + 2 * KV_TILE + so, qkvl + gk + CDIM);  // Vl
    }
    asm volatile("cp.async.commit_group;");

    const int am  = ((lane >> 3) & 1) * 8 + (lane & 7);
    const int ak8 = lane >> 4;
    const int bn  = (lane >> 4) * 8 + (lane & 7);
    const int bk8 = (lane >> 3) & 1;
    const uint32_t sBiasW = sb + A_SBI + wid * A_BIW;
    const uint32_t b_ones = (lane < 4) ? 0x3C003C00u : 0u;
    uint32_t bo2[2] = {b_ones, b_ones};

    uint32_t qfh[2][4], qfl[2][4];
    float m0 = -1e30f, m1 = -1e30f;
    float oa[4][4];
    float sacc[4] = {0.0f, 0.0f, 0.0f, 0.0f};
    #pragma unroll
    for (int j = 0; j < 4; ++j)
        #pragma unroll
        for (int p = 0; p < 4; ++p) oa[j][p] = 0.0f;

    for (int kt = 0; kt < 7; ++kt) {
        asm volatile("cp.async.wait_group 0;");
        __syncthreads();
        if (kt == 0) {
            #pragma unroll
            for (int kk = 0; kk < 2; ++kk) {
                const uint32_t off =
                    (wid * 16 + am) * ROWB + (kk * 2 + ak8) * 16;
                ldm4(qfh[kk], sb + A_SQH + off);
                ldm4(qfl[kk], sb + A_SQL + off);
            }
        }
        // ---- async bias(kt) into per-warp staging ----
        {
            const int mp0 = kt * AQT;
            #pragma unroll
            for (int e = lane; e < 224; e += 32) {
                const int r = e / 14, c = e % 14;
                cp16(sBiasW + r * 240 + c * 16,
                     biasb + (size_t)h * NPOS * NPOS +
                         (size_t)(n0 + wid * 16 + r) * NPOS + mp0 + c * 8);
            }
            asm volatile("cp.async.commit_group;");
        }
        // ---- async KV(kt+1) into alternate buffer ----
        if (kt < 6) {
            const int mp1 = (kt + 1) * AQT;
            const uint32_t dst = sb + A_KV0 + ((kt + 1) & 1) * KV_BUF;
            #pragma unroll
            for (int e = tid; e < 448; e += 224) {
                const int r = e >> 2, c = e & 3;
                const size_t gk = (size_t)(b * NPOS + mp1 + r) * QKVC + CDIM +
                                  h * DHEAD + c * 8;
                const uint32_t so = r * ROWB + c * 16;
                cp16(dst + 0 * KV_TILE + so, qkvh + gk);
                cp16(dst + 1 * KV_TILE + so, qkvh + gk + CDIM);
                cp16(dst + 2 * KV_TILE + so, qkvl + gk + CDIM);
            }
            asm volatile("cp.async.commit_group;");
        }

        const uint32_t kvb = sb + A_KV0 + (kt & 1) * KV_BUF;

        // ---- scores: 2-term (qh.kh + ql.kh) ----
        float sa[14][4];
        #pragma unroll
        for (int t = 0; t < 14; ++t)
            #pragma unroll
            for (int p = 0; p < 4; ++p) sa[t][p] = 0.0f;
        #pragma unroll
        for (int kk = 0; kk < 2; ++kk) {
            #pragma unroll
            for (int g = 0; g < 7; ++g) {
                const uint32_t off =
                    (g * 16 + bn) * ROWB + (kk * 2 + bk8) * 16;
                uint32_t kh4[4];
                ldm4(kh4, kvb + off);
                mma_f16(sa[2 * g],     qfh[kk], kh4);
                mma_f16(sa[2 * g],     qfl[kk], kh4);
                mma_f16(sa[2 * g + 1], qfh[kk], kh4 + 2);
                mma_f16(sa[2 * g + 1], qfl[kk], kh4 + 2);
            }
        }

        // ---- bias add (wait for bias group; KV(kt+1) may still fly) ----
        if (kt < 6)
            asm volatile("cp.async.wait_group 1;");
        else
            asm volatile("cp.async.wait_group 0;");
        __syncwarp();
        #pragma unroll
        for (int c7 = 0; c7 < 7; ++c7) {
            uint32_t bb[4];
            ldm4(bb, sBiasW + am * 240 + c7 * 32 + ak8 * 16);
            float2 f0 = __half22float2(*(__half2*)&bb[0]);
            float2 f1 = __half22float2(*(__half2*)&bb[1]);
            float2 f2 = __half22float2(*(__half2*)&bb[2]);
            float2 f3 = __half22float2(*(__half2*)&bb[3]);
            sa[2 * c7][0] += f0.x;     sa[2 * c7][1] += f0.y;
            sa[2 * c7][2] += f1.x;     sa[2 * c7][3] += f1.y;
            sa[2 * c7 + 1][0] += f2.x; sa[2 * c7 + 1][1] += f2.y;
            sa[2 * c7 + 1][2] += f3.x; sa[2 * c7 + 1][3] += f3.y;
        }

        // ---- online softmax: max ----
        float mx0 = -1e30f, mx1 = -1e30f;
        #pragma unroll
        for (int t = 0; t < 14; ++t) {
            mx0 = fmaxf(mx0, fmaxf(sa[t][0], sa[t][1]));
            mx1 = fmaxf(mx1, fmaxf(sa[t][2], sa[t][3]));
        }
        mx0 = fmaxf(mx0, __shfl_xor_sync(0xffffffffu, mx0, 1));
        mx0 = fmaxf(mx0, __shfl_xor_sync(0xffffffffu, mx0, 2));
        mx1 = fmaxf(mx1, __shfl_xor_sync(0xffffffffu, mx1, 1));
        mx1 = fmaxf(mx1, __shfl_xor_sync(0xffffffffu, mx1, 2));
        const float nm0 = fmaxf(m0, mx0), nm1 = fmaxf(m1, mx1);
        const float f0 = __expf(m0 - nm0), f1 = __expf(m1 - nm1);
        m0 = nm0; m1 = nm1;
        const float mls0 = m0 * LOG2E, mls1 = m1 * LOG2E;

        // rescale O and sum accumulators
        #pragma unroll
        for (int j = 0; j < 4; ++j) {
            oa[j][0] *= f0; oa[j][1] *= f0;
            oa[j][2] *= f1; oa[j][3] *= f1;
        }
        sacc[0] *= f0; sacc[1] *= f0;
        sacc[2] *= f1; sacc[3] *= f1;

        // ---- exp -> fp16 P fragments (A-frag layout) ----
        uint32_t pq[7][4];
        #pragma unroll
        for (int t = 0; t < 7; ++t) {
            #pragma unroll
            for (int half = 0; half < 2; ++half) {
                const float* src = sa[2 * t + half];
                float e0 = fmaf(src[0], LOG2E, -mls0);
                float e1 = fmaf(src[1], LOG2E, -mls0);
                float e2 = fmaf(src[2], LOG2E, -mls1);
                float e3 = fmaf(src[3], LOG2E, -mls1);
                __half2 x01 = __floats2half2_rn(e0, e1);
                __half2 x23 = __floats2half2_rn(e2, e3);
                pq[t][2 * half + 0] = ex2_f16x2(*(uint32_t*)&x01);
                pq[t][2 * half + 1] = ex2_f16x2(*(uint32_t*)&x23);
            }
        }

        // ---- row sums via ones-column MMA ----
        #pragma unroll
        for (int t = 0; t < 7; ++t) mma_f16(sacc, pq[t], bo2);

        // ---- P.V (2-term: p.vh + p.vl) ----
        #pragma unroll
        for (int t = 0; t < 7; ++t) {
            #pragma unroll
            for (int v = 0; v < 2; ++v) {
                const uint32_t off =
                    (t * 16 + am) * ROWB + v * 32 + (lane >> 4) * 16;
                uint32_t vh4[4], vl4[4];
                ldm4t(vh4, kvb + 1 * KV_TILE + off);
                ldm4t(vl4, kvb + 2 * KV_TILE + off);
                mma_f16(oa[2 * v],     pq[t], vh4);
                mma_f16(oa[2 * v],     pq[t], vl4);
                mma_f16(oa[2 * v + 1], pq[t], vh4 + 2);
                mma_f16(oa[2 * v + 1], pq[t], vl4 + 2);
            }
        }
    }

    // ---- epilogue: broadcast sums, normalize, write fp16 hi/lo ----
    const float l0 = __shfl_sync(0xffffffffu, sacc[0], lane & ~3u);
    const float l1 = __shfl_sync(0xffffffffu, sacc[2], lane & ~3u);
    const float inv0 = 1.0f / l0, inv1 = 1.0f / l1;
    const int q  = lane >> 2, tc = lane & 3;
    const size_t r0 = (size_t)(b * NPOS + n0 + wid * 16 + q);
    const size_t r1 = r0 + 8;
    #pragma unroll
    for (int j = 0; j < 4; ++j) {
        const int col = h * DHEAD + j * 8 + tc * 2;
        float a0 = oa[j][0] * inv0, a1 = oa[j][1] * inv0;
        float b0 = oa[j][2] * inv1, b1 = oa[j][3] * inv1;
        __half h0, lo0, h1, lo1;
        split_f16(a0, h0, lo0); split_f16(a1, h1, lo1);
        __half2 th = __halves2half2(h0, h1);
        __half2 tl = __halves2half2(lo0, lo1);
        *(uint32_t*)&atth[r0 * CDIM + col] = *(uint32_t*)&th;
        *(uint32_t*)&attl[r0 * CDIM + col] = *(uint32_t*)&tl;
        split_f16(b0, h0, lo0); split_f16(b1, h1, lo1);
        th = __halves2half2(h0, h1);
        tl = __halves2half2(lo0, lo1);
        *(uint32_t*)&atth[r1 * CDIM + col] = *(uint32_t*)&th;
        *(uint32_t*)&attl[r1 * CDIM + col] = *(uint32_t*)&tl;
    }
}

// ---------------------------------------------------------------------------
// Launch
// ---------------------------------------------------------------------------
extern "C" void kernel_launch(void* const* d_in, const int* in_sizes, int n_in,
                              void* d_out, int out_size) {
    (void)in_sizes; (void)n_in; (void)out_size;
    const float* x      = (const float*)d_in[0];
    const float* ln_w   = (const float*)d_in[1];
    const float* ln_b   = (const float*)d_in[2];
    const float* Wq     = (const float*)d_in[3];
    const float* bq     = (const float*)d_in[4];
    const float* Wk     = (const float*)d_in[5];
    const float* bk     = (const float*)d_in[6];
    const float* Wv     = (const float*)d_in[7];
    const float* bv     = (const float*)d_in[8];
    const float* Wo     = (const float*)d_in[9];
    const float* bo     = (const float*)d_in[10];
    const float* relb   = (const float*)d_in[11];
    const float* W1     = (const float*)d_in[12];
    const float* b1     = (const float*)d_in[13];
    const float* W2     = (const float*)d_in[14];
    const float* b2     = (const float*)d_in[15];
    const int*   relidx = (const int*)d_in[16];
    float* out = (float*)d_out;

    auto sym = [](const void* s) {
        void* p = nullptr;
        cudaGetSymbolAddress(&p, s);
        return p;
    };
    float* xc   = (float*)sym(g_xc);
    float* bqkv = (float*)sym(g_bqkv);
    __half* xnh   = (__half*)sym(g_xnh);
    __half* xnl   = (__half*)sym(g_xnl);
    __half* qkvh  = (__half*)sym(g_qkvh);
    __half* qkvl  = (__half*)sym(g_qkvl);
    __half* atth  = (__half*)sym(g_atth);
    __half* attl  = (__half*)sym(g_attl);
    __half* x1h   = (__half*)sym(g_x1h);
    __half* x1l   = (__half*)sym(g_x1l);
    __half* h1h   = (__half*)sym(g_h1h);
    __half* h1l   = (__half*)sym(g_h1l);
    __half* biasb = (__half*)sym(g_biasb);
    __half* wqkvh = (__half*)sym(g_wqkvh);
    __half* woh   = (__half*)sym(g_woh);
    __half* w1h   = (__half*)sym(g_w1h);
    __half* w2h   = (__half*)sym(g_w2h);

    cudaFuncSetAttribute(attn_mma,
                         cudaFuncAttributeMaxDynamicSharedMemorySize, ATTN_SMEM);
    cudaFuncSetAttribute(hmma_gemm<0, 0, 1>,
                         cudaFuncAttributeMaxDynamicSharedMemorySize, GDSMEM);
    cudaFuncSetAttribute(hmma_gemm<2, 0, 1>,
                         cudaFuncAttributeMaxDynamicSharedMemorySize, GDSMEM);
    cudaFuncSetAttribute(hmma_gemm<1, 0, 1>,
                         cudaFuncAttributeMaxDynamicSharedMemorySize, GDSMEM);
    cudaFuncSetAttribute(hmma_gemm<3, 1, 0>,
                         cudaFuncAttributeMaxDynamicSharedMemorySize, GDSMEM);

    const dim3 tb(32, 8);
    const dim3 gqkv(QKVC / 128, MROWS / 128);   // (12, 98)
    const dim3 g512(CDIM / 128, MROWS / 128);   // (4, 98)
    const dim3 g2048(FFD / 128, MROWS / 128);   // (16, 98)

    wqkv_prep_kernel<<<dim3(16, 16, 3), tb>>>(Wq, Wk, Wv, wqkvh);
    bqkv_prep_kernel<<<1, CDIM>>>(bq, bk, bv, bqkv);
    transpose_kernel<<<dim3(25, 16, BATCH), tb>>>(x, xc, CDIM, NPOS);
    ln_kernel<<<MROWS, 128>>>(xc, ln_w, ln_b, xnh, xnl);
    bias_prep_kernel<<<(NPOS * NPOS + 255) / 256, 256>>>(relb, relidx, biasb);
    // fused QKV projection -> merged fp16 hi/lo [M][1536]
    hmma_gemm<0, 0, 1><<<gqkv, 256, GDSMEM>>>(xnh, xnl, wqkvh, bqkv,
                                              nullptr, nullptr, nullptr,
                                              nullptr, qkvh, qkvl, CDIM, QKVC);
    // MMA flash attention v3 -> fp16 hi/lo
    attn_mma<<<dim3(7, NHEADS, BATCH), 224, ATTN_SMEM>>>(qkvh, qkvl, biasb,
                                                         atth, attl);
    // x1 = xc + att @ Wo + bo   (hi/lo only)
    wprep_kernel<<<dim3(16, 16), tb>>>(Wo, woh, CDIM, CDIM);
    hmma_gemm<2, 0, 1><<<g512, 256, GDSMEM>>>(atth, attl, woh, bo, xc,
                                              nullptr, nullptr, nullptr,
                                              x1h, x1l, CDIM, CDIM);
    // h1 = gelu(x1 @ W1 + b1)   (hi/lo only)
    wprep_kernel<<<dim3(64, 16), tb>>>(W1, w1h, CDIM, FFD);
    hmma_gemm<1, 0, 1><<<g2048, 256, GDSMEM>>>(x1h, x1l, w1h, b1,
                                               nullptr, nullptr, nullptr,
                                               nullptr, h1h, h1l, CDIM, FFD);
    // out(NCHW) = (x1h+x1l) + h1 @ W2 + b2  (fused final transpose)
    wprep_kernel<<<dim3(16, 64), tb>>>(W2, w2h, FFD, CDIM);
    hmma_gemm<3, 1, 0><<<g512, 256, GDSMEM>>>(h1h, h1l, w2h, b2,
                                              nullptr, x1h, x1l,
                                              out, nullptr, nullptr, FFD,
                                              CDIM);
}